// round 1
// baseline (speedup 1.0000x reference)
#include <cuda_runtime.h>
#include <math.h>

#define S_LEN 2048
#define H_DIM 4096
#define NH 32
#define NKV 8
#define HD 128
#define QKV_N 6144            // (NH + 2*NKV) * HD
#define ATT_SCALE 0.08838834764831843f

// Scratch (device globals — allocation-free per harness rules)
__device__ float g_qkv[S_LEN * QKV_N];    // [S, 6144] = [q(32*128) | k(8*128) | v(8*128)]
__device__ float g_attn[S_LEN * H_DIM];   // attention output [S, 4096]

// ---------------------------------------------------------------------------
// SGEMM (NT): C[M,N] = A[M,K] * B[N,K]^T   (both operands K-contiguous rows)
// 128x128 block tile, BK=8, 256 threads, 8x8 per-thread microtile.
// ---------------------------------------------------------------------------
__global__ __launch_bounds__(256)
void sgemm_nt_kernel(int M, int N, int K,
                     const float* __restrict__ A,
                     const float* __restrict__ B,
                     float* __restrict__ C)
{
    __shared__ float As[8][128];
    __shared__ float Bs[8][128];

    const int tid = threadIdx.x;
    const int tr  = tid >> 4;          // 0..15
    const int tc  = tid & 15;          // 0..15
    const int bm  = blockIdx.y * 128;
    const int bn  = blockIdx.x * 128;

    const int lr = tid >> 1;           // 0..127 (tile row to load)
    const int lk = (tid & 1) * 4;      // 0 or 4 (k offset within BK)

    const float* Ap = A + (size_t)(bm + lr) * K + lk;
    const float* Bp = B + (size_t)(bn + lr) * K + lk;

    float acc[8][8];
#pragma unroll
    for (int i = 0; i < 8; i++)
#pragma unroll
        for (int j = 0; j < 8; j++) acc[i][j] = 0.0f;

    for (int k0 = 0; k0 < K; k0 += 8) {
        float4 av = *(const float4*)Ap;  Ap += 8;
        float4 bv = *(const float4*)Bp;  Bp += 8;

        __syncthreads();   // previous iteration's compute done (WAR on smem)
        As[lk + 0][lr] = av.x;  As[lk + 1][lr] = av.y;
        As[lk + 2][lr] = av.z;  As[lk + 3][lr] = av.w;
        Bs[lk + 0][lr] = bv.x;  Bs[lk + 1][lr] = bv.y;
        Bs[lk + 2][lr] = bv.z;  Bs[lk + 3][lr] = bv.w;
        __syncthreads();

#pragma unroll
        for (int k = 0; k < 8; k++) {
            float a[8], b[8];
            *(float4*)&a[0] = *(const float4*)&As[k][tr * 8];
            *(float4*)&a[4] = *(const float4*)&As[k][tr * 8 + 4];
            *(float4*)&b[0] = *(const float4*)&Bs[k][tc * 8];
            *(float4*)&b[4] = *(const float4*)&Bs[k][tc * 8 + 4];
#pragma unroll
            for (int i = 0; i < 8; i++)
#pragma unroll
                for (int j = 0; j < 8; j++)
                    acc[i][j] += a[i] * b[j];
        }
    }

#pragma unroll
    for (int i = 0; i < 8; i++) {
        float* Cp = C + (size_t)(bm + tr * 8 + i) * N + bn + tc * 8;
        *(float4*)(Cp + 0) = make_float4(acc[i][0], acc[i][1], acc[i][2], acc[i][3]);
        *(float4*)(Cp + 4) = make_float4(acc[i][4], acc[i][5], acc[i][6], acc[i][7]);
    }
}

// ---------------------------------------------------------------------------
// RoPE on Q (heads 0..31) and K (heads 32..39) in-place on g_qkv.
// NOTE: q heads live at offsets h*128 for h<32, k heads at 4096+(h-32)*128
//       which is ALSO h*128 for h in [32,40) — one indexing covers both.
// ---------------------------------------------------------------------------
__global__ void rope_kernel(const int* __restrict__ positions)
{
    const int s = blockIdx.x;
    const int h = blockIdx.y;          // 0..39
    const int d = threadIdx.x;         // 0..63

    const float pos = (float)positions[s];
    const float inv_freq = powf(1000000.0f, -(float)d * (1.0f / 64.0f));
    const float ang = pos * inv_freq;
    float sn, cs;
    sincosf(ang, &sn, &cs);

    float* base = g_qkv + (size_t)s * QKV_N + h * HD;
    const float x1 = base[d];
    const float x2 = base[d + 64];
    base[d]      = x1 * cs - x2 * sn;
    base[d + 64] = x2 * cs + x1 * sn;
}

// ---------------------------------------------------------------------------
// Causal GQA flash attention. 64x64 tiles, 256 threads (16x16), fp32,
// online softmax; P staged through smem for the PV GEMM.
// grid = (S/64, NH). Heavy q-tiles scheduled first (reverse blockIdx.x).
// ---------------------------------------------------------------------------
#define QS_STRIDE 68
#define VS_STRIDE 132
#define FLASH_SMEM_FLOATS (128*QS_STRIDE /*Qs*/ + 128*QS_STRIDE /*Ks*/ + 64*VS_STRIDE /*Vs*/ + 64*68 /*Ps*/)
#define FLASH_SMEM_BYTES  (FLASH_SMEM_FLOATS * 4)

__global__ __launch_bounds__(256)
void flash_kernel()
{
    extern __shared__ float sm[];
    float* Qs = sm;                         // [d=128][r=64] stride 68 (transposed)
    float* Ks = Qs + 128 * QS_STRIDE;       // [d=128][c=64] stride 68 (transposed)
    float* Vs = Ks + 128 * QS_STRIDE;       // [k=64][d=128] stride 132
    float* Ps = Vs + 64 * VS_STRIDE;        // [k=64][r=64] stride 68

    const int tid = threadIdx.x;
    const int tx  = tid & 15;               // 0..15 -> S cols / O col-octet
    const int ty  = tid >> 4;               // 0..15 -> 4 rows each
    const int qt  = gridDim.x - 1 - blockIdx.x;   // heavy tiles first
    const int h   = blockIdx.y;
    const int kh  = h >> 2;                 // GQA: 4 q-heads per kv-head

    const float* Qg = g_qkv + (size_t)(qt * 64) * QKV_N + h * HD;
    const float* Kg = g_qkv + NH * HD + kh * HD;
    const float* Vg = g_qkv + (NH + NKV) * HD + kh * HD;

    // Load Q tile transposed into smem
    for (int i = tid; i < 64 * 32; i += 256) {
        const int r  = i >> 5;
        const int d4 = (i & 31) * 4;
        float4 v = *(const float4*)(Qg + (size_t)r * QKV_N + d4);
        Qs[(d4 + 0) * QS_STRIDE + r] = v.x;
        Qs[(d4 + 1) * QS_STRIDE + r] = v.y;
        Qs[(d4 + 2) * QS_STRIDE + r] = v.z;
        Qs[(d4 + 3) * QS_STRIDE + r] = v.w;
    }

    float mrow[4], lrow[4], acc[4][8];
#pragma unroll
    for (int i = 0; i < 4; i++) {
        mrow[i] = -INFINITY;
        lrow[i] = 0.0f;
#pragma unroll
        for (int j = 0; j < 8; j++) acc[i][j] = 0.0f;
    }

    for (int jt = 0; jt <= qt; jt++) {
        __syncthreads();   // previous PV done; Q stores done (first iter)

        const float* Kt = Kg + (size_t)(jt * 64) * QKV_N;
        const float* Vt = Vg + (size_t)(jt * 64) * QKV_N;
        for (int i = tid; i < 64 * 32; i += 256) {
            const int r  = i >> 5;
            const int d4 = (i & 31) * 4;
            float4 kv = *(const float4*)(Kt + (size_t)r * QKV_N + d4);
            Ks[(d4 + 0) * QS_STRIDE + r] = kv.x;
            Ks[(d4 + 1) * QS_STRIDE + r] = kv.y;
            Ks[(d4 + 2) * QS_STRIDE + r] = kv.z;
            Ks[(d4 + 3) * QS_STRIDE + r] = kv.w;
            float4 vv = *(const float4*)(Vt + (size_t)r * QKV_N + d4);
            *(float4*)&Vs[r * VS_STRIDE + d4] = vv;
        }
        __syncthreads();

        // S = Q K^T  (64x64x128)
        float s4[4][4];
#pragma unroll
        for (int i = 0; i < 4; i++)
#pragma unroll
            for (int j = 0; j < 4; j++) s4[i][j] = 0.0f;

#pragma unroll 4
        for (int d = 0; d < 128; d++) {
            float4 a = *(const float4*)&Qs[d * QS_STRIDE + ty * 4];
            float4 b = *(const float4*)&Ks[d * QS_STRIDE + tx * 4];
            float av[4] = {a.x, a.y, a.z, a.w};
            float bv[4] = {b.x, b.y, b.z, b.w};
#pragma unroll
            for (int i = 0; i < 4; i++)
#pragma unroll
                for (int j = 0; j < 4; j++)
                    s4[i][j] += av[i] * bv[j];
        }

        // scale + causal mask
        const int qrow0 = qt * 64 + ty * 4;
        const int kcol0 = jt * 64 + tx * 4;
#pragma unroll
        for (int i = 0; i < 4; i++)
#pragma unroll
            for (int j = 0; j < 4; j++) {
                float sv = s4[i][j] * ATT_SCALE;
                if (kcol0 + j > qrow0 + i) sv = -1e30f;
                s4[i][j] = sv;
            }

        // online softmax per row (row spread across 16 lanes of a half-warp)
#pragma unroll
        for (int i = 0; i < 4; i++) {
            float rm = fmaxf(fmaxf(s4[i][0], s4[i][1]), fmaxf(s4[i][2], s4[i][3]));
#pragma unroll
            for (int msk = 1; msk < 16; msk <<= 1)
                rm = fmaxf(rm, __shfl_xor_sync(0xffffffffu, rm, msk));
            const float mn = fmaxf(mrow[i], rm);
            const float corr = expf(mrow[i] - mn);
            float rs = 0.0f;
#pragma unroll
            for (int j = 0; j < 4; j++) {
                float p = expf(s4[i][j] - mn);
                s4[i][j] = p;
                rs += p;
            }
#pragma unroll
            for (int msk = 1; msk < 16; msk <<= 1)
                rs += __shfl_xor_sync(0xffffffffu, rs, msk);
            lrow[i] = lrow[i] * corr + rs;
            mrow[i] = mn;
#pragma unroll
            for (int j = 0; j < 8; j++) acc[i][j] *= corr;
        }

        // stage P (transposed: Ps[k][r])
#pragma unroll
        for (int i = 0; i < 4; i++)
#pragma unroll
            for (int j = 0; j < 4; j++)
                Ps[(tx * 4 + j) * 68 + ty * 4 + i] = s4[i][j];
        __syncthreads();

        // O += P V  (64x128x64)
#pragma unroll 4
        for (int k = 0; k < 64; k++) {
            float4 p  = *(const float4*)&Ps[k * 68 + ty * 4];
            float4 v0 = *(const float4*)&Vs[k * VS_STRIDE + tx * 8];
            float4 v1 = *(const float4*)&Vs[k * VS_STRIDE + tx * 8 + 4];
            float pv[4] = {p.x, p.y, p.z, p.w};
            float vv[8] = {v0.x, v0.y, v0.z, v0.w, v1.x, v1.y, v1.z, v1.w};
#pragma unroll
            for (int i = 0; i < 4; i++)
#pragma unroll
                for (int j = 0; j < 8; j++)
                    acc[i][j] += pv[i] * vv[j];
        }
    }

    // epilogue: normalize + write
#pragma unroll
    for (int i = 0; i < 4; i++) {
        const float inv_l = 1.0f / lrow[i];
        const int row = qt * 64 + ty * 4 + i;
        float* op = g_attn + (size_t)row * H_DIM + h * HD + tx * 8;
        *(float4*)(op + 0) = make_float4(acc[i][0] * inv_l, acc[i][1] * inv_l,
                                         acc[i][2] * inv_l, acc[i][3] * inv_l);
        *(float4*)(op + 4) = make_float4(acc[i][4] * inv_l, acc[i][5] * inv_l,
                                         acc[i][6] * inv_l, acc[i][7] * inv_l);
    }
}

// ---------------------------------------------------------------------------
// Launch
// ---------------------------------------------------------------------------
extern "C" void kernel_launch(void* const* d_in, const int* in_sizes, int n_in,
                              void* d_out, int out_size)
{
    (void)in_sizes; (void)n_in; (void)out_size;
    const int*   positions = (const int*)d_in[0];
    const float* hidden    = (const float*)d_in[1];
    const float* w_qkv     = (const float*)d_in[2];
    const float* w_o       = (const float*)d_in[3];
    float*       out       = (float*)d_out;

    float *qkv_ptr = nullptr, *attn_ptr = nullptr;
    cudaGetSymbolAddress((void**)&qkv_ptr, g_qkv);
    cudaGetSymbolAddress((void**)&attn_ptr, g_attn);

    cudaFuncSetAttribute(flash_kernel,
                         cudaFuncAttributeMaxDynamicSharedMemorySize,
                         FLASH_SMEM_BYTES);

    // 1) QKV projection: [2048,6144] = hidden[2048,4096] @ w_qkv^T
    sgemm_nt_kernel<<<dim3(QKV_N / 128, S_LEN / 128), 256>>>(
        S_LEN, QKV_N, H_DIM, hidden, w_qkv, qkv_ptr);

    // 2) RoPE on Q and K heads (in-place)
    rope_kernel<<<dim3(S_LEN, NH + NKV), 64>>>(positions);

    // 3) Causal GQA flash attention -> g_attn
    flash_kernel<<<dim3(S_LEN / 64, NH), 256, FLASH_SMEM_BYTES>>>();

    // 4) Output projection: out[2048,4096] = g_attn @ w_o^T
    sgemm_nt_kernel<<<dim3(H_DIM / 128, S_LEN / 128), 256>>>(
        S_LEN, H_DIM, H_DIM, attn_ptr, w_o, out);
}

// round 2
// speedup vs baseline: 1.7792x; 1.7792x over previous
#include <cuda_runtime.h>
#include <math.h>
#include <stdint.h>

#define S_LEN 2048
#define H_DIM 4096
#define NH 32
#define NKV 8
#define HD 128
#define QKV_N 6144            // (NH + 2*NKV) * HD
#define ATT_SCALE 0.08838834764831843f

// Scratch (device globals — allocation-free per harness rules)
__device__ float g_qkv[S_LEN * QKV_N];    // [S, 6144] = [q(32*128) | k(8*128) | v(8*128)]
__device__ float g_attn[S_LEN * H_DIM];   // attention output [S, 4096]

__device__ __forceinline__ uint32_t f2tf(float x) {
    uint32_t r;
    asm("cvt.rna.tf32.f32 %0, %1;" : "=r"(r) : "f"(x));
    return r;
}

// ---------------------------------------------------------------------------
// TF32 tensor-core GEMM (NT): C[M,N] = A[M,K] * B[N,K]^T
// 128x128 block tile, BK=16, 256 threads (8 warps), warp tile 64x32,
// mma.sync.m16n8k8.tf32. Conflict-free fragment loads (smem stride 20).
// ---------------------------------------------------------------------------
#define BM 128
#define BN 128
#define BK 16
#define TSTR 20   // smem row stride (floats): 20*g mod 32 spans 8 banks, conflict-free frags

__global__ __launch_bounds__(256)
void gemm_tf32_nt(int M, int N, int K,
                  const float* __restrict__ A,
                  const float* __restrict__ B,
                  float* __restrict__ C)
{
    __shared__ uint32_t As[BM * TSTR];
    __shared__ uint32_t Bs[BN * TSTR];

    const int tid  = threadIdx.x;
    const int warp = tid >> 5;
    const int lane = tid & 31;
    const int g    = lane >> 2;     // 0..7
    const int t    = lane & 3;      // 0..3

    const int bm = blockIdx.y * BM;
    const int bn = blockIdx.x * BN;
    const int wm = (warp & 1) * 64; // warp row (2 rows of 64)
    const int wn = (warp >> 1) * 32;// warp col (4 cols of 32)

    // global load mapping: each thread owns one half-row (8 floats) of A and B tile
    const int lr = tid >> 1;        // 0..127
    const int lc = (tid & 1) * 8;   // 0 or 8

    const float* Ap = A + (size_t)(bm + lr) * K + lc;
    const float* Bp = B + (size_t)(bn + lr) * K + lc;

    float acc[4][4][4];
#pragma unroll
    for (int i = 0; i < 4; i++)
#pragma unroll
        for (int j = 0; j < 4; j++)
#pragma unroll
            for (int r = 0; r < 4; r++) acc[i][j][r] = 0.0f;

    for (int k0 = 0; k0 < K; k0 += BK) {
        float4 av0 = *(const float4*)(Ap + 0);
        float4 av1 = *(const float4*)(Ap + 4);
        float4 bv0 = *(const float4*)(Bp + 0);
        float4 bv1 = *(const float4*)(Bp + 4);
        Ap += BK; Bp += BK;

        __syncthreads();   // WAR: previous iteration's fragment loads done
        uint32_t* as = &As[lr * TSTR + lc];
        as[0] = f2tf(av0.x); as[1] = f2tf(av0.y); as[2] = f2tf(av0.z); as[3] = f2tf(av0.w);
        as[4] = f2tf(av1.x); as[5] = f2tf(av1.y); as[6] = f2tf(av1.z); as[7] = f2tf(av1.w);
        uint32_t* bs = &Bs[lr * TSTR + lc];
        bs[0] = f2tf(bv0.x); bs[1] = f2tf(bv0.y); bs[2] = f2tf(bv0.z); bs[3] = f2tf(bv0.w);
        bs[4] = f2tf(bv1.x); bs[5] = f2tf(bv1.y); bs[6] = f2tf(bv1.z); bs[7] = f2tf(bv1.w);
        __syncthreads();

#pragma unroll
        for (int ks = 0; ks < 2; ks++) {
            const int kb = ks * 8;
            uint32_t a[4][4], b[4][2];
#pragma unroll
            for (int am = 0; am < 4; am++) {
                const int r = wm + am * 16;
                a[am][0] = As[(r +     g) * TSTR + kb +     t];
                a[am][1] = As[(r + 8 + g) * TSTR + kb +     t];
                a[am][2] = As[(r +     g) * TSTR + kb + 4 + t];
                a[am][3] = As[(r + 8 + g) * TSTR + kb + 4 + t];
            }
#pragma unroll
            for (int an = 0; an < 4; an++) {
                const int c = wn + an * 8;
                b[an][0] = Bs[(c + g) * TSTR + kb +     t];
                b[an][1] = Bs[(c + g) * TSTR + kb + 4 + t];
            }
#pragma unroll
            for (int am = 0; am < 4; am++)
#pragma unroll
                for (int an = 0; an < 4; an++) {
                    asm volatile(
                        "mma.sync.aligned.m16n8k8.row.col.f32.tf32.tf32.f32 "
                        "{%0,%1,%2,%3}, {%4,%5,%6,%7}, {%8,%9}, {%0,%1,%2,%3};\n"
                        : "+f"(acc[am][an][0]), "+f"(acc[am][an][1]),
                          "+f"(acc[am][an][2]), "+f"(acc[am][an][3])
                        : "r"(a[am][0]), "r"(a[am][1]), "r"(a[am][2]), "r"(a[am][3]),
                          "r"(b[an][0]), "r"(b[an][1]));
                }
        }
    }

    // epilogue: c0,c1 at (row=g, col=2t..2t+1); c2,c3 at row g+8
#pragma unroll
    for (int am = 0; am < 4; am++) {
        const int row0 = bm + wm + am * 16 + g;
#pragma unroll
        for (int an = 0; an < 4; an++) {
            const int col = bn + wn + an * 8 + t * 2;
            float* c0 = C + (size_t)row0 * N + col;
            c0[0] = acc[am][an][0];
            c0[1] = acc[am][an][1];
            float* c2 = c0 + (size_t)8 * N;
            c2[0] = acc[am][an][2];
            c2[1] = acc[am][an][3];
        }
    }
}

// ---------------------------------------------------------------------------
// RoPE on Q (heads 0..31) and K (heads 32..39) in-place on g_qkv.
// ---------------------------------------------------------------------------
__global__ void rope_kernel(const int* __restrict__ positions)
{
    const int s = blockIdx.x;
    const int h = blockIdx.y;          // 0..39
    const int d = threadIdx.x;         // 0..63

    const float pos = (float)positions[s];
    const float inv_freq = powf(1000000.0f, -(float)d * (1.0f / 64.0f));
    const float ang = pos * inv_freq;
    float sn, cs;
    sincosf(ang, &sn, &cs);

    float* base = g_qkv + (size_t)s * QKV_N + h * HD;
    const float x1 = base[d];
    const float x2 = base[d + 64];
    base[d]      = x1 * cs - x2 * sn;
    base[d + 64] = x2 * cs + x1 * sn;
}

// ---------------------------------------------------------------------------
// Causal GQA flash attention. 64x64 tiles, 256 threads (16x16), fp32,
// online softmax; P staged through smem for the PV GEMM.
// ---------------------------------------------------------------------------
#define QS_STRIDE 68
#define VS_STRIDE 132
#define FLASH_SMEM_FLOATS (128*QS_STRIDE + 128*QS_STRIDE + 64*VS_STRIDE + 64*68)
#define FLASH_SMEM_BYTES  (FLASH_SMEM_FLOATS * 4)

__global__ __launch_bounds__(256)
void flash_kernel()
{
    extern __shared__ float sm[];
    float* Qs = sm;                         // [d=128][r=64] stride 68
    float* Ks = Qs + 128 * QS_STRIDE;       // [d=128][c=64] stride 68
    float* Vs = Ks + 128 * QS_STRIDE;       // [k=64][d=128] stride 132
    float* Ps = Vs + 64 * VS_STRIDE;        // [k=64][r=64] stride 68

    const int tid = threadIdx.x;
    const int tx  = tid & 15;
    const int ty  = tid >> 4;
    const int qt  = gridDim.x - 1 - blockIdx.x;
    const int h   = blockIdx.y;
    const int kh  = h >> 2;

    const float* Qg = g_qkv + (size_t)(qt * 64) * QKV_N + h * HD;
    const float* Kg = g_qkv + NH * HD + kh * HD;
    const float* Vg = g_qkv + (NH + NKV) * HD + kh * HD;

    for (int i = tid; i < 64 * 32; i += 256) {
        const int r  = i >> 5;
        const int d4 = (i & 31) * 4;
        float4 v = *(const float4*)(Qg + (size_t)r * QKV_N + d4);
        Qs[(d4 + 0) * QS_STRIDE + r] = v.x;
        Qs[(d4 + 1) * QS_STRIDE + r] = v.y;
        Qs[(d4 + 2) * QS_STRIDE + r] = v.z;
        Qs[(d4 + 3) * QS_STRIDE + r] = v.w;
    }

    float mrow[4], lrow[4], acc[4][8];
#pragma unroll
    for (int i = 0; i < 4; i++) {
        mrow[i] = -INFINITY;
        lrow[i] = 0.0f;
#pragma unroll
        for (int j = 0; j < 8; j++) acc[i][j] = 0.0f;
    }

    for (int jt = 0; jt <= qt; jt++) {
        __syncthreads();

        const float* Kt = Kg + (size_t)(jt * 64) * QKV_N;
        const float* Vt = Vg + (size_t)(jt * 64) * QKV_N;
        for (int i = tid; i < 64 * 32; i += 256) {
            const int r  = i >> 5;
            const int d4 = (i & 31) * 4;
            float4 kv = *(const float4*)(Kt + (size_t)r * QKV_N + d4);
            Ks[(d4 + 0) * QS_STRIDE + r] = kv.x;
            Ks[(d4 + 1) * QS_STRIDE + r] = kv.y;
            Ks[(d4 + 2) * QS_STRIDE + r] = kv.z;
            Ks[(d4 + 3) * QS_STRIDE + r] = kv.w;
            float4 vv = *(const float4*)(Vt + (size_t)r * QKV_N + d4);
            *(float4*)&Vs[r * VS_STRIDE + d4] = vv;
        }
        __syncthreads();

        float s4[4][4];
#pragma unroll
        for (int i = 0; i < 4; i++)
#pragma unroll
            for (int j = 0; j < 4; j++) s4[i][j] = 0.0f;

#pragma unroll 4
        for (int d = 0; d < 128; d++) {
            float4 a = *(const float4*)&Qs[d * QS_STRIDE + ty * 4];
            float4 b = *(const float4*)&Ks[d * QS_STRIDE + tx * 4];
            float av[4] = {a.x, a.y, a.z, a.w};
            float bv[4] = {b.x, b.y, b.z, b.w};
#pragma unroll
            for (int i = 0; i < 4; i++)
#pragma unroll
                for (int j = 0; j < 4; j++)
                    s4[i][j] += av[i] * bv[j];
        }

        const int qrow0 = qt * 64 + ty * 4;
        const int kcol0 = jt * 64 + tx * 4;
#pragma unroll
        for (int i = 0; i < 4; i++)
#pragma unroll
            for (int j = 0; j < 4; j++) {
                float sv = s4[i][j] * ATT_SCALE;
                if (kcol0 + j > qrow0 + i) sv = -1e30f;
                s4[i][j] = sv;
            }

#pragma unroll
        for (int i = 0; i < 4; i++) {
            float rm = fmaxf(fmaxf(s4[i][0], s4[i][1]), fmaxf(s4[i][2], s4[i][3]));
#pragma unroll
            for (int msk = 1; msk < 16; msk <<= 1)
                rm = fmaxf(rm, __shfl_xor_sync(0xffffffffu, rm, msk));
            const float mn = fmaxf(mrow[i], rm);
            const float corr = expf(mrow[i] - mn);
            float rs = 0.0f;
#pragma unroll
            for (int j = 0; j < 4; j++) {
                float p = expf(s4[i][j] - mn);
                s4[i][j] = p;
                rs += p;
            }
#pragma unroll
            for (int msk = 1; msk < 16; msk <<= 1)
                rs += __shfl_xor_sync(0xffffffffu, rs, msk);
            lrow[i] = lrow[i] * corr + rs;
            mrow[i] = mn;
#pragma unroll
            for (int j = 0; j < 8; j++) acc[i][j] *= corr;
        }

#pragma unroll
        for (int i = 0; i < 4; i++)
#pragma unroll
            for (int j = 0; j < 4; j++)
                Ps[(tx * 4 + j) * 68 + ty * 4 + i] = s4[i][j];
        __syncthreads();

#pragma unroll 4
        for (int k = 0; k < 64; k++) {
            float4 p  = *(const float4*)&Ps[k * 68 + ty * 4];
            float4 v0 = *(const float4*)&Vs[k * VS_STRIDE + tx * 8];
            float4 v1 = *(const float4*)&Vs[k * VS_STRIDE + tx * 8 + 4];
            float pv[4] = {p.x, p.y, p.z, p.w};
            float vv[8] = {v0.x, v0.y, v0.z, v0.w, v1.x, v1.y, v1.z, v1.w};
#pragma unroll
            for (int i = 0; i < 4; i++)
#pragma unroll
                for (int j = 0; j < 8; j++)
                    acc[i][j] += pv[i] * vv[j];
        }
    }

#pragma unroll
    for (int i = 0; i < 4; i++) {
        const float inv_l = 1.0f / lrow[i];
        const int row = qt * 64 + ty * 4 + i;
        float* op = g_attn + (size_t)row * H_DIM + h * HD + tx * 8;
        *(float4*)(op + 0) = make_float4(acc[i][0] * inv_l, acc[i][1] * inv_l,
                                         acc[i][2] * inv_l, acc[i][3] * inv_l);
        *(float4*)(op + 4) = make_float4(acc[i][4] * inv_l, acc[i][5] * inv_l,
                                         acc[i][6] * inv_l, acc[i][7] * inv_l);
    }
}

// ---------------------------------------------------------------------------
// Launch
// ---------------------------------------------------------------------------
extern "C" void kernel_launch(void* const* d_in, const int* in_sizes, int n_in,
                              void* d_out, int out_size)
{
    (void)in_sizes; (void)n_in; (void)out_size;
    const int*   positions = (const int*)d_in[0];
    const float* hidden    = (const float*)d_in[1];
    const float* w_qkv     = (const float*)d_in[2];
    const float* w_o       = (const float*)d_in[3];
    float*       out       = (float*)d_out;

    float *qkv_ptr = nullptr, *attn_ptr = nullptr;
    cudaGetSymbolAddress((void**)&qkv_ptr, g_qkv);
    cudaGetSymbolAddress((void**)&attn_ptr, g_attn);

    cudaFuncSetAttribute(flash_kernel,
                         cudaFuncAttributeMaxDynamicSharedMemorySize,
                         FLASH_SMEM_BYTES);

    // 1) QKV projection: [2048,6144] = hidden[2048,4096] @ w_qkv^T
    gemm_tf32_nt<<<dim3(QKV_N / BN, S_LEN / BM), 256>>>(
        S_LEN, QKV_N, H_DIM, hidden, w_qkv, qkv_ptr);

    // 2) RoPE on Q and K heads (in-place)
    rope_kernel<<<dim3(S_LEN, NH + NKV), 64>>>(positions);

    // 3) Causal GQA flash attention -> g_attn
    flash_kernel<<<dim3(S_LEN / 64, NH), 256, FLASH_SMEM_BYTES>>>();

    // 4) Output projection: out[2048,4096] = g_attn @ w_o^T
    gemm_tf32_nt<<<dim3(H_DIM / BN, S_LEN / BM), 256>>>(
        S_LEN, H_DIM, H_DIM, attn_ptr, w_o, out);
}

// round 3
// speedup vs baseline: 2.5763x; 1.4480x over previous
#include <cuda_runtime.h>
#include <math.h>
#include <stdint.h>

#define S_LEN 2048
#define H_DIM 4096
#define NH 32
#define NKV 8
#define HD 128
#define QKV_N 6144
#define ATT_SCALE 0.08838834764831843f

__device__ float g_qkv[S_LEN * QKV_N];
__device__ float g_attn[S_LEN * H_DIM];

__device__ __forceinline__ uint32_t f2tf(float x) {
    uint32_t r;
    asm("cvt.rna.tf32.f32 %0, %1;" : "=r"(r) : "f"(x));
    return r;
}

#define MMA_TF32(ACC, A0, A1, A2, A3, B0, B1)                                  \
    asm volatile(                                                              \
        "mma.sync.aligned.m16n8k8.row.col.f32.tf32.tf32.f32 "                  \
        "{%0,%1,%2,%3}, {%4,%5,%6,%7}, {%8,%9}, {%0,%1,%2,%3};\n"              \
        : "+f"(ACC[0]), "+f"(ACC[1]), "+f"(ACC[2]), "+f"(ACC[3])               \
        : "r"(A0), "r"(A1), "r"(A2), "r"(A3), "r"(B0), "r"(B1))

// ---------------------------------------------------------------------------
// TF32 GEMM (NT), double-buffered smem: C[M,N] = A[M,K] * B[N,K]^T
// ---------------------------------------------------------------------------
#define BM 128
#define BN 128
#define BK 16
#define TSTR 20

__global__ __launch_bounds__(256)
void gemm_tf32_nt(int M, int N, int K,
                  const float* __restrict__ A,
                  const float* __restrict__ B,
                  float* __restrict__ C)
{
    __shared__ uint32_t As[2][BM * TSTR];
    __shared__ uint32_t Bs[2][BN * TSTR];

    const int tid  = threadIdx.x;
    const int warp = tid >> 5;
    const int lane = tid & 31;
    const int g    = lane >> 2;
    const int t    = lane & 3;

    const int bm = blockIdx.y * BM;
    const int bn = blockIdx.x * BN;
    const int wm = (warp & 1) * 64;
    const int wn = (warp >> 1) * 32;

    const int lr = tid >> 1;
    const int lc = (tid & 1) * 8;

    const float* Ap = A + (size_t)(bm + lr) * K + lc;
    const float* Bp = B + (size_t)(bn + lr) * K + lc;

    float acc[4][4][4];
#pragma unroll
    for (int i = 0; i < 4; i++)
#pragma unroll
        for (int j = 0; j < 4; j++)
#pragma unroll
            for (int r = 0; r < 4; r++) acc[i][j][r] = 0.0f;

    // prologue: load + store stage 0
    float4 av0 = *(const float4*)(Ap + 0);
    float4 av1 = *(const float4*)(Ap + 4);
    float4 bv0 = *(const float4*)(Bp + 0);
    float4 bv1 = *(const float4*)(Bp + 4);
    Ap += BK; Bp += BK;
    {
        uint32_t* as = &As[0][lr * TSTR + lc];
        as[0]=f2tf(av0.x); as[1]=f2tf(av0.y); as[2]=f2tf(av0.z); as[3]=f2tf(av0.w);
        as[4]=f2tf(av1.x); as[5]=f2tf(av1.y); as[6]=f2tf(av1.z); as[7]=f2tf(av1.w);
        uint32_t* bs = &Bs[0][lr * TSTR + lc];
        bs[0]=f2tf(bv0.x); bs[1]=f2tf(bv0.y); bs[2]=f2tf(bv0.z); bs[3]=f2tf(bv0.w);
        bs[4]=f2tf(bv1.x); bs[5]=f2tf(bv1.y); bs[6]=f2tf(bv1.z); bs[7]=f2tf(bv1.w);
    }
    __syncthreads();

    int p = 0;
    for (int k0 = 0; k0 < K; k0 += BK) {
        const bool more = (k0 + BK < K);
        if (more) {
            av0 = *(const float4*)(Ap + 0);
            av1 = *(const float4*)(Ap + 4);
            bv0 = *(const float4*)(Bp + 0);
            bv1 = *(const float4*)(Bp + 4);
            Ap += BK; Bp += BK;
        }

#pragma unroll
        for (int ks = 0; ks < 2; ks++) {
            const int kb = ks * 8;
            uint32_t a[4][4], b[4][2];
#pragma unroll
            for (int am = 0; am < 4; am++) {
                const int r = wm + am * 16;
                a[am][0] = As[p][(r +     g) * TSTR + kb +     t];
                a[am][1] = As[p][(r + 8 + g) * TSTR + kb +     t];
                a[am][2] = As[p][(r +     g) * TSTR + kb + 4 + t];
                a[am][3] = As[p][(r + 8 + g) * TSTR + kb + 4 + t];
            }
#pragma unroll
            for (int an = 0; an < 4; an++) {
                const int c = wn + an * 8;
                b[an][0] = Bs[p][(c + g) * TSTR + kb +     t];
                b[an][1] = Bs[p][(c + g) * TSTR + kb + 4 + t];
            }
#pragma unroll
            for (int am = 0; am < 4; am++)
#pragma unroll
                for (int an = 0; an < 4; an++)
                    MMA_TF32(acc[am][an], a[am][0], a[am][1], a[am][2], a[am][3],
                             b[an][0], b[an][1]);
        }

        if (more) {
            uint32_t* as = &As[p ^ 1][lr * TSTR + lc];
            as[0]=f2tf(av0.x); as[1]=f2tf(av0.y); as[2]=f2tf(av0.z); as[3]=f2tf(av0.w);
            as[4]=f2tf(av1.x); as[5]=f2tf(av1.y); as[6]=f2tf(av1.z); as[7]=f2tf(av1.w);
            uint32_t* bs = &Bs[p ^ 1][lr * TSTR + lc];
            bs[0]=f2tf(bv0.x); bs[1]=f2tf(bv0.y); bs[2]=f2tf(bv0.z); bs[3]=f2tf(bv0.w);
            bs[4]=f2tf(bv1.x); bs[5]=f2tf(bv1.y); bs[6]=f2tf(bv1.z); bs[7]=f2tf(bv1.w);
        }
        __syncthreads();
        p ^= 1;
    }

#pragma unroll
    for (int am = 0; am < 4; am++) {
        const int row0 = bm + wm + am * 16 + g;
#pragma unroll
        for (int an = 0; an < 4; an++) {
            const int col = bn + wn + an * 8 + t * 2;
            float* c0 = C + (size_t)row0 * N + col;
            c0[0] = acc[am][an][0];
            c0[1] = acc[am][an][1];
            float* c2 = c0 + (size_t)8 * N;
            c2[0] = acc[am][an][2];
            c2[1] = acc[am][an][3];
        }
    }
}

// ---------------------------------------------------------------------------
// RoPE (in-place on g_qkv; q heads 0..31 and k heads 32..39 are contiguous)
// ---------------------------------------------------------------------------
__global__ void rope_kernel(const int* __restrict__ positions)
{
    const int s = blockIdx.x;
    const int h = blockIdx.y;
    const int d = threadIdx.x;

    const float pos = (float)positions[s];
    const float inv_freq = powf(1000000.0f, -(float)d * (1.0f / 64.0f));
    const float ang = pos * inv_freq;
    float sn, cs;
    sincosf(ang, &sn, &cs);

    float* base = g_qkv + (size_t)s * QKV_N + h * HD;
    const float x1 = base[d];
    const float x2 = base[d + 64];
    base[d]      = x1 * cs - x2 * sn;
    base[d + 64] = x2 * cs + x1 * sn;
}

// ---------------------------------------------------------------------------
// Tensor-core causal GQA flash attention.
// q-tile 128 rows (8 warps x 16), k-tiles 64. mma.m16n8k8.tf32.
// smem strides: 132 for [row][d] tiles (conflict-free frags), 68 for P.
// ---------------------------------------------------------------------------
#define FKSTR 132
#define FPSTR 68
#define FLASH_SMEM_WORDS (128*FKSTR + 64*FKSTR + 64*FKSTR + 128*FPSTR)
#define FLASH_SMEM_BYTES (FLASH_SMEM_WORDS * 4)

__global__ __launch_bounds__(256)
void flash_tc_kernel()
{
    extern __shared__ uint32_t fsm[];
    uint32_t* Qs = fsm;                   // [128][132] q rows x d
    uint32_t* Ks = Qs + 128 * FKSTR;      // [64][132]  k rows x d
    uint32_t* Vs = Ks + 64 * FKSTR;       // [64][132]  k rows x d (read transposed)
    uint32_t* Ps = Vs + 64 * FKSTR;       // [128][68]  q rows x kpos

    const int tid  = threadIdx.x;
    const int warp = tid >> 5;
    const int lane = tid & 31;
    const int g    = lane >> 2;
    const int t    = lane & 3;
    const int qt   = gridDim.x - 1 - blockIdx.x;   // heavy tiles first
    const int h    = blockIdx.y;
    const int kh   = h >> 2;
    const int wr   = warp * 16;

    const float* Qg = g_qkv + (size_t)(qt * 128) * QKV_N + h * HD;
    const float* Kg = g_qkv + NH * HD + kh * HD;
    const float* Vg = g_qkv + (NH + NKV) * HD + kh * HD;

    // load Q tile (tf32)
    for (int i = tid; i < 128 * 32; i += 256) {
        const int r  = i >> 5;
        const int d4 = (i & 31) * 4;
        float4 v = *(const float4*)(Qg + (size_t)r * QKV_N + d4);
        *(uint4*)&Qs[r * FKSTR + d4] =
            make_uint4(f2tf(v.x), f2tf(v.y), f2tf(v.z), f2tf(v.w));
    }

    float m0 = -INFINITY, m1 = -INFINITY, l0 = 0.0f, l1 = 0.0f;
    float o[16][4];
#pragma unroll
    for (int nf = 0; nf < 16; nf++)
#pragma unroll
        for (int r = 0; r < 4; r++) o[nf][r] = 0.0f;

    const int row0 = qt * 128 + wr + g;    // row for c0/c1 (c2/c3 at row0+8)
    const int n_ktiles = 2 * qt + 2;

    for (int jt = 0; jt < n_ktiles; jt++) {
        __syncthreads();   // K/V consumed (prev iter); Q stores visible (first)

        const float* Kt = Kg + (size_t)(jt * 64) * QKV_N;
        const float* Vt = Vg + (size_t)(jt * 64) * QKV_N;
        for (int i = tid; i < 64 * 32; i += 256) {
            const int r  = i >> 5;
            const int d4 = (i & 31) * 4;
            float4 kv = *(const float4*)(Kt + (size_t)r * QKV_N + d4);
            *(uint4*)&Ks[r * FKSTR + d4] =
                make_uint4(f2tf(kv.x), f2tf(kv.y), f2tf(kv.z), f2tf(kv.w));
            float4 vv = *(const float4*)(Vt + (size_t)r * QKV_N + d4);
            *(uint4*)&Vs[r * FKSTR + d4] =
                make_uint4(f2tf(vv.x), f2tf(vv.y), f2tf(vv.z), f2tf(vv.w));
        }
        __syncthreads();

        // ---- S = Q K^T  (warp: 16 x 64, k=128) ----
        float s[8][4];
#pragma unroll
        for (int nf = 0; nf < 8; nf++)
#pragma unroll
            for (int r = 0; r < 4; r++) s[nf][r] = 0.0f;

#pragma unroll
        for (int kc = 0; kc < 16; kc++) {
            const int kb = kc * 8;
            uint32_t a0 = Qs[(wr +     g) * FKSTR + kb +     t];
            uint32_t a1 = Qs[(wr + 8 + g) * FKSTR + kb +     t];
            uint32_t a2 = Qs[(wr +     g) * FKSTR + kb + 4 + t];
            uint32_t a3 = Qs[(wr + 8 + g) * FKSTR + kb + 4 + t];
#pragma unroll
            for (int nf = 0; nf < 8; nf++) {
                uint32_t b0 = Ks[(nf * 8 + g) * FKSTR + kb +     t];
                uint32_t b1 = Ks[(nf * 8 + g) * FKSTR + kb + 4 + t];
                MMA_TF32(s[nf], a0, a1, a2, a3, b0, b1);
            }
        }

        // ---- scale + causal mask ----
        const int colbase = jt * 64 + 2 * t;
#pragma unroll
        for (int nf = 0; nf < 8; nf++) {
            const int col = colbase + nf * 8;
            float v0 = s[nf][0] * ATT_SCALE;
            float v1 = s[nf][1] * ATT_SCALE;
            float v2 = s[nf][2] * ATT_SCALE;
            float v3 = s[nf][3] * ATT_SCALE;
            if (col     > row0)     v0 = -1e30f;
            if (col + 1 > row0)     v1 = -1e30f;
            if (col     > row0 + 8) v2 = -1e30f;
            if (col + 1 > row0 + 8) v3 = -1e30f;
            s[nf][0] = v0; s[nf][1] = v1; s[nf][2] = v2; s[nf][3] = v3;
        }

        // ---- online softmax (rows spread over 4 lanes t) ----
        float rm0 = -INFINITY, rm1 = -INFINITY;
#pragma unroll
        for (int nf = 0; nf < 8; nf++) {
            rm0 = fmaxf(rm0, fmaxf(s[nf][0], s[nf][1]));
            rm1 = fmaxf(rm1, fmaxf(s[nf][2], s[nf][3]));
        }
        rm0 = fmaxf(rm0, __shfl_xor_sync(0xffffffffu, rm0, 1));
        rm0 = fmaxf(rm0, __shfl_xor_sync(0xffffffffu, rm0, 2));
        rm1 = fmaxf(rm1, __shfl_xor_sync(0xffffffffu, rm1, 1));
        rm1 = fmaxf(rm1, __shfl_xor_sync(0xffffffffu, rm1, 2));

        const float mn0 = fmaxf(m0, rm0);
        const float mn1 = fmaxf(m1, rm1);
        const float cr0 = __expf(m0 - mn0);
        const float cr1 = __expf(m1 - mn1);

        float rs0 = 0.0f, rs1 = 0.0f;
#pragma unroll
        for (int nf = 0; nf < 8; nf++) {
            s[nf][0] = __expf(s[nf][0] - mn0);
            s[nf][1] = __expf(s[nf][1] - mn0);
            s[nf][2] = __expf(s[nf][2] - mn1);
            s[nf][3] = __expf(s[nf][3] - mn1);
            rs0 += s[nf][0] + s[nf][1];
            rs1 += s[nf][2] + s[nf][3];
        }
        rs0 += __shfl_xor_sync(0xffffffffu, rs0, 1);
        rs0 += __shfl_xor_sync(0xffffffffu, rs0, 2);
        rs1 += __shfl_xor_sync(0xffffffffu, rs1, 1);
        rs1 += __shfl_xor_sync(0xffffffffu, rs1, 2);

        l0 = l0 * cr0 + rs0;  m0 = mn0;
        l1 = l1 * cr1 + rs1;  m1 = mn1;

#pragma unroll
        for (int nf = 0; nf < 16; nf++) {
            o[nf][0] *= cr0;  o[nf][1] *= cr0;
            o[nf][2] *= cr1;  o[nf][3] *= cr1;
        }

        // ---- stage P (tf32) into per-warp smem region ----
#pragma unroll
        for (int nf = 0; nf < 8; nf++) {
            const int c = nf * 8 + 2 * t;
            *(uint2*)&Ps[(wr +     g) * FPSTR + c] =
                make_uint2(f2tf(s[nf][0]), f2tf(s[nf][1]));
            *(uint2*)&Ps[(wr + 8 + g) * FPSTR + c] =
                make_uint2(f2tf(s[nf][2]), f2tf(s[nf][3]));
        }
        __syncwarp();

        // ---- O += P V  (warp: 16 x 128, k=64) ----
#pragma unroll
        for (int kc = 0; kc < 8; kc++) {
            const int kb = kc * 8;
            uint32_t a0 = Ps[(wr +     g) * FPSTR + kb +     t];
            uint32_t a1 = Ps[(wr + 8 + g) * FPSTR + kb +     t];
            uint32_t a2 = Ps[(wr +     g) * FPSTR + kb + 4 + t];
            uint32_t a3 = Ps[(wr + 8 + g) * FPSTR + kb + 4 + t];
#pragma unroll
            for (int nf = 0; nf < 16; nf++) {
                uint32_t b0 = Vs[(kb +     t) * FKSTR + nf * 8 + g];
                uint32_t b1 = Vs[(kb + 4 + t) * FKSTR + nf * 8 + g];
                MMA_TF32(o[nf], a0, a1, a2, a3, b0, b1);
            }
        }
        __syncwarp();   // Ps reads done before next iteration overwrites
    }

    // ---- epilogue ----
    const float il0 = 1.0f / l0;
    const float il1 = 1.0f / l1;
#pragma unroll
    for (int nf = 0; nf < 16; nf++) {
        const int col = h * HD + nf * 8 + 2 * t;
        float* p0 = g_attn + (size_t)row0 * H_DIM + col;
        p0[0] = o[nf][0] * il0;
        p0[1] = o[nf][1] * il0;
        float* p1 = g_attn + (size_t)(row0 + 8) * H_DIM + col;
        p1[0] = o[nf][2] * il1;
        p1[1] = o[nf][3] * il1;
    }
}

// ---------------------------------------------------------------------------
// Launch
// ---------------------------------------------------------------------------
extern "C" void kernel_launch(void* const* d_in, const int* in_sizes, int n_in,
                              void* d_out, int out_size)
{
    (void)in_sizes; (void)n_in; (void)out_size;
    const int*   positions = (const int*)d_in[0];
    const float* hidden    = (const float*)d_in[1];
    const float* w_qkv     = (const float*)d_in[2];
    const float* w_o       = (const float*)d_in[3];
    float*       out       = (float*)d_out;

    float *qkv_ptr = nullptr, *attn_ptr = nullptr;
    cudaGetSymbolAddress((void**)&qkv_ptr, g_qkv);
    cudaGetSymbolAddress((void**)&attn_ptr, g_attn);

    cudaFuncSetAttribute(flash_tc_kernel,
                         cudaFuncAttributeMaxDynamicSharedMemorySize,
                         FLASH_SMEM_BYTES);

    gemm_tf32_nt<<<dim3(QKV_N / BN, S_LEN / BM), 256>>>(
        S_LEN, QKV_N, H_DIM, hidden, w_qkv, qkv_ptr);

    rope_kernel<<<dim3(S_LEN, NH + NKV), 64>>>(positions);

    flash_tc_kernel<<<dim3(S_LEN / 128, NH), 256, FLASH_SMEM_BYTES>>>();

    gemm_tf32_nt<<<dim3(H_DIM / BN, S_LEN / BM), 256>>>(
        S_LEN, H_DIM, H_DIM, attn_ptr, w_o, out);
}

// round 4
// speedup vs baseline: 2.8220x; 1.0954x over previous
#include <cuda_runtime.h>
#include <math.h>
#include <stdint.h>

#define S_LEN 2048
#define H_DIM 4096
#define NH 32
#define NKV 8
#define HD 128
#define QKV_N 6144
#define ATT_SCALE 0.08838834764831843f

__device__ float g_qkv[S_LEN * QKV_N];
__device__ float g_attn[S_LEN * H_DIM];

__device__ __forceinline__ uint32_t f2tf(float x) {
    uint32_t r;
    asm("cvt.rna.tf32.f32 %0, %1;" : "=r"(r) : "f"(x));
    return r;
}

#define MMA_TF32(ACC, A0, A1, A2, A3, B0, B1)                                  \
    asm volatile(                                                              \
        "mma.sync.aligned.m16n8k8.row.col.f32.tf32.tf32.f32 "                  \
        "{%0,%1,%2,%3}, {%4,%5,%6,%7}, {%8,%9}, {%0,%1,%2,%3};\n"              \
        : "+f"(ACC[0]), "+f"(ACC[1]), "+f"(ACC[2]), "+f"(ACC[3])               \
        : "r"(A0), "r"(A1), "r"(A2), "r"(A3), "r"(B0), "r"(B1))

// ---------------------------------------------------------------------------
// TF32 GEMM (NT) — round-2 single-buffer version (measured faster than the
// double-buffered variant: 719.9us vs 765.2us, regs 102 vs 119).
// ---------------------------------------------------------------------------
#define BM 128
#define BN 128
#define BK 16
#define TSTR 20

__global__ __launch_bounds__(256)
void gemm_tf32_nt(int M, int N, int K,
                  const float* __restrict__ A,
                  const float* __restrict__ B,
                  float* __restrict__ C)
{
    __shared__ uint32_t As[BM * TSTR];
    __shared__ uint32_t Bs[BN * TSTR];

    const int tid  = threadIdx.x;
    const int warp = tid >> 5;
    const int lane = tid & 31;
    const int g    = lane >> 2;
    const int t    = lane & 3;

    const int bm = blockIdx.y * BM;
    const int bn = blockIdx.x * BN;
    const int wm = (warp & 1) * 64;
    const int wn = (warp >> 1) * 32;

    const int lr = tid >> 1;
    const int lc = (tid & 1) * 8;

    const float* Ap = A + (size_t)(bm + lr) * K + lc;
    const float* Bp = B + (size_t)(bn + lr) * K + lc;

    float acc[4][4][4];
#pragma unroll
    for (int i = 0; i < 4; i++)
#pragma unroll
        for (int j = 0; j < 4; j++)
#pragma unroll
            for (int r = 0; r < 4; r++) acc[i][j][r] = 0.0f;

    for (int k0 = 0; k0 < K; k0 += BK) {
        float4 av0 = *(const float4*)(Ap + 0);
        float4 av1 = *(const float4*)(Ap + 4);
        float4 bv0 = *(const float4*)(Bp + 0);
        float4 bv1 = *(const float4*)(Bp + 4);
        Ap += BK; Bp += BK;

        __syncthreads();
        uint32_t* as = &As[lr * TSTR + lc];
        as[0]=f2tf(av0.x); as[1]=f2tf(av0.y); as[2]=f2tf(av0.z); as[3]=f2tf(av0.w);
        as[4]=f2tf(av1.x); as[5]=f2tf(av1.y); as[6]=f2tf(av1.z); as[7]=f2tf(av1.w);
        uint32_t* bs = &Bs[lr * TSTR + lc];
        bs[0]=f2tf(bv0.x); bs[1]=f2tf(bv0.y); bs[2]=f2tf(bv0.z); bs[3]=f2tf(bv0.w);
        bs[4]=f2tf(bv1.x); bs[5]=f2tf(bv1.y); bs[6]=f2tf(bv1.z); bs[7]=f2tf(bv1.w);
        __syncthreads();

#pragma unroll
        for (int ks = 0; ks < 2; ks++) {
            const int kb = ks * 8;
            uint32_t a[4][4], b[4][2];
#pragma unroll
            for (int am = 0; am < 4; am++) {
                const int r = wm + am * 16;
                a[am][0] = As[(r +     g) * TSTR + kb +     t];
                a[am][1] = As[(r + 8 + g) * TSTR + kb +     t];
                a[am][2] = As[(r +     g) * TSTR + kb + 4 + t];
                a[am][3] = As[(r + 8 + g) * TSTR + kb + 4 + t];
            }
#pragma unroll
            for (int an = 0; an < 4; an++) {
                const int c = wn + an * 8;
                b[an][0] = Bs[(c + g) * TSTR + kb +     t];
                b[an][1] = Bs[(c + g) * TSTR + kb + 4 + t];
            }
#pragma unroll
            for (int am = 0; am < 4; am++)
#pragma unroll
                for (int an = 0; an < 4; an++)
                    MMA_TF32(acc[am][an], a[am][0], a[am][1], a[am][2], a[am][3],
                             b[an][0], b[an][1]);
        }
    }

#pragma unroll
    for (int am = 0; am < 4; am++) {
        const int row0 = bm + wm + am * 16 + g;
#pragma unroll
        for (int an = 0; an < 4; an++) {
            const int col = bn + wn + an * 8 + t * 2;
            float* c0 = C + (size_t)row0 * N + col;
            c0[0] = acc[am][an][0];
            c0[1] = acc[am][an][1];
            float* c2 = c0 + (size_t)8 * N;
            c2[0] = acc[am][an][2];
            c2[1] = acc[am][an][3];
        }
    }
}

// ---------------------------------------------------------------------------
// RoPE (in-place on g_qkv)
// ---------------------------------------------------------------------------
__global__ void rope_kernel(const int* __restrict__ positions)
{
    const int s = blockIdx.x;
    const int h = blockIdx.y;
    const int d = threadIdx.x;

    const float pos = (float)positions[s];
    const float inv_freq = powf(1000000.0f, -(float)d * (1.0f / 64.0f));
    const float ang = pos * inv_freq;
    float sn, cs;
    sincosf(ang, &sn, &cs);

    float* base = g_qkv + (size_t)s * QKV_N + h * HD;
    const float x1 = base[d];
    const float x2 = base[d + 64];
    base[d]      = x1 * cs - x2 * sn;
    base[d + 64] = x2 * cs + x1 * sn;
}

// ---------------------------------------------------------------------------
// Tensor-core causal GQA flash attention.
// q-tile 128 rows (8 warps x 16), k-tiles 64. mma.m16n8k8.tf32.
// Q/K: [row][d] stride 132 (conflict-free frags).
// V:   [row][d] stride 128 with XOR swizzle col^=((row&3)<<3)
//      -> conflict-free transposed b-frag reads AND conflict-free uint4 stores.
// P:   [row][kpos] stride 68.
// ---------------------------------------------------------------------------
#define FKSTR 132
#define FVSTR 128
#define FPSTR 68
#define FLASH_SMEM_WORDS (128*FKSTR + 64*FKSTR + 64*FVSTR + 128*FPSTR)
#define FLASH_SMEM_BYTES (FLASH_SMEM_WORDS * 4)

__global__ __launch_bounds__(256)
void flash_tc_kernel()
{
    extern __shared__ uint32_t fsm[];
    uint32_t* Qs = fsm;                   // [128][132]
    uint32_t* Ks = Qs + 128 * FKSTR;      // [64][132]
    uint32_t* Vs = Ks + 64 * FKSTR;       // [64][128] swizzled
    uint32_t* Ps = Vs + 64 * FVSTR;       // [128][68]

    const int tid  = threadIdx.x;
    const int warp = tid >> 5;
    const int lane = tid & 31;
    const int g    = lane >> 2;
    const int t    = lane & 3;
    const int qt   = gridDim.x - 1 - blockIdx.x;
    const int h    = blockIdx.y;
    const int kh   = h >> 2;
    const int wr   = warp * 16;

    const float* Qg = g_qkv + (size_t)(qt * 128) * QKV_N + h * HD;
    const float* Kg = g_qkv + NH * HD + kh * HD;
    const float* Vg = g_qkv + (NH + NKV) * HD + kh * HD;

    for (int i = tid; i < 128 * 32; i += 256) {
        const int r  = i >> 5;
        const int d4 = (i & 31) * 4;
        float4 v = *(const float4*)(Qg + (size_t)r * QKV_N + d4);
        *(uint4*)&Qs[r * FKSTR + d4] =
            make_uint4(f2tf(v.x), f2tf(v.y), f2tf(v.z), f2tf(v.w));
    }

    float m0 = -INFINITY, m1 = -INFINITY, l0 = 0.0f, l1 = 0.0f;
    float o[16][4];
#pragma unroll
    for (int nf = 0; nf < 16; nf++)
#pragma unroll
        for (int r = 0; r < 4; r++) o[nf][r] = 0.0f;

    const int row0 = qt * 128 + wr + g;
    const int n_ktiles = 2 * qt + 2;

    for (int jt = 0; jt < n_ktiles; jt++) {
        __syncthreads();

        const float* Kt = Kg + (size_t)(jt * 64) * QKV_N;
        const float* Vt = Vg + (size_t)(jt * 64) * QKV_N;
        for (int i = tid; i < 64 * 32; i += 256) {
            const int r  = i >> 5;
            const int d4 = (i & 31) * 4;
            float4 kv = *(const float4*)(Kt + (size_t)r * QKV_N + d4);
            *(uint4*)&Ks[r * FKSTR + d4] =
                make_uint4(f2tf(kv.x), f2tf(kv.y), f2tf(kv.z), f2tf(kv.w));
            float4 vv = *(const float4*)(Vt + (size_t)r * QKV_N + d4);
            const int dsw = d4 ^ ((r & 3) << 3);   // XOR swizzle (16B-preserving)
            *(uint4*)&Vs[r * FVSTR + dsw] =
                make_uint4(f2tf(vv.x), f2tf(vv.y), f2tf(vv.z), f2tf(vv.w));
        }
        __syncthreads();

        // ---- S = Q K^T ----
        float s[8][4];
#pragma unroll
        for (int nf = 0; nf < 8; nf++)
#pragma unroll
            for (int r = 0; r < 4; r++) s[nf][r] = 0.0f;

#pragma unroll
        for (int kc = 0; kc < 16; kc++) {
            const int kb = kc * 8;
            uint32_t a0 = Qs[(wr +     g) * FKSTR + kb +     t];
            uint32_t a1 = Qs[(wr + 8 + g) * FKSTR + kb +     t];
            uint32_t a2 = Qs[(wr +     g) * FKSTR + kb + 4 + t];
            uint32_t a3 = Qs[(wr + 8 + g) * FKSTR + kb + 4 + t];
#pragma unroll
            for (int nf = 0; nf < 8; nf++) {
                uint32_t b0 = Ks[(nf * 8 + g) * FKSTR + kb +     t];
                uint32_t b1 = Ks[(nf * 8 + g) * FKSTR + kb + 4 + t];
                MMA_TF32(s[nf], a0, a1, a2, a3, b0, b1);
            }
        }

        // ---- scale + causal mask ----
        const int colbase = jt * 64 + 2 * t;
#pragma unroll
        for (int nf = 0; nf < 8; nf++) {
            const int col = colbase + nf * 8;
            float v0 = s[nf][0] * ATT_SCALE;
            float v1 = s[nf][1] * ATT_SCALE;
            float v2 = s[nf][2] * ATT_SCALE;
            float v3 = s[nf][3] * ATT_SCALE;
            if (col     > row0)     v0 = -1e30f;
            if (col + 1 > row0)     v1 = -1e30f;
            if (col     > row0 + 8) v2 = -1e30f;
            if (col + 1 > row0 + 8) v3 = -1e30f;
            s[nf][0] = v0; s[nf][1] = v1; s[nf][2] = v2; s[nf][3] = v3;
        }

        // ---- online softmax ----
        float rm0 = -INFINITY, rm1 = -INFINITY;
#pragma unroll
        for (int nf = 0; nf < 8; nf++) {
            rm0 = fmaxf(rm0, fmaxf(s[nf][0], s[nf][1]));
            rm1 = fmaxf(rm1, fmaxf(s[nf][2], s[nf][3]));
        }
        rm0 = fmaxf(rm0, __shfl_xor_sync(0xffffffffu, rm0, 1));
        rm0 = fmaxf(rm0, __shfl_xor_sync(0xffffffffu, rm0, 2));
        rm1 = fmaxf(rm1, __shfl_xor_sync(0xffffffffu, rm1, 1));
        rm1 = fmaxf(rm1, __shfl_xor_sync(0xffffffffu, rm1, 2));

        const float mn0 = fmaxf(m0, rm0);
        const float mn1 = fmaxf(m1, rm1);
        const float cr0 = __expf(m0 - mn0);
        const float cr1 = __expf(m1 - mn1);

        float rs0 = 0.0f, rs1 = 0.0f;
#pragma unroll
        for (int nf = 0; nf < 8; nf++) {
            s[nf][0] = __expf(s[nf][0] - mn0);
            s[nf][1] = __expf(s[nf][1] - mn0);
            s[nf][2] = __expf(s[nf][2] - mn1);
            s[nf][3] = __expf(s[nf][3] - mn1);
            rs0 += s[nf][0] + s[nf][1];
            rs1 += s[nf][2] + s[nf][3];
        }
        rs0 += __shfl_xor_sync(0xffffffffu, rs0, 1);
        rs0 += __shfl_xor_sync(0xffffffffu, rs0, 2);
        rs1 += __shfl_xor_sync(0xffffffffu, rs1, 1);
        rs1 += __shfl_xor_sync(0xffffffffu, rs1, 2);

        l0 = l0 * cr0 + rs0;  m0 = mn0;
        l1 = l1 * cr1 + rs1;  m1 = mn1;

#pragma unroll
        for (int nf = 0; nf < 16; nf++) {
            o[nf][0] *= cr0;  o[nf][1] *= cr0;
            o[nf][2] *= cr1;  o[nf][3] *= cr1;
        }

        // ---- stage P ----
#pragma unroll
        for (int nf = 0; nf < 8; nf++) {
            const int c = nf * 8 + 2 * t;
            *(uint2*)&Ps[(wr +     g) * FPSTR + c] =
                make_uint2(f2tf(s[nf][0]), f2tf(s[nf][1]));
            *(uint2*)&Ps[(wr + 8 + g) * FPSTR + c] =
                make_uint2(f2tf(s[nf][2]), f2tf(s[nf][3]));
        }
        __syncwarp();

        // ---- O += P V ----
#pragma unroll
        for (int kc = 0; kc < 8; kc++) {
            const int kb = kc * 8;
            uint32_t a0 = Ps[(wr +     g) * FPSTR + kb +     t];
            uint32_t a1 = Ps[(wr + 8 + g) * FPSTR + kb +     t];
            uint32_t a2 = Ps[(wr +     g) * FPSTR + kb + 4 + t];
            uint32_t a3 = Ps[(wr + 8 + g) * FPSTR + kb + 4 + t];
            const int sw = t << 3;          // (row&3)<<3 with row=kb+t / kb+4+t
#pragma unroll
            for (int nf = 0; nf < 16; nf++) {
                uint32_t b0 = Vs[(kb +     t) * FVSTR + ((nf * 8 + g) ^ sw)];
                uint32_t b1 = Vs[(kb + 4 + t) * FVSTR + ((nf * 8 + g) ^ sw)];
                MMA_TF32(o[nf], a0, a1, a2, a3, b0, b1);
            }
        }
        __syncwarp();
    }

    // ---- epilogue ----
    const float il0 = 1.0f / l0;
    const float il1 = 1.0f / l1;
#pragma unroll
    for (int nf = 0; nf < 16; nf++) {
        const int col = h * HD + nf * 8 + 2 * t;
        float* p0 = g_attn + (size_t)row0 * H_DIM + col;
        p0[0] = o[nf][0] * il0;
        p0[1] = o[nf][1] * il0;
        float* p1 = g_attn + (size_t)(row0 + 8) * H_DIM + col;
        p1[0] = o[nf][2] * il1;
        p1[1] = o[nf][3] * il1;
    }
}

// ---------------------------------------------------------------------------
// Launch
// ---------------------------------------------------------------------------
extern "C" void kernel_launch(void* const* d_in, const int* in_sizes, int n_in,
                              void* d_out, int out_size)
{
    (void)in_sizes; (void)n_in; (void)out_size;
    const int*   positions = (const int*)d_in[0];
    const float* hidden    = (const float*)d_in[1];
    const float* w_qkv     = (const float*)d_in[2];
    const float* w_o       = (const float*)d_in[3];
    float*       out       = (float*)d_out;

    float *qkv_ptr = nullptr, *attn_ptr = nullptr;
    cudaGetSymbolAddress((void**)&qkv_ptr, g_qkv);
    cudaGetSymbolAddress((void**)&attn_ptr, g_attn);

    cudaFuncSetAttribute(flash_tc_kernel,
                         cudaFuncAttributeMaxDynamicSharedMemorySize,
                         FLASH_SMEM_BYTES);

    gemm_tf32_nt<<<dim3(QKV_N / BN, S_LEN / BM), 256>>>(
        S_LEN, QKV_N, H_DIM, hidden, w_qkv, qkv_ptr);

    rope_kernel<<<dim3(S_LEN, NH + NKV), 64>>>(positions);

    flash_tc_kernel<<<dim3(S_LEN / 128, NH), 256, FLASH_SMEM_BYTES>>>();

    gemm_tf32_nt<<<dim3(H_DIM / BN, S_LEN / BM), 256>>>(
        S_LEN, H_DIM, H_DIM, attn_ptr, w_o, out);
}

// round 6
// speedup vs baseline: 3.4790x; 1.2328x over previous
#include <cuda_runtime.h>
#include <math.h>
#include <stdint.h>

#define S_LEN 2048
#define H_DIM 4096
#define NH 32
#define NKV 8
#define HD 128
#define QKV_N 6144
#define ATT_SCALE 0.08838834764831843f

__device__ float g_qkv[S_LEN * QKV_N];
__device__ float g_attn[S_LEN * H_DIM];
// tf32 pre-converted inputs
__device__ uint32_t g_hid_tf[S_LEN * H_DIM];
__device__ uint32_t g_wqkv_tf[QKV_N * H_DIM];
__device__ uint32_t g_wo_tf[H_DIM * H_DIM];

__device__ __forceinline__ uint32_t f2tf(float x) {
    uint32_t r;
    asm("cvt.rna.tf32.f32 %0, %1;" : "=r"(r) : "f"(x));
    return r;
}

__device__ __forceinline__ uint32_t smem_u32(const void* p) {
    uint32_t a;
    asm("{ .reg .u64 t; cvta.to.shared.u64 t, %1; cvt.u32.u64 %0, t; }"
        : "=r"(a) : "l"(p));
    return a;
}

#define MMA_TF32(ACC, A0, A1, A2, A3, B0, B1)                                  \
    asm volatile(                                                              \
        "mma.sync.aligned.m16n8k8.row.col.f32.tf32.tf32.f32 "                  \
        "{%0,%1,%2,%3}, {%4,%5,%6,%7}, {%8,%9}, {%0,%1,%2,%3};\n"              \
        : "+f"(ACC[0]), "+f"(ACC[1]), "+f"(ACC[2]), "+f"(ACC[3])               \
        : "r"(A0), "r"(A1), "r"(A2), "r"(A3), "r"(B0), "r"(B1))

#define CP_ASYNC16(dst, src)                                                   \
    asm volatile("cp.async.cg.shared.global [%0], [%1], 16;"                   \
                 :: "r"(dst), "l"(src) : "memory")
#define CP_COMMIT()  asm volatile("cp.async.commit_group;" ::: "memory")
#define CP_WAIT1()   asm volatile("cp.async.wait_group 1;" ::: "memory")
#define CP_WAIT0()   asm volatile("cp.async.wait_group 0;" ::: "memory")

// ---------------------------------------------------------------------------
// Input -> tf32 conversion (grid-stride, float4)
// ---------------------------------------------------------------------------
__global__ void cvt_tf32_kernel(const float4* __restrict__ in,
                                uint4* __restrict__ out, int n4)
{
    for (int i = blockIdx.x * blockDim.x + threadIdx.x; i < n4;
         i += gridDim.x * blockDim.x) {
        float4 v = in[i];
        out[i] = make_uint4(f2tf(v.x), f2tf(v.y), f2tf(v.z), f2tf(v.w));
    }
}

// ---------------------------------------------------------------------------
// TF32 GEMM (NT), cp.async 3-stage pipeline: C = A[M,K] * B[N,K]^T
// Inputs already tf32-rounded (raw bits). 128x128 tile, BK=16, 256 thr.
// ---------------------------------------------------------------------------
#define BK 16
#define TSTR 20
#define GTILE_WORDS (128 * TSTR)       // one 128-row tile, padded
#define G_SMEM_BYTES (6 * GTILE_WORDS * 4)   // A[3] + B[3] = 61440

__global__ __launch_bounds__(256)
void gemm_tf32_nt(int K, int Nfull,
                  const uint32_t* __restrict__ A,
                  const uint32_t* __restrict__ B,
                  float* __restrict__ C)
{
    extern __shared__ uint32_t gdyn[];
    uint32_t* As = gdyn;                    // [3][GTILE_WORDS]
    uint32_t* Bs = gdyn + 3 * GTILE_WORDS;
    const uint32_t as_base = smem_u32(As);
    const uint32_t bs_base = smem_u32(Bs);

    const int tid  = threadIdx.x;
    const int warp = tid >> 5;
    const int lane = tid & 31;
    const int g    = lane >> 2;
    const int t    = lane & 3;

    const int bm = blockIdx.y * 128;
    const int bn = blockIdx.x * 128;
    const int wm = (warp & 1) * 64;
    const int wn = (warp >> 1) * 32;

    // cp.async mapping: 512 16B-chunks per tile; 2 per thread (A and B each)
    const int r0 = (tid + 0)   >> 2;    // rows 0..63
    const int c0 = (tid + 0)   &  3;
    const int r1 = (tid + 256) >> 2;    // rows 64..127
    const int c1 = (tid + 256) &  3;

    const uint32_t* A0 = A + (size_t)(bm + r0) * K + c0 * 4;
    const uint32_t* A1 = A + (size_t)(bm + r1) * K + c1 * 4;
    const uint32_t* B0 = B + (size_t)(bn + r0) * K + c0 * 4;
    const uint32_t* B1 = B + (size_t)(bn + r1) * K + c1 * 4;
    const uint32_t dA0 = (uint32_t)(r0 * TSTR + c0 * 4) * 4;
    const uint32_t dA1 = (uint32_t)(r1 * TSTR + c1 * 4) * 4;
    const uint32_t dB0 = (uint32_t)(r0 * TSTR + c0 * 4) * 4;
    const uint32_t dB1 = (uint32_t)(r1 * TSTR + c1 * 4) * 4;

    float acc[4][4][4];
#pragma unroll
    for (int i = 0; i < 4; i++)
#pragma unroll
        for (int j = 0; j < 4; j++)
#pragma unroll
            for (int r = 0; r < 4; r++) acc[i][j][r] = 0.0f;

    const int n_kt = K / BK;

    // prologue: stages 0,1
#pragma unroll
    for (int s = 0; s < 2; s++) {
        const uint32_t ab = as_base + s * GTILE_WORDS * 4;
        const uint32_t bb = bs_base + s * GTILE_WORDS * 4;
        const int koff = s * BK;
        CP_ASYNC16(ab + dA0, A0 + koff);
        CP_ASYNC16(ab + dA1, A1 + koff);
        CP_ASYNC16(bb + dB0, B0 + koff);
        CP_ASYNC16(bb + dB1, B1 + koff);
        CP_COMMIT();
    }

    int stg = 0;
    for (int kt = 0; kt < n_kt; kt++) {
        CP_WAIT1();
        __syncthreads();

        // issue stage kt+2 (overwrites buffer consumed in iter kt-1)
        if (kt + 2 < n_kt) {
            const int s2 = (kt + 2) % 3;
            const uint32_t ab = as_base + s2 * GTILE_WORDS * 4;
            const uint32_t bb = bs_base + s2 * GTILE_WORDS * 4;
            const int koff = (kt + 2) * BK;
            CP_ASYNC16(ab + dA0, A0 + koff);
            CP_ASYNC16(ab + dA1, A1 + koff);
            CP_ASYNC16(bb + dB0, B0 + koff);
            CP_ASYNC16(bb + dB1, B1 + koff);
        }
        CP_COMMIT();

        const uint32_t* as = As + stg * GTILE_WORDS;
        const uint32_t* bs = Bs + stg * GTILE_WORDS;
#pragma unroll
        for (int ks = 0; ks < 2; ks++) {
            const int kb = ks * 8;
            uint32_t a[4][4], b[4][2];
#pragma unroll
            for (int am = 0; am < 4; am++) {
                const int r = wm + am * 16;
                a[am][0] = as[(r +     g) * TSTR + kb +     t];
                a[am][1] = as[(r + 8 + g) * TSTR + kb +     t];
                a[am][2] = as[(r +     g) * TSTR + kb + 4 + t];
                a[am][3] = as[(r + 8 + g) * TSTR + kb + 4 + t];
            }
#pragma unroll
            for (int an = 0; an < 4; an++) {
                const int c = wn + an * 8;
                b[an][0] = bs[(c + g) * TSTR + kb +     t];
                b[an][1] = bs[(c + g) * TSTR + kb + 4 + t];
            }
#pragma unroll
            for (int am = 0; am < 4; am++)
#pragma unroll
                for (int an = 0; an < 4; an++)
                    MMA_TF32(acc[am][an], a[am][0], a[am][1], a[am][2], a[am][3],
                             b[an][0], b[an][1]);
        }
        stg = (stg + 1) % 3;
    }
    CP_WAIT0();

#pragma unroll
    for (int am = 0; am < 4; am++) {
        const int row0 = bm + wm + am * 16 + g;
#pragma unroll
        for (int an = 0; an < 4; an++) {
            const int col = bn + wn + an * 8 + t * 2;
            float* c0p = C + (size_t)row0 * Nfull + col;
            c0p[0] = acc[am][an][0];
            c0p[1] = acc[am][an][1];
            float* c2p = c0p + (size_t)8 * Nfull;
            c2p[0] = acc[am][an][2];
            c2p[1] = acc[am][an][3];
        }
    }
}

// ---------------------------------------------------------------------------
// RoPE (in-place on g_qkv)
// ---------------------------------------------------------------------------
__global__ void rope_kernel(const int* __restrict__ positions)
{
    const int s = blockIdx.x;
    const int h = blockIdx.y;
    const int d = threadIdx.x;

    const float pos = (float)positions[s];
    const float inv_freq = powf(1000000.0f, -(float)d * (1.0f / 64.0f));
    const float ang = pos * inv_freq;
    float sn, cs;
    sincosf(ang, &sn, &cs);

    float* base = g_qkv + (size_t)s * QKV_N + h * HD;
    const float x1 = base[d];
    const float x2 = base[d + 64];
    base[d]      = x1 * cs - x2 * sn;
    base[d + 64] = x2 * cs + x1 * sn;
}

// ---------------------------------------------------------------------------
// Tensor-core causal GQA flash attention (round-4 layout; epilogue now
// rounds g_attn to tf32 so the O-proj GEMM consumes it directly)
// ---------------------------------------------------------------------------
#define FKSTR 132
#define FVSTR 128
#define FPSTR 68
#define FLASH_SMEM_WORDS (128*FKSTR + 64*FKSTR + 64*FVSTR + 128*FPSTR)
#define FLASH_SMEM_BYTES (FLASH_SMEM_WORDS * 4)

__global__ __launch_bounds__(256)
void flash_tc_kernel()
{
    extern __shared__ uint32_t fsm[];
    uint32_t* Qs = fsm;
    uint32_t* Ks = Qs + 128 * FKSTR;
    uint32_t* Vs = Ks + 64 * FKSTR;
    uint32_t* Ps = Vs + 64 * FVSTR;

    const int tid  = threadIdx.x;
    const int warp = tid >> 5;
    const int lane = tid & 31;
    const int g    = lane >> 2;
    const int t    = lane & 3;
    const int qt   = gridDim.x - 1 - blockIdx.x;
    const int h    = blockIdx.y;
    const int kh   = h >> 2;
    const int wr   = warp * 16;

    const float* Qg = g_qkv + (size_t)(qt * 128) * QKV_N + h * HD;
    const float* Kg = g_qkv + NH * HD + kh * HD;
    const float* Vg = g_qkv + (NH + NKV) * HD + kh * HD;

    for (int i = tid; i < 128 * 32; i += 256) {
        const int r  = i >> 5;
        const int d4 = (i & 31) * 4;
        float4 v = *(const float4*)(Qg + (size_t)r * QKV_N + d4);
        *(uint4*)&Qs[r * FKSTR + d4] =
            make_uint4(f2tf(v.x), f2tf(v.y), f2tf(v.z), f2tf(v.w));
    }

    float m0 = -INFINITY, m1 = -INFINITY, l0 = 0.0f, l1 = 0.0f;
    float o[16][4];
#pragma unroll
    for (int nf = 0; nf < 16; nf++)
#pragma unroll
        for (int r = 0; r < 4; r++) o[nf][r] = 0.0f;

    const int row0 = qt * 128 + wr + g;
    const int n_ktiles = 2 * qt + 2;

    for (int jt = 0; jt < n_ktiles; jt++) {
        __syncthreads();

        const float* Kt = Kg + (size_t)(jt * 64) * QKV_N;
        const float* Vt = Vg + (size_t)(jt * 64) * QKV_N;
        for (int i = tid; i < 64 * 32; i += 256) {
            const int r  = i >> 5;
            const int d4 = (i & 31) * 4;
            float4 kv = *(const float4*)(Kt + (size_t)r * QKV_N + d4);
            *(uint4*)&Ks[r * FKSTR + d4] =
                make_uint4(f2tf(kv.x), f2tf(kv.y), f2tf(kv.z), f2tf(kv.w));
            float4 vv = *(const float4*)(Vt + (size_t)r * QKV_N + d4);
            const int dsw = d4 ^ ((r & 3) << 3);
            *(uint4*)&Vs[r * FVSTR + dsw] =
                make_uint4(f2tf(vv.x), f2tf(vv.y), f2tf(vv.z), f2tf(vv.w));
        }
        __syncthreads();

        float s[8][4];
#pragma unroll
        for (int nf = 0; nf < 8; nf++)
#pragma unroll
            for (int r = 0; r < 4; r++) s[nf][r] = 0.0f;

#pragma unroll
        for (int kc = 0; kc < 16; kc++) {
            const int kb = kc * 8;
            uint32_t a0 = Qs[(wr +     g) * FKSTR + kb +     t];
            uint32_t a1 = Qs[(wr + 8 + g) * FKSTR + kb +     t];
            uint32_t a2 = Qs[(wr +     g) * FKSTR + kb + 4 + t];
            uint32_t a3 = Qs[(wr + 8 + g) * FKSTR + kb + 4 + t];
#pragma unroll
            for (int nf = 0; nf < 8; nf++) {
                uint32_t b0 = Ks[(nf * 8 + g) * FKSTR + kb +     t];
                uint32_t b1 = Ks[(nf * 8 + g) * FKSTR + kb + 4 + t];
                MMA_TF32(s[nf], a0, a1, a2, a3, b0, b1);
            }
        }

        const int colbase = jt * 64 + 2 * t;
#pragma unroll
        for (int nf = 0; nf < 8; nf++) {
            const int col = colbase + nf * 8;
            float v0 = s[nf][0] * ATT_SCALE;
            float v1 = s[nf][1] * ATT_SCALE;
            float v2 = s[nf][2] * ATT_SCALE;
            float v3 = s[nf][3] * ATT_SCALE;
            if (col     > row0)     v0 = -1e30f;
            if (col + 1 > row0)     v1 = -1e30f;
            if (col     > row0 + 8) v2 = -1e30f;
            if (col + 1 > row0 + 8) v3 = -1e30f;
            s[nf][0] = v0; s[nf][1] = v1; s[nf][2] = v2; s[nf][3] = v3;
        }

        float rm0 = -INFINITY, rm1 = -INFINITY;
#pragma unroll
        for (int nf = 0; nf < 8; nf++) {
            rm0 = fmaxf(rm0, fmaxf(s[nf][0], s[nf][1]));
            rm1 = fmaxf(rm1, fmaxf(s[nf][2], s[nf][3]));
        }
        rm0 = fmaxf(rm0, __shfl_xor_sync(0xffffffffu, rm0, 1));
        rm0 = fmaxf(rm0, __shfl_xor_sync(0xffffffffu, rm0, 2));
        rm1 = fmaxf(rm1, __shfl_xor_sync(0xffffffffu, rm1, 1));
        rm1 = fmaxf(rm1, __shfl_xor_sync(0xffffffffu, rm1, 2));

        const float mn0 = fmaxf(m0, rm0);
        const float mn1 = fmaxf(m1, rm1);
        const float cr0 = __expf(m0 - mn0);
        const float cr1 = __expf(m1 - mn1);

        float rs0 = 0.0f, rs1 = 0.0f;
#pragma unroll
        for (int nf = 0; nf < 8; nf++) {
            s[nf][0] = __expf(s[nf][0] - mn0);
            s[nf][1] = __expf(s[nf][1] - mn0);
            s[nf][2] = __expf(s[nf][2] - mn1);
            s[nf][3] = __expf(s[nf][3] - mn1);
            rs0 += s[nf][0] + s[nf][1];
            rs1 += s[nf][2] + s[nf][3];
        }
        rs0 += __shfl_xor_sync(0xffffffffu, rs0, 1);
        rs0 += __shfl_xor_sync(0xffffffffu, rs0, 2);
        rs1 += __shfl_xor_sync(0xffffffffu, rs1, 1);
        rs1 += __shfl_xor_sync(0xffffffffu, rs1, 2);

        l0 = l0 * cr0 + rs0;  m0 = mn0;
        l1 = l1 * cr1 + rs1;  m1 = mn1;

#pragma unroll
        for (int nf = 0; nf < 16; nf++) {
            o[nf][0] *= cr0;  o[nf][1] *= cr0;
            o[nf][2] *= cr1;  o[nf][3] *= cr1;
        }

#pragma unroll
        for (int nf = 0; nf < 8; nf++) {
            const int c = nf * 8 + 2 * t;
            *(uint2*)&Ps[(wr +     g) * FPSTR + c] =
                make_uint2(f2tf(s[nf][0]), f2tf(s[nf][1]));
            *(uint2*)&Ps[(wr + 8 + g) * FPSTR + c] =
                make_uint2(f2tf(s[nf][2]), f2tf(s[nf][3]));
        }
        __syncwarp();

#pragma unroll
        for (int kc = 0; kc < 8; kc++) {
            const int kb = kc * 8;
            uint32_t a0 = Ps[(wr +     g) * FPSTR + kb +     t];
            uint32_t a1 = Ps[(wr + 8 + g) * FPSTR + kb +     t];
            uint32_t a2 = Ps[(wr +     g) * FPSTR + kb + 4 + t];
            uint32_t a3 = Ps[(wr + 8 + g) * FPSTR + kb + 4 + t];
            const int sw = t << 3;
#pragma unroll
            for (int nf = 0; nf < 16; nf++) {
                uint32_t b0 = Vs[(kb +     t) * FVSTR + ((nf * 8 + g) ^ sw)];
                uint32_t b1 = Vs[(kb + 4 + t) * FVSTR + ((nf * 8 + g) ^ sw)];
                MMA_TF32(o[nf], a0, a1, a2, a3, b0, b1);
            }
        }
        __syncwarp();
    }

    // epilogue: normalize, round to tf32 (O-proj GEMM consumes raw bits)
    const float il0 = 1.0f / l0;
    const float il1 = 1.0f / l1;
#pragma unroll
    for (int nf = 0; nf < 16; nf++) {
        const int col = h * HD + nf * 8 + 2 * t;
        float* p0 = g_attn + (size_t)row0 * H_DIM + col;
        p0[0] = __uint_as_float(f2tf(o[nf][0] * il0));
        p0[1] = __uint_as_float(f2tf(o[nf][1] * il0));
        float* p1 = g_attn + (size_t)(row0 + 8) * H_DIM + col;
        p1[0] = __uint_as_float(f2tf(o[nf][2] * il1));
        p1[1] = __uint_as_float(f2tf(o[nf][3] * il1));
    }
}

// ---------------------------------------------------------------------------
// Launch
// ---------------------------------------------------------------------------
extern "C" void kernel_launch(void* const* d_in, const int* in_sizes, int n_in,
                              void* d_out, int out_size)
{
    (void)in_sizes; (void)n_in; (void)out_size;
    const int*   positions = (const int*)d_in[0];
    const float* hidden    = (const float*)d_in[1];
    const float* w_qkv     = (const float*)d_in[2];
    const float* w_o       = (const float*)d_in[3];
    float*       out       = (float*)d_out;

    float *qkv_ptr = nullptr, *attn_ptr = nullptr;
    uint32_t *hid_tf = nullptr, *wqkv_tf = nullptr, *wo_tf = nullptr;
    cudaGetSymbolAddress((void**)&qkv_ptr, g_qkv);
    cudaGetSymbolAddress((void**)&attn_ptr, g_attn);
    cudaGetSymbolAddress((void**)&hid_tf, g_hid_tf);
    cudaGetSymbolAddress((void**)&wqkv_tf, g_wqkv_tf);
    cudaGetSymbolAddress((void**)&wo_tf, g_wo_tf);

    cudaFuncSetAttribute(gemm_tf32_nt,
                         cudaFuncAttributeMaxDynamicSharedMemorySize,
                         G_SMEM_BYTES);
    cudaFuncSetAttribute(flash_tc_kernel,
                         cudaFuncAttributeMaxDynamicSharedMemorySize,
                         FLASH_SMEM_BYTES);

    // 0) one-time-per-call input conversions (fp32 -> tf32 bits)
    cvt_tf32_kernel<<<592, 256>>>((const float4*)hidden, (uint4*)hid_tf,
                                  S_LEN * H_DIM / 4);
    cvt_tf32_kernel<<<592, 256>>>((const float4*)w_qkv, (uint4*)wqkv_tf,
                                  QKV_N * H_DIM / 4);
    cvt_tf32_kernel<<<592, 256>>>((const float4*)w_o, (uint4*)wo_tf,
                                  H_DIM * H_DIM / 4);

    // 1) QKV projection
    gemm_tf32_nt<<<dim3(QKV_N / 128, S_LEN / 128), 256, G_SMEM_BYTES>>>(
        H_DIM, QKV_N, hid_tf, wqkv_tf, qkv_ptr);

    // 2) RoPE
    rope_kernel<<<dim3(S_LEN, NH + NKV), 64>>>(positions);

    // 3) Flash attention
    flash_tc_kernel<<<dim3(S_LEN / 128, NH), 256, FLASH_SMEM_BYTES>>>();

    // 4) Output projection
    gemm_tf32_nt<<<dim3(H_DIM / 128, S_LEN / 128), 256, G_SMEM_BYTES>>>(
        H_DIM, H_DIM, (const uint32_t*)attn_ptr, wo_tf, out);
}

// round 7
// speedup vs baseline: 4.0142x; 1.1538x over previous
#include <cuda_runtime.h>
#include <math.h>
#include <stdint.h>

#define S_LEN 2048
#define H_DIM 4096
#define NH 32
#define NKV 8
#define HD 128
#define QKV_N 6144
#define ATT_SCALE 0.08838834764831843f

__device__ float g_qkv[S_LEN * QKV_N];
__device__ float g_attn[S_LEN * H_DIM];
// fragment-packed tf32 operands
__device__ uint32_t g_hidA [S_LEN * H_DIM];    // A-packed hidden
__device__ uint32_t g_wqkvB[QKV_N * H_DIM];    // B-packed w_qkv
__device__ uint32_t g_woB  [H_DIM * H_DIM];    // B-packed w_o
__device__ uint32_t g_attnA[S_LEN * H_DIM];    // A-packed attention output

__device__ __forceinline__ uint32_t f2tf(float x) {
    uint32_t r;
    asm("cvt.rna.tf32.f32 %0, %1;" : "=r"(r) : "f"(x));
    return r;
}

__device__ __forceinline__ uint32_t smem_u32(const void* p) {
    uint32_t a;
    asm("{ .reg .u64 t; cvta.to.shared.u64 t, %1; cvt.u32.u64 %0, t; }"
        : "=r"(a) : "l"(p));
    return a;
}

#define MMA_TF32(ACC, A0, A1, A2, A3, B0, B1)                                  \
    asm volatile(                                                              \
        "mma.sync.aligned.m16n8k8.row.col.f32.tf32.tf32.f32 "                  \
        "{%0,%1,%2,%3}, {%4,%5,%6,%7}, {%8,%9}, {%0,%1,%2,%3};\n"              \
        : "+f"(ACC[0]), "+f"(ACC[1]), "+f"(ACC[2]), "+f"(ACC[3])               \
        : "r"(A0), "r"(A1), "r"(A2), "r"(A3), "r"(B0), "r"(B1))

#define CP_ASYNC16(dst, src)                                                   \
    asm volatile("cp.async.cg.shared.global [%0], [%1], 16;"                   \
                 :: "r"(dst), "l"(src) : "memory")
#define CP_COMMIT()  asm volatile("cp.async.commit_group;" ::: "memory")
#define CP_WAIT1()   asm volatile("cp.async.wait_group 1;" ::: "memory")
#define CP_WAIT0()   asm volatile("cp.async.wait_group 0;" ::: "memory")

// ---------------------------------------------------------------------------
// A-pack: float [M,K] row-major -> fragment-packed tf32.
// Slab (mblk128, k16) = 2048 words contiguous; sub = m16loc*2 + k8loc (128 w);
// lane word quad = A[row][k], A[row+8][k], A[row][k+4], A[row+8][k+4].
// ---------------------------------------------------------------------------
__global__ void pack_a_kernel(const float* __restrict__ in,
                              uint4* __restrict__ out, int K, int n4)
{
    const int k16n = K / 16;
    for (int idx = blockIdx.x * blockDim.x + threadIdx.x; idx < n4;
         idx += gridDim.x * blockDim.x) {
        const int slab = idx >> 9;          // 512 uint4 per slab
        const int rem  = idx & 511;
        const int sub  = rem >> 5;          // 0..15
        const int lane = rem & 31;
        const int mblk = slab / k16n;
        const int k16  = slab - mblk * k16n;
        const int row  = mblk * 128 + (sub >> 1) * 16 + (lane >> 2);
        const int k    = k16 * 16 + (sub & 1) * 8 + (lane & 3);
        const float* p = in + (size_t)row * K + k;
        out[idx] = make_uint4(f2tf(p[0]),
                              f2tf(p[(size_t)8 * K]),
                              f2tf(p[4]),
                              f2tf(p[(size_t)8 * K + 4]));
    }
}

// ---------------------------------------------------------------------------
// B-pack: float [N,K] row-major -> fragment-packed tf32.
// Slab (nblk128, k16) = 2048 words; sub = n8loc*2 + k8loc (64 w);
// lane word pair = B[n][k], B[n][k+4].
// ---------------------------------------------------------------------------
__global__ void pack_b_kernel(const float* __restrict__ in,
                              uint2* __restrict__ out, int K, int n2)
{
    const int k16n = K / 16;
    for (int idx = blockIdx.x * blockDim.x + threadIdx.x; idx < n2;
         idx += gridDim.x * blockDim.x) {
        const int slab = idx >> 10;         // 1024 uint2 per slab
        const int rem  = idx & 1023;
        const int sub  = rem >> 5;          // 0..31
        const int lane = rem & 31;
        const int nblk = slab / k16n;
        const int k16  = slab - nblk * k16n;
        const int row  = nblk * 128 + (sub >> 1) * 8 + (lane >> 2);
        const int k    = k16 * 16 + (sub & 1) * 8 + (lane & 3);
        const float* p = in + (size_t)row * K + k;
        out[idx] = make_uint2(f2tf(p[0]), f2tf(p[4]));
    }
}

// ---------------------------------------------------------------------------
// TF32 GEMM on fragment-packed operands, cp.async 3-stage pipeline.
// 128x128 tile, BK=16. Slabs are contiguous 8KB; frag loads are LDS.128/64.
// ---------------------------------------------------------------------------
#define SLAB_W 2048                       // words per (A or B) k16-slab
#define G_SMEM_BYTES (6 * SLAB_W * 4)     // 3 stages x (A+B) = 49152

__global__ __launch_bounds__(256)
void gemm_tf32_nt(int K, int Nfull,
                  const uint32_t* __restrict__ A,   // packed
                  const uint32_t* __restrict__ B,   // packed
                  float* __restrict__ C)
{
    extern __shared__ uint32_t gdyn[];
    uint32_t* As = gdyn;                  // [3][SLAB_W]
    uint32_t* Bs = gdyn + 3 * SLAB_W;
    const uint32_t as_base = smem_u32(As);
    const uint32_t bs_base = smem_u32(Bs);

    const int tid  = threadIdx.x;
    const int warp = tid >> 5;
    const int lane = tid & 31;
    const int g    = lane >> 2;
    const int t    = lane & 3;

    const int k16n = K / 16;
    const uint32_t* Aslab = A + (size_t)blockIdx.y * k16n * SLAB_W;
    const uint32_t* Bslab = B + (size_t)blockIdx.x * k16n * SLAB_W;

    const int m16b = (warp & 1) * 4;      // m16loc base
    const int n8b  = (warp >> 1) * 4;     // n8loc base

    float acc[4][4][4];
#pragma unroll
    for (int i = 0; i < 4; i++)
#pragma unroll
        for (int j = 0; j < 4; j++)
#pragma unroll
            for (int r = 0; r < 4; r++) acc[i][j][r] = 0.0f;

    // prologue: stages 0,1
#pragma unroll
    for (int s = 0; s < 2; s++) {
        const uint32_t ab = as_base + s * SLAB_W * 4;
        const uint32_t bb = bs_base + s * SLAB_W * 4;
        const uint32_t* Ap = Aslab + (size_t)s * SLAB_W;
        const uint32_t* Bp = Bslab + (size_t)s * SLAB_W;
#pragma unroll
        for (int i = 0; i < 2; i++) {
            CP_ASYNC16(ab + (tid + i * 256) * 16, Ap + (tid + i * 256) * 4);
            CP_ASYNC16(bb + (tid + i * 256) * 16, Bp + (tid + i * 256) * 4);
        }
        CP_COMMIT();
    }

    int stg = 0;
    for (int kt = 0; kt < k16n; kt++) {
        CP_WAIT1();
        __syncthreads();

        if (kt + 2 < k16n) {
            const int s2 = (kt + 2) % 3;
            const uint32_t ab = as_base + s2 * SLAB_W * 4;
            const uint32_t bb = bs_base + s2 * SLAB_W * 4;
            const uint32_t* Ap = Aslab + (size_t)(kt + 2) * SLAB_W;
            const uint32_t* Bp = Bslab + (size_t)(kt + 2) * SLAB_W;
#pragma unroll
            for (int i = 0; i < 2; i++) {
                CP_ASYNC16(ab + (tid + i * 256) * 16, Ap + (tid + i * 256) * 4);
                CP_ASYNC16(bb + (tid + i * 256) * 16, Bp + (tid + i * 256) * 4);
            }
        }
        CP_COMMIT();

        const uint32_t* as = As + stg * SLAB_W;
        const uint32_t* bs = Bs + stg * SLAB_W;
#pragma unroll
        for (int ks = 0; ks < 2; ks++) {
            uint4 aw[4];
            uint2 bw[4];
#pragma unroll
            for (int am = 0; am < 4; am++)
                aw[am] = *(const uint4*)&as[((m16b + am) * 2 + ks) * 128 + lane * 4];
#pragma unroll
            for (int an = 0; an < 4; an++)
                bw[an] = *(const uint2*)&bs[((n8b + an) * 2 + ks) * 64 + lane * 2];
#pragma unroll
            for (int am = 0; am < 4; am++)
#pragma unroll
                for (int an = 0; an < 4; an++)
                    MMA_TF32(acc[am][an], aw[am].x, aw[am].y, aw[am].z, aw[am].w,
                             bw[an].x, bw[an].y);
        }
        stg = (stg + 1) % 3;
    }
    CP_WAIT0();

    const int bm = blockIdx.y * 128;
    const int bn = blockIdx.x * 128;
#pragma unroll
    for (int am = 0; am < 4; am++) {
        const int row0 = bm + m16b * 16 + am * 16 + g;
#pragma unroll
        for (int an = 0; an < 4; an++) {
            const int col = bn + n8b * 8 + an * 8 + t * 2;
            float* c0p = C + (size_t)row0 * Nfull + col;
            c0p[0] = acc[am][an][0];
            c0p[1] = acc[am][an][1];
            float* c2p = c0p + (size_t)8 * Nfull;
            c2p[0] = acc[am][an][2];
            c2p[1] = acc[am][an][3];
        }
    }
}

// ---------------------------------------------------------------------------
// RoPE (in-place on g_qkv)
// ---------------------------------------------------------------------------
__global__ void rope_kernel(const int* __restrict__ positions)
{
    const int s = blockIdx.x;
    const int h = blockIdx.y;
    const int d = threadIdx.x;

    const float pos = (float)positions[s];
    const float inv_freq = powf(1000000.0f, -(float)d * (1.0f / 64.0f));
    const float ang = pos * inv_freq;
    float sn, cs;
    sincosf(ang, &sn, &cs);

    float* base = g_qkv + (size_t)s * QKV_N + h * HD;
    const float x1 = base[d];
    const float x2 = base[d + 64];
    base[d]      = x1 * cs - x2 * sn;
    base[d + 64] = x2 * cs + x1 * sn;
}

// ---------------------------------------------------------------------------
// Tensor-core causal GQA flash attention (unchanged from round 6)
// ---------------------------------------------------------------------------
#define FKSTR 132
#define FVSTR 128
#define FPSTR 68
#define FLASH_SMEM_WORDS (128*FKSTR + 64*FKSTR + 64*FVSTR + 128*FPSTR)
#define FLASH_SMEM_BYTES (FLASH_SMEM_WORDS * 4)

__global__ __launch_bounds__(256)
void flash_tc_kernel()
{
    extern __shared__ uint32_t fsm[];
    uint32_t* Qs = fsm;
    uint32_t* Ks = Qs + 128 * FKSTR;
    uint32_t* Vs = Ks + 64 * FKSTR;
    uint32_t* Ps = Vs + 64 * FVSTR;

    const int tid  = threadIdx.x;
    const int warp = tid >> 5;
    const int lane = tid & 31;
    const int g    = lane >> 2;
    const int t    = lane & 3;
    const int qt   = gridDim.x - 1 - blockIdx.x;
    const int h    = blockIdx.y;
    const int kh   = h >> 2;
    const int wr   = warp * 16;

    const float* Qg = g_qkv + (size_t)(qt * 128) * QKV_N + h * HD;
    const float* Kg = g_qkv + NH * HD + kh * HD;
    const float* Vg = g_qkv + (NH + NKV) * HD + kh * HD;

    for (int i = tid; i < 128 * 32; i += 256) {
        const int r  = i >> 5;
        const int d4 = (i & 31) * 4;
        float4 v = *(const float4*)(Qg + (size_t)r * QKV_N + d4);
        *(uint4*)&Qs[r * FKSTR + d4] =
            make_uint4(f2tf(v.x), f2tf(v.y), f2tf(v.z), f2tf(v.w));
    }

    float m0 = -INFINITY, m1 = -INFINITY, l0 = 0.0f, l1 = 0.0f;
    float o[16][4];
#pragma unroll
    for (int nf = 0; nf < 16; nf++)
#pragma unroll
        for (int r = 0; r < 4; r++) o[nf][r] = 0.0f;

    const int row0 = qt * 128 + wr + g;
    const int n_ktiles = 2 * qt + 2;

    for (int jt = 0; jt < n_ktiles; jt++) {
        __syncthreads();

        const float* Kt = Kg + (size_t)(jt * 64) * QKV_N;
        const float* Vt = Vg + (size_t)(jt * 64) * QKV_N;
        for (int i = tid; i < 64 * 32; i += 256) {
            const int r  = i >> 5;
            const int d4 = (i & 31) * 4;
            float4 kv = *(const float4*)(Kt + (size_t)r * QKV_N + d4);
            *(uint4*)&Ks[r * FKSTR + d4] =
                make_uint4(f2tf(kv.x), f2tf(kv.y), f2tf(kv.z), f2tf(kv.w));
            float4 vv = *(const float4*)(Vt + (size_t)r * QKV_N + d4);
            const int dsw = d4 ^ ((r & 3) << 3);
            *(uint4*)&Vs[r * FVSTR + dsw] =
                make_uint4(f2tf(vv.x), f2tf(vv.y), f2tf(vv.z), f2tf(vv.w));
        }
        __syncthreads();

        float s[8][4];
#pragma unroll
        for (int nf = 0; nf < 8; nf++)
#pragma unroll
            for (int r = 0; r < 4; r++) s[nf][r] = 0.0f;

#pragma unroll
        for (int kc = 0; kc < 16; kc++) {
            const int kb = kc * 8;
            uint32_t a0 = Qs[(wr +     g) * FKSTR + kb +     t];
            uint32_t a1 = Qs[(wr + 8 + g) * FKSTR + kb +     t];
            uint32_t a2 = Qs[(wr +     g) * FKSTR + kb + 4 + t];
            uint32_t a3 = Qs[(wr + 8 + g) * FKSTR + kb + 4 + t];
#pragma unroll
            for (int nf = 0; nf < 8; nf++) {
                uint32_t b0 = Ks[(nf * 8 + g) * FKSTR + kb +     t];
                uint32_t b1 = Ks[(nf * 8 + g) * FKSTR + kb + 4 + t];
                MMA_TF32(s[nf], a0, a1, a2, a3, b0, b1);
            }
        }

        const int colbase = jt * 64 + 2 * t;
#pragma unroll
        for (int nf = 0; nf < 8; nf++) {
            const int col = colbase + nf * 8;
            float v0 = s[nf][0] * ATT_SCALE;
            float v1 = s[nf][1] * ATT_SCALE;
            float v2 = s[nf][2] * ATT_SCALE;
            float v3 = s[nf][3] * ATT_SCALE;
            if (col     > row0)     v0 = -1e30f;
            if (col + 1 > row0)     v1 = -1e30f;
            if (col     > row0 + 8) v2 = -1e30f;
            if (col + 1 > row0 + 8) v3 = -1e30f;
            s[nf][0] = v0; s[nf][1] = v1; s[nf][2] = v2; s[nf][3] = v3;
        }

        float rm0 = -INFINITY, rm1 = -INFINITY;
#pragma unroll
        for (int nf = 0; nf < 8; nf++) {
            rm0 = fmaxf(rm0, fmaxf(s[nf][0], s[nf][1]));
            rm1 = fmaxf(rm1, fmaxf(s[nf][2], s[nf][3]));
        }
        rm0 = fmaxf(rm0, __shfl_xor_sync(0xffffffffu, rm0, 1));
        rm0 = fmaxf(rm0, __shfl_xor_sync(0xffffffffu, rm0, 2));
        rm1 = fmaxf(rm1, __shfl_xor_sync(0xffffffffu, rm1, 1));
        rm1 = fmaxf(rm1, __shfl_xor_sync(0xffffffffu, rm1, 2));

        const float mn0 = fmaxf(m0, rm0);
        const float mn1 = fmaxf(m1, rm1);
        const float cr0 = __expf(m0 - mn0);
        const float cr1 = __expf(m1 - mn1);

        float rs0 = 0.0f, rs1 = 0.0f;
#pragma unroll
        for (int nf = 0; nf < 8; nf++) {
            s[nf][0] = __expf(s[nf][0] - mn0);
            s[nf][1] = __expf(s[nf][1] - mn0);
            s[nf][2] = __expf(s[nf][2] - mn1);
            s[nf][3] = __expf(s[nf][3] - mn1);
            rs0 += s[nf][0] + s[nf][1];
            rs1 += s[nf][2] + s[nf][3];
        }
        rs0 += __shfl_xor_sync(0xffffffffu, rs0, 1);
        rs0 += __shfl_xor_sync(0xffffffffu, rs0, 2);
        rs1 += __shfl_xor_sync(0xffffffffu, rs1, 1);
        rs1 += __shfl_xor_sync(0xffffffffu, rs1, 2);

        l0 = l0 * cr0 + rs0;  m0 = mn0;
        l1 = l1 * cr1 + rs1;  m1 = mn1;

#pragma unroll
        for (int nf = 0; nf < 16; nf++) {
            o[nf][0] *= cr0;  o[nf][1] *= cr0;
            o[nf][2] *= cr1;  o[nf][3] *= cr1;
        }

#pragma unroll
        for (int nf = 0; nf < 8; nf++) {
            const int c = nf * 8 + 2 * t;
            *(uint2*)&Ps[(wr +     g) * FPSTR + c] =
                make_uint2(f2tf(s[nf][0]), f2tf(s[nf][1]));
            *(uint2*)&Ps[(wr + 8 + g) * FPSTR + c] =
                make_uint2(f2tf(s[nf][2]), f2tf(s[nf][3]));
        }
        __syncwarp();

#pragma unroll
        for (int kc = 0; kc < 8; kc++) {
            const int kb = kc * 8;
            uint32_t a0 = Ps[(wr +     g) * FPSTR + kb +     t];
            uint32_t a1 = Ps[(wr + 8 + g) * FPSTR + kb +     t];
            uint32_t a2 = Ps[(wr +     g) * FPSTR + kb + 4 + t];
            uint32_t a3 = Ps[(wr + 8 + g) * FPSTR + kb + 4 + t];
            const int sw = t << 3;
#pragma unroll
            for (int nf = 0; nf < 16; nf++) {
                uint32_t b0 = Vs[(kb +     t) * FVSTR + ((nf * 8 + g) ^ sw)];
                uint32_t b1 = Vs[(kb + 4 + t) * FVSTR + ((nf * 8 + g) ^ sw)];
                MMA_TF32(o[nf], a0, a1, a2, a3, b0, b1);
            }
        }
        __syncwarp();
    }

    const float il0 = 1.0f / l0;
    const float il1 = 1.0f / l1;
#pragma unroll
    for (int nf = 0; nf < 16; nf++) {
        const int col = h * HD + nf * 8 + 2 * t;
        float* p0 = g_attn + (size_t)row0 * H_DIM + col;
        p0[0] = __uint_as_float(f2tf(o[nf][0] * il0));
        p0[1] = __uint_as_float(f2tf(o[nf][1] * il0));
        float* p1 = g_attn + (size_t)(row0 + 8) * H_DIM + col;
        p1[0] = __uint_as_float(f2tf(o[nf][2] * il1));
        p1[1] = __uint_as_float(f2tf(o[nf][3] * il1));
    }
}

// ---------------------------------------------------------------------------
// Launch
// ---------------------------------------------------------------------------
extern "C" void kernel_launch(void* const* d_in, const int* in_sizes, int n_in,
                              void* d_out, int out_size)
{
    (void)in_sizes; (void)n_in; (void)out_size;
    const int*   positions = (const int*)d_in[0];
    const float* hidden    = (const float*)d_in[1];
    const float* w_qkv     = (const float*)d_in[2];
    const float* w_o       = (const float*)d_in[3];
    float*       out       = (float*)d_out;

    float *qkv_ptr = nullptr, *attn_ptr = nullptr;
    uint32_t *hidA = nullptr, *wqkvB = nullptr, *woB = nullptr, *attnA = nullptr;
    cudaGetSymbolAddress((void**)&qkv_ptr, g_qkv);
    cudaGetSymbolAddress((void**)&attn_ptr, g_attn);
    cudaGetSymbolAddress((void**)&hidA, g_hidA);
    cudaGetSymbolAddress((void**)&wqkvB, g_wqkvB);
    cudaGetSymbolAddress((void**)&woB, g_woB);
    cudaGetSymbolAddress((void**)&attnA, g_attnA);

    cudaFuncSetAttribute(gemm_tf32_nt,
                         cudaFuncAttributeMaxDynamicSharedMemorySize,
                         G_SMEM_BYTES);
    cudaFuncSetAttribute(flash_tc_kernel,
                         cudaFuncAttributeMaxDynamicSharedMemorySize,
                         FLASH_SMEM_BYTES);

    // 0) convert + pack operands
    pack_a_kernel<<<2048, 256>>>(hidden, (uint4*)hidA, H_DIM,
                                 S_LEN * H_DIM / 4);
    pack_b_kernel<<<2048, 256>>>(w_qkv, (uint2*)wqkvB, H_DIM,
                                 QKV_N * H_DIM / 2);
    pack_b_kernel<<<2048, 256>>>(w_o, (uint2*)woB, H_DIM,
                                 H_DIM * H_DIM / 2);

    // 1) QKV projection
    gemm_tf32_nt<<<dim3(QKV_N / 128, S_LEN / 128), 256, G_SMEM_BYTES>>>(
        H_DIM, QKV_N, hidA, wqkvB, qkv_ptr);

    // 2) RoPE
    rope_kernel<<<dim3(S_LEN, NH + NKV), 64>>>(positions);

    // 3) Flash attention
    flash_tc_kernel<<<dim3(S_LEN / 128, NH), 256, FLASH_SMEM_BYTES>>>();

    // 3b) pack attention output for O-proj (values already tf32-rounded)
    pack_a_kernel<<<2048, 256>>>(attn_ptr, (uint4*)attnA, H_DIM,
                                 S_LEN * H_DIM / 4);

    // 4) Output projection
    gemm_tf32_nt<<<dim3(H_DIM / 128, S_LEN / 128), 256, G_SMEM_BYTES>>>(
        H_DIM, H_DIM, attnA, woB, out);
}

// round 8
// speedup vs baseline: 4.0190x; 1.0012x over previous
#include <cuda_runtime.h>
#include <math.h>
#include <stdint.h>

#define S_LEN 2048
#define H_DIM 4096
#define NH 32
#define NKV 8
#define HD 128
#define QKV_N 6144
#define ATT_SCALE 0.08838834764831843f

__device__ float g_qkv[S_LEN * QKV_N];
__device__ float g_attn[S_LEN * H_DIM];
// fragment-packed tf32 operands
__device__ uint32_t g_hidA [S_LEN * H_DIM];    // A-packed hidden
__device__ uint32_t g_wqkvB[QKV_N * H_DIM];    // B-packed w_qkv
__device__ uint32_t g_woB  [H_DIM * H_DIM];    // B-packed w_o
__device__ uint32_t g_attnA[S_LEN * H_DIM];    // A-packed attention output

__device__ __forceinline__ uint32_t f2tf(float x) {
    uint32_t r;
    asm("cvt.rna.tf32.f32 %0, %1;" : "=r"(r) : "f"(x));
    return r;
}

__device__ __forceinline__ uint32_t smem_u32(const void* p) {
    uint32_t a;
    asm("{ .reg .u64 t; cvta.to.shared.u64 t, %1; cvt.u32.u64 %0, t; }"
        : "=r"(a) : "l"(p));
    return a;
}

#define MMA_TF32(ACC, A0, A1, A2, A3, B0, B1)                                  \
    asm volatile(                                                              \
        "mma.sync.aligned.m16n8k8.row.col.f32.tf32.tf32.f32 "                  \
        "{%0,%1,%2,%3}, {%4,%5,%6,%7}, {%8,%9}, {%0,%1,%2,%3};\n"              \
        : "+f"(ACC[0]), "+f"(ACC[1]), "+f"(ACC[2]), "+f"(ACC[3])               \
        : "r"(A0), "r"(A1), "r"(A2), "r"(A3), "r"(B0), "r"(B1))

#define CP_ASYNC16(dst, src)                                                   \
    asm volatile("cp.async.cg.shared.global [%0], [%1], 16;"                   \
                 :: "r"(dst), "l"(src) : "memory")
#define CP_COMMIT()  asm volatile("cp.async.commit_group;" ::: "memory")
#define CP_WAIT1()   asm volatile("cp.async.wait_group 1;" ::: "memory")
#define CP_WAIT0()   asm volatile("cp.async.wait_group 0;" ::: "memory")

// ---------------------------------------------------------------------------
// A-pack: float [M,K] row-major -> fragment-packed tf32.
// Slab (mblk128, k16) = 2048 words contiguous; sub = m16loc*2 + k8loc (128 w);
// lane word quad = A[row][k], A[row+8][k], A[row][k+4], A[row+8][k+4].
// ---------------------------------------------------------------------------
__global__ void pack_a_kernel(const float* __restrict__ in,
                              uint4* __restrict__ out, int K, int n4)
{
    const int k16n = K / 16;
    for (int idx = blockIdx.x * blockDim.x + threadIdx.x; idx < n4;
         idx += gridDim.x * blockDim.x) {
        const int slab = idx >> 9;          // 512 uint4 per slab
        const int rem  = idx & 511;
        const int sub  = rem >> 5;          // 0..15
        const int lane = rem & 31;
        const int mblk = slab / k16n;
        const int k16  = slab - mblk * k16n;
        const int row  = mblk * 128 + (sub >> 1) * 16 + (lane >> 2);
        const int k    = k16 * 16 + (sub & 1) * 8 + (lane & 3);
        const float* p = in + (size_t)row * K + k;
        out[idx] = make_uint4(f2tf(p[0]),
                              f2tf(p[(size_t)8 * K]),
                              f2tf(p[4]),
                              f2tf(p[(size_t)8 * K + 4]));
    }
}

// ---------------------------------------------------------------------------
// B-pack: float [N,K] row-major -> fragment-packed tf32.
// Slab (nblk128, k16) = 2048 words; sub = n8loc*2 + k8loc (64 w);
// lane word pair = B[n][k], B[n][k+4].
// ---------------------------------------------------------------------------
__global__ void pack_b_kernel(const float* __restrict__ in,
                              uint2* __restrict__ out, int K, int n2)
{
    const int k16n = K / 16;
    for (int idx = blockIdx.x * blockDim.x + threadIdx.x; idx < n2;
         idx += gridDim.x * blockDim.x) {
        const int slab = idx >> 10;         // 1024 uint2 per slab
        const int rem  = idx & 1023;
        const int sub  = rem >> 5;          // 0..31
        const int lane = rem & 31;
        const int nblk = slab / k16n;
        const int k16  = slab - nblk * k16n;
        const int row  = nblk * 128 + (sub >> 1) * 8 + (lane >> 2);
        const int k    = k16 * 16 + (sub & 1) * 8 + (lane & 3);
        const float* p = in + (size_t)row * K + k;
        out[idx] = make_uint2(f2tf(p[0]), f2tf(p[4]));
    }
}

// ---------------------------------------------------------------------------
// TF32 GEMM on fragment-packed operands, cp.async 3-stage pipeline.
// 128x128 tile, BK=16. Slabs are contiguous 8KB; frag loads are LDS.128/64.
// ---------------------------------------------------------------------------
#define SLAB_W 2048                       // words per (A or B) k16-slab
#define G_SMEM_BYTES (6 * SLAB_W * 4)     // 3 stages x (A+B) = 49152

__global__ __launch_bounds__(256)
void gemm_tf32_nt(int K, int Nfull,
                  const uint32_t* __restrict__ A,   // packed
                  const uint32_t* __restrict__ B,   // packed
                  float* __restrict__ C)
{
    extern __shared__ uint32_t gdyn[];
    uint32_t* As = gdyn;                  // [3][SLAB_W]
    uint32_t* Bs = gdyn + 3 * SLAB_W;
    const uint32_t as_base = smem_u32(As);
    const uint32_t bs_base = smem_u32(Bs);

    const int tid  = threadIdx.x;
    const int warp = tid >> 5;
    const int lane = tid & 31;
    const int g    = lane >> 2;
    const int t    = lane & 3;

    const int k16n = K / 16;
    const uint32_t* Aslab = A + (size_t)blockIdx.y * k16n * SLAB_W;
    const uint32_t* Bslab = B + (size_t)blockIdx.x * k16n * SLAB_W;

    const int m16b = (warp & 1) * 4;      // m16loc base
    const int n8b  = (warp >> 1) * 4;     // n8loc base

    float acc[4][4][4];
#pragma unroll
    for (int i = 0; i < 4; i++)
#pragma unroll
        for (int j = 0; j < 4; j++)
#pragma unroll
            for (int r = 0; r < 4; r++) acc[i][j][r] = 0.0f;

    // prologue: stages 0,1
#pragma unroll
    for (int s = 0; s < 2; s++) {
        const uint32_t ab = as_base + s * SLAB_W * 4;
        const uint32_t bb = bs_base + s * SLAB_W * 4;
        const uint32_t* Ap = Aslab + (size_t)s * SLAB_W;
        const uint32_t* Bp = Bslab + (size_t)s * SLAB_W;
#pragma unroll
        for (int i = 0; i < 2; i++) {
            CP_ASYNC16(ab + (tid + i * 256) * 16, Ap + (tid + i * 256) * 4);
            CP_ASYNC16(bb + (tid + i * 256) * 16, Bp + (tid + i * 256) * 4);
        }
        CP_COMMIT();
    }

    int stg = 0;
    for (int kt = 0; kt < k16n; kt++) {
        CP_WAIT1();
        __syncthreads();

        if (kt + 2 < k16n) {
            const int s2 = (kt + 2) % 3;
            const uint32_t ab = as_base + s2 * SLAB_W * 4;
            const uint32_t bb = bs_base + s2 * SLAB_W * 4;
            const uint32_t* Ap = Aslab + (size_t)(kt + 2) * SLAB_W;
            const uint32_t* Bp = Bslab + (size_t)(kt + 2) * SLAB_W;
#pragma unroll
            for (int i = 0; i < 2; i++) {
                CP_ASYNC16(ab + (tid + i * 256) * 16, Ap + (tid + i * 256) * 4);
                CP_ASYNC16(bb + (tid + i * 256) * 16, Bp + (tid + i * 256) * 4);
            }
        }
        CP_COMMIT();

        const uint32_t* as = As + stg * SLAB_W;
        const uint32_t* bs = Bs + stg * SLAB_W;
#pragma unroll
        for (int ks = 0; ks < 2; ks++) {
            uint4 aw[4];
            uint2 bw[4];
#pragma unroll
            for (int am = 0; am < 4; am++)
                aw[am] = *(const uint4*)&as[((m16b + am) * 2 + ks) * 128 + lane * 4];
#pragma unroll
            for (int an = 0; an < 4; an++)
                bw[an] = *(const uint2*)&bs[((n8b + an) * 2 + ks) * 64 + lane * 2];
#pragma unroll
            for (int am = 0; am < 4; am++)
#pragma unroll
                for (int an = 0; an < 4; an++)
                    MMA_TF32(acc[am][an], aw[am].x, aw[am].y, aw[am].z, aw[am].w,
                             bw[an].x, bw[an].y);
        }
        stg = (stg + 1) % 3;
    }
    CP_WAIT0();

    const int bm = blockIdx.y * 128;
    const int bn = blockIdx.x * 128;
#pragma unroll
    for (int am = 0; am < 4; am++) {
        const int row0 = bm + m16b * 16 + am * 16 + g;
#pragma unroll
        for (int an = 0; an < 4; an++) {
            const int col = bn + n8b * 8 + an * 8 + t * 2;
            float* c0p = C + (size_t)row0 * Nfull + col;
            c0p[0] = acc[am][an][0];
            c0p[1] = acc[am][an][1];
            float* c2p = c0p + (size_t)8 * Nfull;
            c2p[0] = acc[am][an][2];
            c2p[1] = acc[am][an][3];
        }
    }
}

// ---------------------------------------------------------------------------
// RoPE (in-place on g_qkv)
// ---------------------------------------------------------------------------
__global__ void rope_kernel(const int* __restrict__ positions)
{
    const int s = blockIdx.x;
    const int h = blockIdx.y;
    const int d = threadIdx.x;

    const float pos = (float)positions[s];
    const float inv_freq = powf(1000000.0f, -(float)d * (1.0f / 64.0f));
    const float ang = pos * inv_freq;
    float sn, cs;
    sincosf(ang, &sn, &cs);

    float* base = g_qkv + (size_t)s * QKV_N + h * HD;
    const float x1 = base[d];
    const float x2 = base[d + 64];
    base[d]      = x1 * cs - x2 * sn;
    base[d + 64] = x2 * cs + x1 * sn;
}

// ---------------------------------------------------------------------------
// Tensor-core causal GQA flash attention (unchanged from round 6)
// ---------------------------------------------------------------------------
#define FKSTR 132
#define FVSTR 128
#define FPSTR 68
#define FLASH_SMEM_WORDS (128*FKSTR + 64*FKSTR + 64*FVSTR + 128*FPSTR)
#define FLASH_SMEM_BYTES (FLASH_SMEM_WORDS * 4)

__global__ __launch_bounds__(256)
void flash_tc_kernel()
{
    extern __shared__ uint32_t fsm[];
    uint32_t* Qs = fsm;
    uint32_t* Ks = Qs + 128 * FKSTR;
    uint32_t* Vs = Ks + 64 * FKSTR;
    uint32_t* Ps = Vs + 64 * FVSTR;

    const int tid  = threadIdx.x;
    const int warp = tid >> 5;
    const int lane = tid & 31;
    const int g    = lane >> 2;
    const int t    = lane & 3;
    const int qt   = gridDim.x - 1 - blockIdx.x;
    const int h    = blockIdx.y;
    const int kh   = h >> 2;
    const int wr   = warp * 16;

    const float* Qg = g_qkv + (size_t)(qt * 128) * QKV_N + h * HD;
    const float* Kg = g_qkv + NH * HD + kh * HD;
    const float* Vg = g_qkv + (NH + NKV) * HD + kh * HD;

    for (int i = tid; i < 128 * 32; i += 256) {
        const int r  = i >> 5;
        const int d4 = (i & 31) * 4;
        float4 v = *(const float4*)(Qg + (size_t)r * QKV_N + d4);
        *(uint4*)&Qs[r * FKSTR + d4] =
            make_uint4(f2tf(v.x), f2tf(v.y), f2tf(v.z), f2tf(v.w));
    }

    float m0 = -INFINITY, m1 = -INFINITY, l0 = 0.0f, l1 = 0.0f;
    float o[16][4];
#pragma unroll
    for (int nf = 0; nf < 16; nf++)
#pragma unroll
        for (int r = 0; r < 4; r++) o[nf][r] = 0.0f;

    const int row0 = qt * 128 + wr + g;
    const int n_ktiles = 2 * qt + 2;

    for (int jt = 0; jt < n_ktiles; jt++) {
        __syncthreads();

        const float* Kt = Kg + (size_t)(jt * 64) * QKV_N;
        const float* Vt = Vg + (size_t)(jt * 64) * QKV_N;
        for (int i = tid; i < 64 * 32; i += 256) {
            const int r  = i >> 5;
            const int d4 = (i & 31) * 4;
            float4 kv = *(const float4*)(Kt + (size_t)r * QKV_N + d4);
            *(uint4*)&Ks[r * FKSTR + d4] =
                make_uint4(f2tf(kv.x), f2tf(kv.y), f2tf(kv.z), f2tf(kv.w));
            float4 vv = *(const float4*)(Vt + (size_t)r * QKV_N + d4);
            const int dsw = d4 ^ ((r & 3) << 3);
            *(uint4*)&Vs[r * FVSTR + dsw] =
                make_uint4(f2tf(vv.x), f2tf(vv.y), f2tf(vv.z), f2tf(vv.w));
        }
        __syncthreads();

        float s[8][4];
#pragma unroll
        for (int nf = 0; nf < 8; nf++)
#pragma unroll
            for (int r = 0; r < 4; r++) s[nf][r] = 0.0f;

#pragma unroll
        for (int kc = 0; kc < 16; kc++) {
            const int kb = kc * 8;
            uint32_t a0 = Qs[(wr +     g) * FKSTR + kb +     t];
            uint32_t a1 = Qs[(wr + 8 + g) * FKSTR + kb +     t];
            uint32_t a2 = Qs[(wr +     g) * FKSTR + kb + 4 + t];
            uint32_t a3 = Qs[(wr + 8 + g) * FKSTR + kb + 4 + t];
#pragma unroll
            for (int nf = 0; nf < 8; nf++) {
                uint32_t b0 = Ks[(nf * 8 + g) * FKSTR + kb +     t];
                uint32_t b1 = Ks[(nf * 8 + g) * FKSTR + kb + 4 + t];
                MMA_TF32(s[nf], a0, a1, a2, a3, b0, b1);
            }
        }

        const int colbase = jt * 64 + 2 * t;
#pragma unroll
        for (int nf = 0; nf < 8; nf++) {
            const int col = colbase + nf * 8;
            float v0 = s[nf][0] * ATT_SCALE;
            float v1 = s[nf][1] * ATT_SCALE;
            float v2 = s[nf][2] * ATT_SCALE;
            float v3 = s[nf][3] * ATT_SCALE;
            if (col     > row0)     v0 = -1e30f;
            if (col + 1 > row0)     v1 = -1e30f;
            if (col     > row0 + 8) v2 = -1e30f;
            if (col + 1 > row0 + 8) v3 = -1e30f;
            s[nf][0] = v0; s[nf][1] = v1; s[nf][2] = v2; s[nf][3] = v3;
        }

        float rm0 = -INFINITY, rm1 = -INFINITY;
#pragma unroll
        for (int nf = 0; nf < 8; nf++) {
            rm0 = fmaxf(rm0, fmaxf(s[nf][0], s[nf][1]));
            rm1 = fmaxf(rm1, fmaxf(s[nf][2], s[nf][3]));
        }
        rm0 = fmaxf(rm0, __shfl_xor_sync(0xffffffffu, rm0, 1));
        rm0 = fmaxf(rm0, __shfl_xor_sync(0xffffffffu, rm0, 2));
        rm1 = fmaxf(rm1, __shfl_xor_sync(0xffffffffu, rm1, 1));
        rm1 = fmaxf(rm1, __shfl_xor_sync(0xffffffffu, rm1, 2));

        const float mn0 = fmaxf(m0, rm0);
        const float mn1 = fmaxf(m1, rm1);
        const float cr0 = __expf(m0 - mn0);
        const float cr1 = __expf(m1 - mn1);

        float rs0 = 0.0f, rs1 = 0.0f;
#pragma unroll
        for (int nf = 0; nf < 8; nf++) {
            s[nf][0] = __expf(s[nf][0] - mn0);
            s[nf][1] = __expf(s[nf][1] - mn0);
            s[nf][2] = __expf(s[nf][2] - mn1);
            s[nf][3] = __expf(s[nf][3] - mn1);
            rs0 += s[nf][0] + s[nf][1];
            rs1 += s[nf][2] + s[nf][3];
        }
        rs0 += __shfl_xor_sync(0xffffffffu, rs0, 1);
        rs0 += __shfl_xor_sync(0xffffffffu, rs0, 2);
        rs1 += __shfl_xor_sync(0xffffffffu, rs1, 1);
        rs1 += __shfl_xor_sync(0xffffffffu, rs1, 2);

        l0 = l0 * cr0 + rs0;  m0 = mn0;
        l1 = l1 * cr1 + rs1;  m1 = mn1;

#pragma unroll
        for (int nf = 0; nf < 16; nf++) {
            o[nf][0] *= cr0;  o[nf][1] *= cr0;
            o[nf][2] *= cr1;  o[nf][3] *= cr1;
        }

#pragma unroll
        for (int nf = 0; nf < 8; nf++) {
            const int c = nf * 8 + 2 * t;
            *(uint2*)&Ps[(wr +     g) * FPSTR + c] =
                make_uint2(f2tf(s[nf][0]), f2tf(s[nf][1]));
            *(uint2*)&Ps[(wr + 8 + g) * FPSTR + c] =
                make_uint2(f2tf(s[nf][2]), f2tf(s[nf][3]));
        }
        __syncwarp();

#pragma unroll
        for (int kc = 0; kc < 8; kc++) {
            const int kb = kc * 8;
            uint32_t a0 = Ps[(wr +     g) * FPSTR + kb +     t];
            uint32_t a1 = Ps[(wr + 8 + g) * FPSTR + kb +     t];
            uint32_t a2 = Ps[(wr +     g) * FPSTR + kb + 4 + t];
            uint32_t a3 = Ps[(wr + 8 + g) * FPSTR + kb + 4 + t];
            const int sw = t << 3;
#pragma unroll
            for (int nf = 0; nf < 16; nf++) {
                uint32_t b0 = Vs[(kb +     t) * FVSTR + ((nf * 8 + g) ^ sw)];
                uint32_t b1 = Vs[(kb + 4 + t) * FVSTR + ((nf * 8 + g) ^ sw)];
                MMA_TF32(o[nf], a0, a1, a2, a3, b0, b1);
            }
        }
        __syncwarp();
    }

    const float il0 = 1.0f / l0;
    const float il1 = 1.0f / l1;
#pragma unroll
    for (int nf = 0; nf < 16; nf++) {
        const int col = h * HD + nf * 8 + 2 * t;
        float* p0 = g_attn + (size_t)row0 * H_DIM + col;
        p0[0] = __uint_as_float(f2tf(o[nf][0] * il0));
        p0[1] = __uint_as_float(f2tf(o[nf][1] * il0));
        float* p1 = g_attn + (size_t)(row0 + 8) * H_DIM + col;
        p1[0] = __uint_as_float(f2tf(o[nf][2] * il1));
        p1[1] = __uint_as_float(f2tf(o[nf][3] * il1));
    }
}

// ---------------------------------------------------------------------------
// Launch
// ---------------------------------------------------------------------------
extern "C" void kernel_launch(void* const* d_in, const int* in_sizes, int n_in,
                              void* d_out, int out_size)
{
    (void)in_sizes; (void)n_in; (void)out_size;
    const int*   positions = (const int*)d_in[0];
    const float* hidden    = (const float*)d_in[1];
    const float* w_qkv     = (const float*)d_in[2];
    const float* w_o       = (const float*)d_in[3];
    float*       out       = (float*)d_out;

    float *qkv_ptr = nullptr, *attn_ptr = nullptr;
    uint32_t *hidA = nullptr, *wqkvB = nullptr, *woB = nullptr, *attnA = nullptr;
    cudaGetSymbolAddress((void**)&qkv_ptr, g_qkv);
    cudaGetSymbolAddress((void**)&attn_ptr, g_attn);
    cudaGetSymbolAddress((void**)&hidA, g_hidA);
    cudaGetSymbolAddress((void**)&wqkvB, g_wqkvB);
    cudaGetSymbolAddress((void**)&woB, g_woB);
    cudaGetSymbolAddress((void**)&attnA, g_attnA);

    cudaFuncSetAttribute(gemm_tf32_nt,
                         cudaFuncAttributeMaxDynamicSharedMemorySize,
                         G_SMEM_BYTES);
    cudaFuncSetAttribute(flash_tc_kernel,
                         cudaFuncAttributeMaxDynamicSharedMemorySize,
                         FLASH_SMEM_BYTES);

    // 0) convert + pack operands
    pack_a_kernel<<<2048, 256>>>(hidden, (uint4*)hidA, H_DIM,
                                 S_LEN * H_DIM / 4);
    pack_b_kernel<<<2048, 256>>>(w_qkv, (uint2*)wqkvB, H_DIM,
                                 QKV_N * H_DIM / 2);
    pack_b_kernel<<<2048, 256>>>(w_o, (uint2*)woB, H_DIM,
                                 H_DIM * H_DIM / 2);

    // 1) QKV projection
    gemm_tf32_nt<<<dim3(QKV_N / 128, S_LEN / 128), 256, G_SMEM_BYTES>>>(
        H_DIM, QKV_N, hidA, wqkvB, qkv_ptr);

    // 2) RoPE
    rope_kernel<<<dim3(S_LEN, NH + NKV), 64>>>(positions);

    // 3) Flash attention
    flash_tc_kernel<<<dim3(S_LEN / 128, NH), 256, FLASH_SMEM_BYTES>>>();

    // 3b) pack attention output for O-proj (values already tf32-rounded)
    pack_a_kernel<<<2048, 256>>>(attn_ptr, (uint4*)attnA, H_DIM,
                                 S_LEN * H_DIM / 4);

    // 4) Output projection
    gemm_tf32_nt<<<dim3(H_DIM / 128, S_LEN / 128), 256, G_SMEM_BYTES>>>(
        H_DIM, H_DIM, attnA, woB, out);
}

// round 10
// speedup vs baseline: 4.1835x; 1.0409x over previous
#include <cuda_runtime.h>
#include <math.h>
#include <stdint.h>

#define S_LEN 2048
#define H_DIM 4096
#define NH 32
#define NKV 8
#define HD 128
#define QKV_N 6144
#define ATT_SCALE 0.08838834764831843f

__device__ float g_qkv[S_LEN * QKV_N];
__device__ float g_attn[S_LEN * H_DIM];
// fragment-packed tf32 operands
__device__ uint32_t g_hidA [S_LEN * H_DIM];
__device__ uint32_t g_wqkvB[QKV_N * H_DIM];
__device__ uint32_t g_woB  [H_DIM * H_DIM];
__device__ uint32_t g_attnA[S_LEN * H_DIM];

__device__ __forceinline__ uint32_t f2tf(float x) {
    uint32_t r;
    asm("cvt.rna.tf32.f32 %0, %1;" : "=r"(r) : "f"(x));
    return r;
}

__device__ __forceinline__ uint32_t smem_u32(const void* p) {
    uint32_t a;
    asm("{ .reg .u64 t; cvta.to.shared.u64 t, %1; cvt.u32.u64 %0, t; }"
        : "=r"(a) : "l"(p));
    return a;
}

#define MMA_TF32(ACC, A0, A1, A2, A3, B0, B1)                                  \
    asm volatile(                                                              \
        "mma.sync.aligned.m16n8k8.row.col.f32.tf32.tf32.f32 "                  \
        "{%0,%1,%2,%3}, {%4,%5,%6,%7}, {%8,%9}, {%0,%1,%2,%3};\n"              \
        : "+f"(ACC[0]), "+f"(ACC[1]), "+f"(ACC[2]), "+f"(ACC[3])               \
        : "r"(A0), "r"(A1), "r"(A2), "r"(A3), "r"(B0), "r"(B1))

#define CP_ASYNC16(dst, src)                                                   \
    asm volatile("cp.async.cg.shared.global [%0], [%1], 16;"                   \
                 :: "r"(dst), "l"(src) : "memory")
#define CP_COMMIT()  asm volatile("cp.async.commit_group;" ::: "memory")
#define CP_WAIT1()   asm volatile("cp.async.wait_group 1;" ::: "memory")
#define CP_WAIT0()   asm volatile("cp.async.wait_group 0;" ::: "memory")

// ---------------------------------------------------------------------------
// A-pack: float [M,K] row-major -> fragment-packed tf32.
// ---------------------------------------------------------------------------
__global__ void pack_a_kernel(const float* __restrict__ in,
                              uint4* __restrict__ out, int K, int n4)
{
    const int k16n = K / 16;
    for (int idx = blockIdx.x * blockDim.x + threadIdx.x; idx < n4;
         idx += gridDim.x * blockDim.x) {
        const int slab = idx >> 9;
        const int rem  = idx & 511;
        const int sub  = rem >> 5;
        const int lane = rem & 31;
        const int mblk = slab / k16n;
        const int k16  = slab - mblk * k16n;
        const int row  = mblk * 128 + (sub >> 1) * 16 + (lane >> 2);
        const int k    = k16 * 16 + (sub & 1) * 8 + (lane & 3);
        const float* p = in + (size_t)row * K + k;
        out[idx] = make_uint4(f2tf(p[0]),
                              f2tf(p[(size_t)8 * K]),
                              f2tf(p[4]),
                              f2tf(p[(size_t)8 * K + 4]));
    }
}

// ---------------------------------------------------------------------------
// B-pack: float [N,K] row-major -> fragment-packed tf32.
// ---------------------------------------------------------------------------
__global__ void pack_b_kernel(const float* __restrict__ in,
                              uint2* __restrict__ out, int K, int n2)
{
    const int k16n = K / 16;
    for (int idx = blockIdx.x * blockDim.x + threadIdx.x; idx < n2;
         idx += gridDim.x * blockDim.x) {
        const int slab = idx >> 10;
        const int rem  = idx & 1023;
        const int sub  = rem >> 5;
        const int lane = rem & 31;
        const int nblk = slab / k16n;
        const int k16  = slab - nblk * k16n;
        const int row  = nblk * 128 + (sub >> 1) * 8 + (lane >> 2);
        const int k    = k16 * 16 + (sub & 1) * 8 + (lane & 3);
        const float* p = in + (size_t)row * K + k;
        out[idx] = make_uint2(f2tf(p[0]), f2tf(p[4]));
    }
}

// ---------------------------------------------------------------------------
// TF32 GEMM on fragment-packed operands (unchanged from round 8)
// ---------------------------------------------------------------------------
#define SLAB_W 2048
#define G_SMEM_BYTES (6 * SLAB_W * 4)

__global__ __launch_bounds__(256)
void gemm_tf32_nt(int K, int Nfull,
                  const uint32_t* __restrict__ A,
                  const uint32_t* __restrict__ B,
                  float* __restrict__ C)
{
    extern __shared__ uint32_t gdyn[];
    uint32_t* As = gdyn;
    uint32_t* Bs = gdyn + 3 * SLAB_W;
    const uint32_t as_base = smem_u32(As);
    const uint32_t bs_base = smem_u32(Bs);

    const int tid  = threadIdx.x;
    const int warp = tid >> 5;
    const int lane = tid & 31;
    const int g    = lane >> 2;
    const int t    = lane & 3;

    const int k16n = K / 16;
    const uint32_t* Aslab = A + (size_t)blockIdx.y * k16n * SLAB_W;
    const uint32_t* Bslab = B + (size_t)blockIdx.x * k16n * SLAB_W;

    const int m16b = (warp & 1) * 4;
    const int n8b  = (warp >> 1) * 4;

    float acc[4][4][4];
#pragma unroll
    for (int i = 0; i < 4; i++)
#pragma unroll
        for (int j = 0; j < 4; j++)
#pragma unroll
            for (int r = 0; r < 4; r++) acc[i][j][r] = 0.0f;

#pragma unroll
    for (int s = 0; s < 2; s++) {
        const uint32_t ab = as_base + s * SLAB_W * 4;
        const uint32_t bb = bs_base + s * SLAB_W * 4;
        const uint32_t* Ap = Aslab + (size_t)s * SLAB_W;
        const uint32_t* Bp = Bslab + (size_t)s * SLAB_W;
#pragma unroll
        for (int i = 0; i < 2; i++) {
            CP_ASYNC16(ab + (tid + i * 256) * 16, Ap + (tid + i * 256) * 4);
            CP_ASYNC16(bb + (tid + i * 256) * 16, Bp + (tid + i * 256) * 4);
        }
        CP_COMMIT();
    }

    int stg = 0;
    for (int kt = 0; kt < k16n; kt++) {
        CP_WAIT1();
        __syncthreads();

        if (kt + 2 < k16n) {
            const int s2 = (kt + 2) % 3;
            const uint32_t ab = as_base + s2 * SLAB_W * 4;
            const uint32_t bb = bs_base + s2 * SLAB_W * 4;
            const uint32_t* Ap = Aslab + (size_t)(kt + 2) * SLAB_W;
            const uint32_t* Bp = Bslab + (size_t)(kt + 2) * SLAB_W;
#pragma unroll
            for (int i = 0; i < 2; i++) {
                CP_ASYNC16(ab + (tid + i * 256) * 16, Ap + (tid + i * 256) * 4);
                CP_ASYNC16(bb + (tid + i * 256) * 16, Bp + (tid + i * 256) * 4);
            }
        }
        CP_COMMIT();

        const uint32_t* as = As + stg * SLAB_W;
        const uint32_t* bs = Bs + stg * SLAB_W;
#pragma unroll
        for (int ks = 0; ks < 2; ks++) {
            uint4 aw[4];
            uint2 bw[4];
#pragma unroll
            for (int am = 0; am < 4; am++)
                aw[am] = *(const uint4*)&as[((m16b + am) * 2 + ks) * 128 + lane * 4];
#pragma unroll
            for (int an = 0; an < 4; an++)
                bw[an] = *(const uint2*)&bs[((n8b + an) * 2 + ks) * 64 + lane * 2];
#pragma unroll
            for (int am = 0; am < 4; am++)
#pragma unroll
                for (int an = 0; an < 4; an++)
                    MMA_TF32(acc[am][an], aw[am].x, aw[am].y, aw[am].z, aw[am].w,
                             bw[an].x, bw[an].y);
        }
        stg = (stg + 1) % 3;
    }
    CP_WAIT0();

    const int bm = blockIdx.y * 128;
    const int bn = blockIdx.x * 128;
#pragma unroll
    for (int am = 0; am < 4; am++) {
        const int row0 = bm + m16b * 16 + am * 16 + g;
#pragma unroll
        for (int an = 0; an < 4; an++) {
            const int col = bn + n8b * 8 + an * 8 + t * 2;
            float* c0p = C + (size_t)row0 * Nfull + col;
            c0p[0] = acc[am][an][0];
            c0p[1] = acc[am][an][1];
            float* c2p = c0p + (size_t)8 * Nfull;
            c2p[0] = acc[am][an][2];
            c2p[1] = acc[am][an][3];
        }
    }
}

// ---------------------------------------------------------------------------
// RoPE + tf32 pre-round. Heads 0..39: rotate + round. Heads 40..47 (V):
// round only. After this kernel all of g_qkv holds tf32-rounded bits.
// ---------------------------------------------------------------------------
__global__ void rope_kernel(const int* __restrict__ positions)
{
    const int s = blockIdx.x;
    const int h = blockIdx.y;          // 0..47
    const int d = threadIdx.x;         // 0..63

    float* base = g_qkv + (size_t)s * QKV_N + h * HD;
    const float x1 = base[d];
    const float x2 = base[d + 64];

    if (h < NH + NKV) {
        const float pos = (float)positions[s];
        const float inv_freq = powf(1000000.0f, -(float)d * (1.0f / 64.0f));
        const float ang = pos * inv_freq;
        float sn, cs;
        sincosf(ang, &sn, &cs);
        base[d]      = __uint_as_float(f2tf(x1 * cs - x2 * sn));
        base[d + 64] = __uint_as_float(f2tf(x2 * cs + x1 * sn));
    } else {
        base[d]      = __uint_as_float(f2tf(x1));
        base[d + 64] = __uint_as_float(f2tf(x2));
    }
}

// ---------------------------------------------------------------------------
// Flash attention v2 (fixed): Q a-frags in registers, K/V cp.async double
// buffer with FULL tile coverage: 8 chunks/thread/tile for K and V each.
// Per-thread mapping: rows warp+8i (i=0..7), column words lane*4.
// ---------------------------------------------------------------------------
#define FKSTR 132
#define FVSTR 128
#define FPSTR 68
#define KSTG_W (64 * FKSTR)       // 8448
#define VSTG_W (64 * FVSTR)       // 8192
#define FLASH_SMEM_WORDS (2 * KSTG_W + 2 * VSTG_W + 128 * FPSTR)
#define FLASH_SMEM_BYTES (FLASH_SMEM_WORDS * 4)   // 167936

__global__ __launch_bounds__(256)
void flash_tc_kernel()
{
    extern __shared__ uint32_t fsm[];
    uint32_t* Ks = fsm;                        // [2][KSTG_W]
    uint32_t* Vs = fsm + 2 * KSTG_W;           // [2][VSTG_W]
    uint32_t* Ps = fsm + 2 * KSTG_W + 2 * VSTG_W;
    const uint32_t ks_base = smem_u32(Ks);
    const uint32_t vs_base = smem_u32(Vs);

    const int tid  = threadIdx.x;
    const int warp = tid >> 5;
    const int lane = tid & 31;
    const int g    = lane >> 2;
    const int t    = lane & 3;
    const int qt   = gridDim.x - 1 - blockIdx.x;
    const int h    = blockIdx.y;
    const int kh   = h >> 2;
    const int wr   = warp * 16;

    const float* Qg = g_qkv + (size_t)(qt * 128) * QKV_N + h * HD;
    const float* Kg = g_qkv + NH * HD + kh * HD;
    const float* Vg = g_qkv + (NH + NKV) * HD + kh * HD;

    // cp.async per-thread mapping: 8 chunks each for K and V.
    // chunk i: row = warp + 8*i, column word = lane*4.
    const int cw  = lane * 4;
    const int vsw = cw ^ ((warp & 3) << 3);   // (row&3)==(warp&3) for all i

    // Q a-fragments -> registers
    uint32_t qf[16][4];
    {
        const float* q0 = Qg + (size_t)(wr +     g) * QKV_N;
        const float* q1 = Qg + (size_t)(wr + 8 + g) * QKV_N;
#pragma unroll
        for (int kc = 0; kc < 16; kc++) {
            const int c = kc * 8 + t;
            qf[kc][0] = __float_as_uint(q0[c]);
            qf[kc][1] = __float_as_uint(q1[c]);
            qf[kc][2] = __float_as_uint(q0[c + 4]);
            qf[kc][3] = __float_as_uint(q1[c + 4]);
        }
    }

    float m0 = -INFINITY, m1 = -INFINITY, l0 = 0.0f, l1 = 0.0f;
    float o[16][4];
#pragma unroll
    for (int nf = 0; nf < 16; nf++)
#pragma unroll
        for (int r = 0; r < 4; r++) o[nf][r] = 0.0f;

    const int row0 = qt * 128 + wr + g;
    const int n_ktiles = 2 * qt + 2;

    // prologue: stage 0 <- tile 0
    {
#pragma unroll
        for (int i = 0; i < 8; i++) {
            const int r = warp + 8 * i;
            CP_ASYNC16(ks_base + (uint32_t)(r * FKSTR + cw) * 4,
                       Kg + (size_t)r * QKV_N + cw);
            CP_ASYNC16(vs_base + (uint32_t)(r * FVSTR + vsw) * 4,
                       Vg + (size_t)r * QKV_N + cw);
        }
        CP_COMMIT();
    }

    for (int jt = 0; jt < n_ktiles; jt++) {
        __syncthreads();   // all readers of buffer (jt+1)&1 (iter jt-1) done
        if (jt + 1 < n_ktiles) {
            const int s = (jt + 1) & 1;
            const float* Kt = Kg + (size_t)((jt + 1) * 64) * QKV_N;
            const float* Vt = Vg + (size_t)((jt + 1) * 64) * QKV_N;
            const uint32_t kb = ks_base + s * KSTG_W * 4;
            const uint32_t vb = vs_base + s * VSTG_W * 4;
#pragma unroll
            for (int i = 0; i < 8; i++) {
                const int r = warp + 8 * i;
                CP_ASYNC16(kb + (uint32_t)(r * FKSTR + cw) * 4,
                           Kt + (size_t)r * QKV_N + cw);
                CP_ASYNC16(vb + (uint32_t)(r * FVSTR + vsw) * 4,
                           Vt + (size_t)r * QKV_N + cw);
            }
        }
        CP_COMMIT();
        CP_WAIT1();        // tile jt's group complete
        __syncthreads();

        const uint32_t* ks = Ks + (jt & 1) * KSTG_W;
        const uint32_t* vs = Vs + (jt & 1) * VSTG_W;

        // ---- S = Q K^T ----
        float s4[8][4];
#pragma unroll
        for (int nf = 0; nf < 8; nf++)
#pragma unroll
            for (int r = 0; r < 4; r++) s4[nf][r] = 0.0f;

#pragma unroll
        for (int kc = 0; kc < 16; kc++) {
            const int kb = kc * 8;
#pragma unroll
            for (int nf = 0; nf < 8; nf++) {
                uint32_t b0 = ks[(nf * 8 + g) * FKSTR + kb +     t];
                uint32_t b1 = ks[(nf * 8 + g) * FKSTR + kb + 4 + t];
                MMA_TF32(s4[nf], qf[kc][0], qf[kc][1], qf[kc][2], qf[kc][3], b0, b1);
            }
        }

        // ---- scale + causal mask ----
        const int colbase = jt * 64 + 2 * t;
#pragma unroll
        for (int nf = 0; nf < 8; nf++) {
            const int col = colbase + nf * 8;
            float v0 = s4[nf][0] * ATT_SCALE;
            float v1 = s4[nf][1] * ATT_SCALE;
            float v2 = s4[nf][2] * ATT_SCALE;
            float v3 = s4[nf][3] * ATT_SCALE;
            if (col     > row0)     v0 = -1e30f;
            if (col + 1 > row0)     v1 = -1e30f;
            if (col     > row0 + 8) v2 = -1e30f;
            if (col + 1 > row0 + 8) v3 = -1e30f;
            s4[nf][0] = v0; s4[nf][1] = v1; s4[nf][2] = v2; s4[nf][3] = v3;
        }

        // ---- online softmax ----
        float rm0 = -INFINITY, rm1 = -INFINITY;
#pragma unroll
        for (int nf = 0; nf < 8; nf++) {
            rm0 = fmaxf(rm0, fmaxf(s4[nf][0], s4[nf][1]));
            rm1 = fmaxf(rm1, fmaxf(s4[nf][2], s4[nf][3]));
        }
        rm0 = fmaxf(rm0, __shfl_xor_sync(0xffffffffu, rm0, 1));
        rm0 = fmaxf(rm0, __shfl_xor_sync(0xffffffffu, rm0, 2));
        rm1 = fmaxf(rm1, __shfl_xor_sync(0xffffffffu, rm1, 1));
        rm1 = fmaxf(rm1, __shfl_xor_sync(0xffffffffu, rm1, 2));

        const float mn0 = fmaxf(m0, rm0);
        const float mn1 = fmaxf(m1, rm1);
        const float cr_0 = __expf(m0 - mn0);
        const float cr_1 = __expf(m1 - mn1);

        float rs0 = 0.0f, rs1 = 0.0f;
#pragma unroll
        for (int nf = 0; nf < 8; nf++) {
            s4[nf][0] = __expf(s4[nf][0] - mn0);
            s4[nf][1] = __expf(s4[nf][1] - mn0);
            s4[nf][2] = __expf(s4[nf][2] - mn1);
            s4[nf][3] = __expf(s4[nf][3] - mn1);
            rs0 += s4[nf][0] + s4[nf][1];
            rs1 += s4[nf][2] + s4[nf][3];
        }
        rs0 += __shfl_xor_sync(0xffffffffu, rs0, 1);
        rs0 += __shfl_xor_sync(0xffffffffu, rs0, 2);
        rs1 += __shfl_xor_sync(0xffffffffu, rs1, 1);
        rs1 += __shfl_xor_sync(0xffffffffu, rs1, 2);

        l0 = l0 * cr_0 + rs0;  m0 = mn0;
        l1 = l1 * cr_1 + rs1;  m1 = mn1;

#pragma unroll
        for (int nf = 0; nf < 16; nf++) {
            o[nf][0] *= cr_0;  o[nf][1] *= cr_0;
            o[nf][2] *= cr_1;  o[nf][3] *= cr_1;
        }

        // ---- stage P ----
#pragma unroll
        for (int nf = 0; nf < 8; nf++) {
            const int c = nf * 8 + 2 * t;
            *(uint2*)&Ps[(wr +     g) * FPSTR + c] =
                make_uint2(f2tf(s4[nf][0]), f2tf(s4[nf][1]));
            *(uint2*)&Ps[(wr + 8 + g) * FPSTR + c] =
                make_uint2(f2tf(s4[nf][2]), f2tf(s4[nf][3]));
        }
        __syncwarp();

        // ---- O += P V ----
#pragma unroll
        for (int kc = 0; kc < 8; kc++) {
            const int kb = kc * 8;
            uint32_t a0 = Ps[(wr +     g) * FPSTR + kb +     t];
            uint32_t a1 = Ps[(wr + 8 + g) * FPSTR + kb +     t];
            uint32_t a2 = Ps[(wr +     g) * FPSTR + kb + 4 + t];
            uint32_t a3 = Ps[(wr + 8 + g) * FPSTR + kb + 4 + t];
            const int sw = t << 3;
#pragma unroll
            for (int nf = 0; nf < 16; nf++) {
                uint32_t b0 = vs[(kb +     t) * FVSTR + ((nf * 8 + g) ^ sw)];
                uint32_t b1 = vs[(kb + 4 + t) * FVSTR + ((nf * 8 + g) ^ sw)];
                MMA_TF32(o[nf], a0, a1, a2, a3, b0, b1);
            }
        }
        __syncwarp();
    }

    const float il0 = 1.0f / l0;
    const float il1 = 1.0f / l1;
#pragma unroll
    for (int nf = 0; nf < 16; nf++) {
        const int col = h * HD + nf * 8 + 2 * t;
        float* p0 = g_attn + (size_t)row0 * H_DIM + col;
        p0[0] = __uint_as_float(f2tf(o[nf][0] * il0));
        p0[1] = __uint_as_float(f2tf(o[nf][1] * il0));
        float* p1 = g_attn + (size_t)(row0 + 8) * H_DIM + col;
        p1[0] = __uint_as_float(f2tf(o[nf][2] * il1));
        p1[1] = __uint_as_float(f2tf(o[nf][3] * il1));
    }
}

// ---------------------------------------------------------------------------
// Launch
// ---------------------------------------------------------------------------
extern "C" void kernel_launch(void* const* d_in, const int* in_sizes, int n_in,
                              void* d_out, int out_size)
{
    (void)in_sizes; (void)n_in; (void)out_size;
    const int*   positions = (const int*)d_in[0];
    const float* hidden    = (const float*)d_in[1];
    const float* w_qkv     = (const float*)d_in[2];
    const float* w_o       = (const float*)d_in[3];
    float*       out       = (float*)d_out;

    float *qkv_ptr = nullptr, *attn_ptr = nullptr;
    uint32_t *hidA = nullptr, *wqkvB = nullptr, *woB = nullptr, *attnA = nullptr;
    cudaGetSymbolAddress((void**)&qkv_ptr, g_qkv);
    cudaGetSymbolAddress((void**)&attn_ptr, g_attn);
    cudaGetSymbolAddress((void**)&hidA, g_hidA);
    cudaGetSymbolAddress((void**)&wqkvB, g_wqkvB);
    cudaGetSymbolAddress((void**)&woB, g_woB);
    cudaGetSymbolAddress((void**)&attnA, g_attnA);

    cudaFuncSetAttribute(gemm_tf32_nt,
                         cudaFuncAttributeMaxDynamicSharedMemorySize,
                         G_SMEM_BYTES);
    cudaFuncSetAttribute(flash_tc_kernel,
                         cudaFuncAttributeMaxDynamicSharedMemorySize,
                         FLASH_SMEM_BYTES);

    // 0) convert + pack operands
    pack_a_kernel<<<2048, 256>>>(hidden, (uint4*)hidA, H_DIM,
                                 S_LEN * H_DIM / 4);
    pack_b_kernel<<<2048, 256>>>(w_qkv, (uint2*)wqkvB, H_DIM,
                                 QKV_N * H_DIM / 2);
    pack_b_kernel<<<2048, 256>>>(w_o, (uint2*)woB, H_DIM,
                                 H_DIM * H_DIM / 2);

    // 1) QKV projection
    gemm_tf32_nt<<<dim3(QKV_N / 128, S_LEN / 128), 256, G_SMEM_BYTES>>>(
        H_DIM, QKV_N, hidA, wqkvB, qkv_ptr);

    // 2) RoPE (+ tf32 rounding of Q, K, V)
    rope_kernel<<<dim3(S_LEN, NH + 2 * NKV), 64>>>(positions);

    // 3) Flash attention
    flash_tc_kernel<<<dim3(S_LEN / 128, NH), 256, FLASH_SMEM_BYTES>>>();

    // 3b) pack attention output for O-proj
    pack_a_kernel<<<2048, 256>>>(attn_ptr, (uint4*)attnA, H_DIM,
                                 S_LEN * H_DIM / 4);

    // 4) Output projection
    gemm_tf32_nt<<<dim3(H_DIM / 128, S_LEN / 128), 256, G_SMEM_BYTES>>>(
        H_DIM, H_DIM, attnA, woB, out);
}

// round 11
// speedup vs baseline: 4.3871x; 1.0487x over previous
#include <cuda_runtime.h>
#include <math.h>
#include <stdint.h>

#define S_LEN 2048
#define H_DIM 4096
#define NH 32
#define NKV 8
#define HD 128
#define QKV_N 6144
#define ATT_SCALE 0.08838834764831843f

__device__ float g_qkv[S_LEN * QKV_N];
__device__ float g_attn[S_LEN * H_DIM];
// fragment-packed tf32 operands
__device__ uint32_t g_hidA [S_LEN * H_DIM];
__device__ uint32_t g_wqkvB[QKV_N * H_DIM];
__device__ uint32_t g_woB  [H_DIM * H_DIM];
__device__ uint32_t g_attnA[S_LEN * H_DIM];

__device__ __forceinline__ uint32_t f2tf(float x) {
    uint32_t r;
    asm("cvt.rna.tf32.f32 %0, %1;" : "=r"(r) : "f"(x));
    return r;
}

__device__ __forceinline__ uint32_t smem_u32(const void* p) {
    uint32_t a;
    asm("{ .reg .u64 t; cvta.to.shared.u64 t, %1; cvt.u32.u64 %0, t; }"
        : "=r"(a) : "l"(p));
    return a;
}

#define MMA_TF32(ACC, A0, A1, A2, A3, B0, B1)                                  \
    asm volatile(                                                              \
        "mma.sync.aligned.m16n8k8.row.col.f32.tf32.tf32.f32 "                  \
        "{%0,%1,%2,%3}, {%4,%5,%6,%7}, {%8,%9}, {%0,%1,%2,%3};\n"              \
        : "+f"(ACC[0]), "+f"(ACC[1]), "+f"(ACC[2]), "+f"(ACC[3])               \
        : "r"(A0), "r"(A1), "r"(A2), "r"(A3), "r"(B0), "r"(B1))

#define CP_ASYNC16(dst, src)                                                   \
    asm volatile("cp.async.cg.shared.global [%0], [%1], 16;"                   \
                 :: "r"(dst), "l"(src) : "memory")
#define CP_COMMIT()  asm volatile("cp.async.commit_group;" ::: "memory")
#define CP_WAIT1()   asm volatile("cp.async.wait_group 1;" ::: "memory")
#define CP_WAIT0()   asm volatile("cp.async.wait_group 0;" ::: "memory")

// ---------------------------------------------------------------------------
// A-pack: float [M,K] row-major -> fragment-packed tf32.
// ---------------------------------------------------------------------------
__global__ void pack_a_kernel(const float* __restrict__ in,
                              uint4* __restrict__ out, int K, int n4)
{
    const int k16n = K / 16;
    for (int idx = blockIdx.x * blockDim.x + threadIdx.x; idx < n4;
         idx += gridDim.x * blockDim.x) {
        const int slab = idx >> 9;
        const int rem  = idx & 511;
        const int sub  = rem >> 5;
        const int lane = rem & 31;
        const int mblk = slab / k16n;
        const int k16  = slab - mblk * k16n;
        const int row  = mblk * 128 + (sub >> 1) * 16 + (lane >> 2);
        const int k    = k16 * 16 + (sub & 1) * 8 + (lane & 3);
        const float* p = in + (size_t)row * K + k;
        out[idx] = make_uint4(f2tf(p[0]),
                              f2tf(p[(size_t)8 * K]),
                              f2tf(p[4]),
                              f2tf(p[(size_t)8 * K + 4]));
    }
}

// ---------------------------------------------------------------------------
// B-pack: float [N,K] row-major -> fragment-packed tf32.
// ---------------------------------------------------------------------------
__global__ void pack_b_kernel(const float* __restrict__ in,
                              uint2* __restrict__ out, int K, int n2)
{
    const int k16n = K / 16;
    for (int idx = blockIdx.x * blockDim.x + threadIdx.x; idx < n2;
         idx += gridDim.x * blockDim.x) {
        const int slab = idx >> 10;
        const int rem  = idx & 1023;
        const int sub  = rem >> 5;
        const int lane = rem & 31;
        const int nblk = slab / k16n;
        const int k16  = slab - nblk * k16n;
        const int row  = nblk * 128 + (sub >> 1) * 8 + (lane >> 2);
        const int k    = k16 * 16 + (sub & 1) * 8 + (lane & 3);
        const float* p = in + (size_t)row * K + k;
        out[idx] = make_uint2(f2tf(p[0]), f2tf(p[4]));
    }
}

// ---------------------------------------------------------------------------
// TF32 GEMM, 128x256 CTA tile, 64x64 warp tiles (m=4,n=8), cp.async 3-stage.
// A slab = 2048 words (128 rows x k16). B tile = two adjacent packed 128-row
// slabs (half 0 / half 1); warps 0-3 consume half 0, warps 4-7 half 1.
// ---------------------------------------------------------------------------
#define A_SLAB_W 2048
#define B_STG_W  4096
#define STG_W    (A_SLAB_W + B_STG_W)
#define G_SMEM_BYTES (3 * STG_W * 4)      // 73728

__global__ __launch_bounds__(256, 1)
void gemm_tf32_nt(int K, int Nfull,
                  const uint32_t* __restrict__ A,
                  const uint32_t* __restrict__ B,
                  float* __restrict__ C)
{
    extern __shared__ uint32_t gdyn[];
    uint32_t* As = gdyn;                     // [3][A_SLAB_W]
    uint32_t* Bs = gdyn + 3 * A_SLAB_W;      // [3][B_STG_W]
    const uint32_t as_base = smem_u32(As);
    const uint32_t bs_base = smem_u32(Bs);

    const int tid  = threadIdx.x;
    const int warp = tid >> 5;
    const int lane = tid & 31;
    const int g    = lane >> 2;
    const int t    = lane & 3;

    const int k16n = K / 16;
    const uint32_t* Aslab  = A + (size_t)blockIdx.y * k16n * A_SLAB_W;
    const uint32_t* Bslab0 = B + (size_t)(2 * blockIdx.x)     * k16n * A_SLAB_W;
    const uint32_t* Bslab1 = B + (size_t)(2 * blockIdx.x + 1) * k16n * A_SLAB_W;

    const int m16b = (warp & 1) * 4;       // 0 or 4
    const int n8b  = (warp >> 1) * 8;      // 0,8,16,24
    const int half = n8b >> 4;             // 0 or 1
    const int n8l  = n8b & 15;             // 0 or 8

    float acc[4][8][4];
#pragma unroll
    for (int i = 0; i < 4; i++)
#pragma unroll
        for (int j = 0; j < 8; j++)
#pragma unroll
            for (int r = 0; r < 4; r++) acc[i][j][r] = 0.0f;

    // stage fill: A 2 chunks/thread, B 4 chunks/thread
#define G_FILL(stage, kt)                                                      \
    do {                                                                       \
        const uint32_t ab = as_base + (stage) * A_SLAB_W * 4;                  \
        const uint32_t bb = bs_base + (stage) * B_STG_W * 4;                   \
        const uint32_t* Ap  = Aslab  + (size_t)(kt) * A_SLAB_W;                \
        const uint32_t* Bp0 = Bslab0 + (size_t)(kt) * A_SLAB_W;                \
        const uint32_t* Bp1 = Bslab1 + (size_t)(kt) * A_SLAB_W;                \
        CP_ASYNC16(ab + tid * 16,          Ap  + tid * 4);                     \
        CP_ASYNC16(ab + (tid + 256) * 16,  Ap  + (tid + 256) * 4);             \
        CP_ASYNC16(bb + tid * 16,          Bp0 + tid * 4);                     \
        CP_ASYNC16(bb + (tid + 256) * 16,  Bp0 + (tid + 256) * 4);             \
        CP_ASYNC16(bb + (tid + 512) * 16,  Bp1 + tid * 4);                     \
        CP_ASYNC16(bb + (tid + 768) * 16,  Bp1 + (tid + 256) * 4);             \
    } while (0)

    G_FILL(0, 0);
    CP_COMMIT();
    G_FILL(1, 1);
    CP_COMMIT();

    int stg = 0;
    for (int kt = 0; kt < k16n; kt++) {
        CP_WAIT1();
        __syncthreads();

        if (kt + 2 < k16n) {
            const int s2 = (kt + 2) % 3;
            G_FILL(s2, kt + 2);
        }
        CP_COMMIT();

        const uint32_t* as = As + stg * A_SLAB_W;
        const uint32_t* bs = Bs + stg * B_STG_W + half * A_SLAB_W;
#pragma unroll
        for (int ks = 0; ks < 2; ks++) {
            uint4 aw[4];
            uint2 bw[8];
#pragma unroll
            for (int am = 0; am < 4; am++)
                aw[am] = *(const uint4*)&as[((m16b + am) * 2 + ks) * 128 + lane * 4];
#pragma unroll
            for (int an = 0; an < 8; an++)
                bw[an] = *(const uint2*)&bs[((n8l + an) * 2 + ks) * 64 + lane * 2];
#pragma unroll
            for (int am = 0; am < 4; am++)
#pragma unroll
                for (int an = 0; an < 8; an++)
                    MMA_TF32(acc[am][an], aw[am].x, aw[am].y, aw[am].z, aw[am].w,
                             bw[an].x, bw[an].y);
        }
        stg = (stg + 1) % 3;
    }
    CP_WAIT0();

    const int bm = blockIdx.y * 128;
    const int bn = blockIdx.x * 256;
#pragma unroll
    for (int am = 0; am < 4; am++) {
        const int row0 = bm + (m16b + am) * 16 + g;
#pragma unroll
        for (int an = 0; an < 8; an++) {
            const int col = bn + (n8b + an) * 8 + t * 2;
            float* c0p = C + (size_t)row0 * Nfull + col;
            c0p[0] = acc[am][an][0];
            c0p[1] = acc[am][an][1];
            float* c2p = c0p + (size_t)8 * Nfull;
            c2p[0] = acc[am][an][2];
            c2p[1] = acc[am][an][3];
        }
    }
#undef G_FILL
}

// ---------------------------------------------------------------------------
// RoPE + tf32 pre-round (heads 0..39 rotate+round, 40..47 round only)
// ---------------------------------------------------------------------------
__global__ void rope_kernel(const int* __restrict__ positions)
{
    const int s = blockIdx.x;
    const int h = blockIdx.y;          // 0..47
    const int d = threadIdx.x;         // 0..63

    float* base = g_qkv + (size_t)s * QKV_N + h * HD;
    const float x1 = base[d];
    const float x2 = base[d + 64];

    if (h < NH + NKV) {
        const float pos = (float)positions[s];
        const float inv_freq = powf(1000000.0f, -(float)d * (1.0f / 64.0f));
        const float ang = pos * inv_freq;
        float sn, cs;
        sincosf(ang, &sn, &cs);
        base[d]      = __uint_as_float(f2tf(x1 * cs - x2 * sn));
        base[d + 64] = __uint_as_float(f2tf(x2 * cs + x1 * sn));
    } else {
        base[d]      = __uint_as_float(f2tf(x1));
        base[d + 64] = __uint_as_float(f2tf(x2));
    }
}

// ---------------------------------------------------------------------------
// Flash attention (unchanged from round 10)
// ---------------------------------------------------------------------------
#define FKSTR 132
#define FVSTR 128
#define FPSTR 68
#define KSTG_W (64 * FKSTR)
#define VSTG_W (64 * FVSTR)
#define FLASH_SMEM_WORDS (2 * KSTG_W + 2 * VSTG_W + 128 * FPSTR)
#define FLASH_SMEM_BYTES (FLASH_SMEM_WORDS * 4)   // 167936

__global__ __launch_bounds__(256)
void flash_tc_kernel()
{
    extern __shared__ uint32_t fsm[];
    uint32_t* Ks = fsm;
    uint32_t* Vs = fsm + 2 * KSTG_W;
    uint32_t* Ps = fsm + 2 * KSTG_W + 2 * VSTG_W;
    const uint32_t ks_base = smem_u32(Ks);
    const uint32_t vs_base = smem_u32(Vs);

    const int tid  = threadIdx.x;
    const int warp = tid >> 5;
    const int lane = tid & 31;
    const int g    = lane >> 2;
    const int t    = lane & 3;
    const int qt   = gridDim.x - 1 - blockIdx.x;
    const int h    = blockIdx.y;
    const int kh   = h >> 2;
    const int wr   = warp * 16;

    const float* Qg = g_qkv + (size_t)(qt * 128) * QKV_N + h * HD;
    const float* Kg = g_qkv + NH * HD + kh * HD;
    const float* Vg = g_qkv + (NH + NKV) * HD + kh * HD;

    const int cw  = lane * 4;
    const int vsw = cw ^ ((warp & 3) << 3);

    uint32_t qf[16][4];
    {
        const float* q0 = Qg + (size_t)(wr +     g) * QKV_N;
        const float* q1 = Qg + (size_t)(wr + 8 + g) * QKV_N;
#pragma unroll
        for (int kc = 0; kc < 16; kc++) {
            const int c = kc * 8 + t;
            qf[kc][0] = __float_as_uint(q0[c]);
            qf[kc][1] = __float_as_uint(q1[c]);
            qf[kc][2] = __float_as_uint(q0[c + 4]);
            qf[kc][3] = __float_as_uint(q1[c + 4]);
        }
    }

    float m0 = -INFINITY, m1 = -INFINITY, l0 = 0.0f, l1 = 0.0f;
    float o[16][4];
#pragma unroll
    for (int nf = 0; nf < 16; nf++)
#pragma unroll
        for (int r = 0; r < 4; r++) o[nf][r] = 0.0f;

    const int row0 = qt * 128 + wr + g;
    const int n_ktiles = 2 * qt + 2;

    {
#pragma unroll
        for (int i = 0; i < 8; i++) {
            const int r = warp + 8 * i;
            CP_ASYNC16(ks_base + (uint32_t)(r * FKSTR + cw) * 4,
                       Kg + (size_t)r * QKV_N + cw);
            CP_ASYNC16(vs_base + (uint32_t)(r * FVSTR + vsw) * 4,
                       Vg + (size_t)r * QKV_N + cw);
        }
        CP_COMMIT();
    }

    for (int jt = 0; jt < n_ktiles; jt++) {
        __syncthreads();
        if (jt + 1 < n_ktiles) {
            const int s = (jt + 1) & 1;
            const float* Kt = Kg + (size_t)((jt + 1) * 64) * QKV_N;
            const float* Vt = Vg + (size_t)((jt + 1) * 64) * QKV_N;
            const uint32_t kb = ks_base + s * KSTG_W * 4;
            const uint32_t vb = vs_base + s * VSTG_W * 4;
#pragma unroll
            for (int i = 0; i < 8; i++) {
                const int r = warp + 8 * i;
                CP_ASYNC16(kb + (uint32_t)(r * FKSTR + cw) * 4,
                           Kt + (size_t)r * QKV_N + cw);
                CP_ASYNC16(vb + (uint32_t)(r * FVSTR + vsw) * 4,
                           Vt + (size_t)r * QKV_N + cw);
            }
        }
        CP_COMMIT();
        CP_WAIT1();
        __syncthreads();

        const uint32_t* ks = Ks + (jt & 1) * KSTG_W;
        const uint32_t* vs = Vs + (jt & 1) * VSTG_W;

        float s4[8][4];
#pragma unroll
        for (int nf = 0; nf < 8; nf++)
#pragma unroll
            for (int r = 0; r < 4; r++) s4[nf][r] = 0.0f;

#pragma unroll
        for (int kc = 0; kc < 16; kc++) {
            const int kb = kc * 8;
#pragma unroll
            for (int nf = 0; nf < 8; nf++) {
                uint32_t b0 = ks[(nf * 8 + g) * FKSTR + kb +     t];
                uint32_t b1 = ks[(nf * 8 + g) * FKSTR + kb + 4 + t];
                MMA_TF32(s4[nf], qf[kc][0], qf[kc][1], qf[kc][2], qf[kc][3], b0, b1);
            }
        }

        const int colbase = jt * 64 + 2 * t;
#pragma unroll
        for (int nf = 0; nf < 8; nf++) {
            const int col = colbase + nf * 8;
            float v0 = s4[nf][0] * ATT_SCALE;
            float v1 = s4[nf][1] * ATT_SCALE;
            float v2 = s4[nf][2] * ATT_SCALE;
            float v3 = s4[nf][3] * ATT_SCALE;
            if (col     > row0)     v0 = -1e30f;
            if (col + 1 > row0)     v1 = -1e30f;
            if (col     > row0 + 8) v2 = -1e30f;
            if (col + 1 > row0 + 8) v3 = -1e30f;
            s4[nf][0] = v0; s4[nf][1] = v1; s4[nf][2] = v2; s4[nf][3] = v3;
        }

        float rm0 = -INFINITY, rm1 = -INFINITY;
#pragma unroll
        for (int nf = 0; nf < 8; nf++) {
            rm0 = fmaxf(rm0, fmaxf(s4[nf][0], s4[nf][1]));
            rm1 = fmaxf(rm1, fmaxf(s4[nf][2], s4[nf][3]));
        }
        rm0 = fmaxf(rm0, __shfl_xor_sync(0xffffffffu, rm0, 1));
        rm0 = fmaxf(rm0, __shfl_xor_sync(0xffffffffu, rm0, 2));
        rm1 = fmaxf(rm1, __shfl_xor_sync(0xffffffffu, rm1, 1));
        rm1 = fmaxf(rm1, __shfl_xor_sync(0xffffffffu, rm1, 2));

        const float mn0 = fmaxf(m0, rm0);
        const float mn1 = fmaxf(m1, rm1);
        const float cr_0 = __expf(m0 - mn0);
        const float cr_1 = __expf(m1 - mn1);

        float rs0 = 0.0f, rs1 = 0.0f;
#pragma unroll
        for (int nf = 0; nf < 8; nf++) {
            s4[nf][0] = __expf(s4[nf][0] - mn0);
            s4[nf][1] = __expf(s4[nf][1] - mn0);
            s4[nf][2] = __expf(s4[nf][2] - mn1);
            s4[nf][3] = __expf(s4[nf][3] - mn1);
            rs0 += s4[nf][0] + s4[nf][1];
            rs1 += s4[nf][2] + s4[nf][3];
        }
        rs0 += __shfl_xor_sync(0xffffffffu, rs0, 1);
        rs0 += __shfl_xor_sync(0xffffffffu, rs0, 2);
        rs1 += __shfl_xor_sync(0xffffffffu, rs1, 1);
        rs1 += __shfl_xor_sync(0xffffffffu, rs1, 2);

        l0 = l0 * cr_0 + rs0;  m0 = mn0;
        l1 = l1 * cr_1 + rs1;  m1 = mn1;

#pragma unroll
        for (int nf = 0; nf < 16; nf++) {
            o[nf][0] *= cr_0;  o[nf][1] *= cr_0;
            o[nf][2] *= cr_1;  o[nf][3] *= cr_1;
        }

#pragma unroll
        for (int nf = 0; nf < 8; nf++) {
            const int c = nf * 8 + 2 * t;
            *(uint2*)&Ps[(wr +     g) * FPSTR + c] =
                make_uint2(f2tf(s4[nf][0]), f2tf(s4[nf][1]));
            *(uint2*)&Ps[(wr + 8 + g) * FPSTR + c] =
                make_uint2(f2tf(s4[nf][2]), f2tf(s4[nf][3]));
        }
        __syncwarp();

#pragma unroll
        for (int kc = 0; kc < 8; kc++) {
            const int kb = kc * 8;
            uint32_t a0 = Ps[(wr +     g) * FPSTR + kb +     t];
            uint32_t a1 = Ps[(wr + 8 + g) * FPSTR + kb +     t];
            uint32_t a2 = Ps[(wr +     g) * FPSTR + kb + 4 + t];
            uint32_t a3 = Ps[(wr + 8 + g) * FPSTR + kb + 4 + t];
            const int sw = t << 3;
#pragma unroll
            for (int nf = 0; nf < 16; nf++) {
                uint32_t b0 = vs[(kb +     t) * FVSTR + ((nf * 8 + g) ^ sw)];
                uint32_t b1 = vs[(kb + 4 + t) * FVSTR + ((nf * 8 + g) ^ sw)];
                MMA_TF32(o[nf], a0, a1, a2, a3, b0, b1);
            }
        }
        __syncwarp();
    }

    const float il0 = 1.0f / l0;
    const float il1 = 1.0f / l1;
#pragma unroll
    for (int nf = 0; nf < 16; nf++) {
        const int col = h * HD + nf * 8 + 2 * t;
        float* p0 = g_attn + (size_t)row0 * H_DIM + col;
        p0[0] = __uint_as_float(f2tf(o[nf][0] * il0));
        p0[1] = __uint_as_float(f2tf(o[nf][1] * il0));
        float* p1 = g_attn + (size_t)(row0 + 8) * H_DIM + col;
        p1[0] = __uint_as_float(f2tf(o[nf][2] * il1));
        p1[1] = __uint_as_float(f2tf(o[nf][3] * il1));
    }
}

// ---------------------------------------------------------------------------
// Launch
// ---------------------------------------------------------------------------
extern "C" void kernel_launch(void* const* d_in, const int* in_sizes, int n_in,
                              void* d_out, int out_size)
{
    (void)in_sizes; (void)n_in; (void)out_size;
    const int*   positions = (const int*)d_in[0];
    const float* hidden    = (const float*)d_in[1];
    const float* w_qkv     = (const float*)d_in[2];
    const float* w_o       = (const float*)d_in[3];
    float*       out       = (float*)d_out;

    float *qkv_ptr = nullptr, *attn_ptr = nullptr;
    uint32_t *hidA = nullptr, *wqkvB = nullptr, *woB = nullptr, *attnA = nullptr;
    cudaGetSymbolAddress((void**)&qkv_ptr, g_qkv);
    cudaGetSymbolAddress((void**)&attn_ptr, g_attn);
    cudaGetSymbolAddress((void**)&hidA, g_hidA);
    cudaGetSymbolAddress((void**)&wqkvB, g_wqkvB);
    cudaGetSymbolAddress((void**)&woB, g_woB);
    cudaGetSymbolAddress((void**)&attnA, g_attnA);

    cudaFuncSetAttribute(gemm_tf32_nt,
                         cudaFuncAttributeMaxDynamicSharedMemorySize,
                         G_SMEM_BYTES);
    cudaFuncSetAttribute(flash_tc_kernel,
                         cudaFuncAttributeMaxDynamicSharedMemorySize,
                         FLASH_SMEM_BYTES);

    // 0) convert + pack operands
    pack_a_kernel<<<2048, 256>>>(hidden, (uint4*)hidA, H_DIM,
                                 S_LEN * H_DIM / 4);
    pack_b_kernel<<<2048, 256>>>(w_qkv, (uint2*)wqkvB, H_DIM,
                                 QKV_N * H_DIM / 2);
    pack_b_kernel<<<2048, 256>>>(w_o, (uint2*)woB, H_DIM,
                                 H_DIM * H_DIM / 2);

    // 1) QKV projection (tiles: 24 x 16)
    gemm_tf32_nt<<<dim3(QKV_N / 256, S_LEN / 128), 256, G_SMEM_BYTES>>>(
        H_DIM, QKV_N, hidA, wqkvB, qkv_ptr);

    // 2) RoPE (+ tf32 rounding of Q, K, V)
    rope_kernel<<<dim3(S_LEN, NH + 2 * NKV), 64>>>(positions);

    // 3) Flash attention
    flash_tc_kernel<<<dim3(S_LEN / 128, NH), 256, FLASH_SMEM_BYTES>>>();

    // 3b) pack attention output for O-proj
    pack_a_kernel<<<2048, 256>>>(attn_ptr, (uint4*)attnA, H_DIM,
                                 S_LEN * H_DIM / 4);

    // 4) Output projection (tiles: 16 x 16)
    gemm_tf32_nt<<<dim3(H_DIM / 256, S_LEN / 128), 256, G_SMEM_BYTES>>>(
        H_DIM, H_DIM, attnA, woB, out);
}

// round 12
// speedup vs baseline: 4.4566x; 1.0159x over previous
#include <cuda_runtime.h>
#include <math.h>
#include <stdint.h>

#define S_LEN 2048
#define H_DIM 4096
#define NH 32
#define NKV 8
#define HD 128
#define QKV_N 6144
#define ATT_SCALE 0.08838834764831843f

__device__ float g_qkv[S_LEN * QKV_N];
__device__ float g_attn[S_LEN * H_DIM];
// fragment-packed tf32 operands
__device__ uint32_t g_hidA [S_LEN * H_DIM];
__device__ uint32_t g_wqkvB[QKV_N * H_DIM];
__device__ uint32_t g_woB  [H_DIM * H_DIM];
__device__ uint32_t g_attnA[S_LEN * H_DIM];

__device__ __forceinline__ uint32_t f2tf(float x) {
    uint32_t r;
    asm("cvt.rna.tf32.f32 %0, %1;" : "=r"(r) : "f"(x));
    return r;
}

__device__ __forceinline__ uint32_t smem_u32(const void* p) {
    uint32_t a;
    asm("{ .reg .u64 t; cvta.to.shared.u64 t, %1; cvt.u32.u64 %0, t; }"
        : "=r"(a) : "l"(p));
    return a;
}

#define MMA_TF32(ACC, A0, A1, A2, A3, B0, B1)                                  \
    asm volatile(                                                              \
        "mma.sync.aligned.m16n8k8.row.col.f32.tf32.tf32.f32 "                  \
        "{%0,%1,%2,%3}, {%4,%5,%6,%7}, {%8,%9}, {%0,%1,%2,%3};\n"              \
        : "+f"(ACC[0]), "+f"(ACC[1]), "+f"(ACC[2]), "+f"(ACC[3])               \
        : "r"(A0), "r"(A1), "r"(A2), "r"(A3), "r"(B0), "r"(B1))

#define CP_ASYNC16(dst, src)                                                   \
    asm volatile("cp.async.cg.shared.global [%0], [%1], 16;"                   \
                 :: "r"(dst), "l"(src) : "memory")
#define CP_COMMIT()  asm volatile("cp.async.commit_group;" ::: "memory")
#define CP_WAIT1()   asm volatile("cp.async.wait_group 1;" ::: "memory")
#define CP_WAIT0()   asm volatile("cp.async.wait_group 0;" ::: "memory")

// ---------------------------------------------------------------------------
// A-pack: float [M,K] row-major -> fragment-packed tf32.
// ---------------------------------------------------------------------------
__global__ void pack_a_kernel(const float* __restrict__ in,
                              uint4* __restrict__ out, int K, int n4)
{
    const int k16n = K / 16;
    for (int idx = blockIdx.x * blockDim.x + threadIdx.x; idx < n4;
         idx += gridDim.x * blockDim.x) {
        const int slab = idx >> 9;
        const int rem  = idx & 511;
        const int sub  = rem >> 5;
        const int lane = rem & 31;
        const int mblk = slab / k16n;
        const int k16  = slab - mblk * k16n;
        const int row  = mblk * 128 + (sub >> 1) * 16 + (lane >> 2);
        const int k    = k16 * 16 + (sub & 1) * 8 + (lane & 3);
        const float* p = in + (size_t)row * K + k;
        out[idx] = make_uint4(f2tf(p[0]),
                              f2tf(p[(size_t)8 * K]),
                              f2tf(p[4]),
                              f2tf(p[(size_t)8 * K + 4]));
    }
}

// ---------------------------------------------------------------------------
// B-pack: float [N,K] row-major -> fragment-packed tf32.
// ---------------------------------------------------------------------------
__global__ void pack_b_kernel(const float* __restrict__ in,
                              uint2* __restrict__ out, int K, int n2)
{
    const int k16n = K / 16;
    for (int idx = blockIdx.x * blockDim.x + threadIdx.x; idx < n2;
         idx += gridDim.x * blockDim.x) {
        const int slab = idx >> 10;
        const int rem  = idx & 1023;
        const int sub  = rem >> 5;
        const int lane = rem & 31;
        const int nblk = slab / k16n;
        const int k16  = slab - nblk * k16n;
        const int row  = nblk * 128 + (sub >> 1) * 8 + (lane >> 2);
        const int k    = k16 * 16 + (sub & 1) * 8 + (lane & 3);
        const float* p = in + (size_t)row * K + k;
        out[idx] = make_uint2(f2tf(p[0]), f2tf(p[4]));
    }
}

// ---------------------------------------------------------------------------
// TF32 GEMM, 128x256 CTA tile, 64x64 warp tiles, cp.async 3-stage ring with
// BK=32 stages (2 k16-slabs per stage): ONE barrier+wait per 2 k16 steps.
// smem: 3 * (A 4096 w + B 8192 w) = 147456 bytes, 1 CTA/SM.
// ---------------------------------------------------------------------------
#define A_SLAB_W 2048
#define A_STG_W  4096                       // 2 slabs
#define B_STG_W  8192                       // 4 slabs (2 kt x 2 halves)
#define G_SMEM_BYTES (3 * (A_STG_W + B_STG_W) * 4)   // 147456

__global__ __launch_bounds__(256, 1)
void gemm_tf32_nt(int K, int Nfull,
                  const uint32_t* __restrict__ A,
                  const uint32_t* __restrict__ B,
                  float* __restrict__ C)
{
    extern __shared__ uint32_t gdyn[];
    uint32_t* As = gdyn;                     // [3][A_STG_W]
    uint32_t* Bs = gdyn + 3 * A_STG_W;       // [3][B_STG_W]
    const uint32_t as_base = smem_u32(As);
    const uint32_t bs_base = smem_u32(Bs);

    const int tid  = threadIdx.x;
    const int warp = tid >> 5;
    const int lane = tid & 31;
    const int g    = lane >> 2;
    const int t    = lane & 3;

    const int k16n = K / 16;
    const int nkp  = k16n / 2;               // BK=32 steps
    const uint32_t* Aslab  = A + (size_t)blockIdx.y * k16n * A_SLAB_W;
    const uint32_t* Bslab0 = B + (size_t)(2 * blockIdx.x)     * k16n * A_SLAB_W;
    const uint32_t* Bslab1 = B + (size_t)(2 * blockIdx.x + 1) * k16n * A_SLAB_W;

    const int m16b = (warp & 1) * 4;
    const int n8b  = (warp >> 1) * 8;
    const int half = n8b >> 4;
    const int n8l  = n8b & 15;

    float acc[4][8][4];
#pragma unroll
    for (int i = 0; i < 4; i++)
#pragma unroll
        for (int j = 0; j < 8; j++)
#pragma unroll
            for (int r = 0; r < 4; r++) acc[i][j][r] = 0.0f;

    // stage fill for BK=32 step kp: A slabs {2kp,2kp+1}, B slabs both halves.
    // B stage layout: [j=0: B0 | B1][j=1: B0 | B1], each slab 2048 w.
#define G_FILL(stage, kp)                                                      \
    do {                                                                       \
        const uint32_t ab = as_base + (stage) * A_STG_W * 4;                   \
        const uint32_t bb = bs_base + (stage) * B_STG_W * 4;                   \
        _Pragma("unroll")                                                      \
        for (int j = 0; j < 2; j++) {                                          \
            const uint32_t* Ap  = Aslab  + (size_t)(2 * (kp) + j) * A_SLAB_W;  \
            const uint32_t* Bp0 = Bslab0 + (size_t)(2 * (kp) + j) * A_SLAB_W;  \
            const uint32_t* Bp1 = Bslab1 + (size_t)(2 * (kp) + j) * A_SLAB_W;  \
            CP_ASYNC16(ab + j * 8192  + tid * 16,         Ap  + tid * 4);      \
            CP_ASYNC16(ab + j * 8192  + (tid + 256) * 16, Ap  + (tid + 256) * 4); \
            CP_ASYNC16(bb + j * 16384 + tid * 16,         Bp0 + tid * 4);      \
            CP_ASYNC16(bb + j * 16384 + (tid + 256) * 16, Bp0 + (tid + 256) * 4); \
            CP_ASYNC16(bb + j * 16384 + 8192 + tid * 16,  Bp1 + tid * 4);      \
            CP_ASYNC16(bb + j * 16384 + 8192 + (tid + 256) * 16,               \
                       Bp1 + (tid + 256) * 4);                                 \
        }                                                                      \
    } while (0)

    G_FILL(0, 0);
    CP_COMMIT();
    G_FILL(1, 1);
    CP_COMMIT();

    int stg = 0;
    for (int kp = 0; kp < nkp; kp++) {
        CP_WAIT1();
        __syncthreads();

        if (kp + 2 < nkp) {
            const int s2 = (kp + 2) % 3;
            G_FILL(s2, kp + 2);
        }
        CP_COMMIT();

#pragma unroll
        for (int j = 0; j < 2; j++) {
            const uint32_t* as = As + stg * A_STG_W + j * A_SLAB_W;
            const uint32_t* bs = Bs + stg * B_STG_W + j * 2 * A_SLAB_W
                                 + half * A_SLAB_W;
#pragma unroll
            for (int ks = 0; ks < 2; ks++) {
                uint4 aw[4];
                uint2 bw[8];
#pragma unroll
                for (int am = 0; am < 4; am++)
                    aw[am] = *(const uint4*)&as[((m16b + am) * 2 + ks) * 128 + lane * 4];
#pragma unroll
                for (int an = 0; an < 8; an++)
                    bw[an] = *(const uint2*)&bs[((n8l + an) * 2 + ks) * 64 + lane * 2];
#pragma unroll
                for (int am = 0; am < 4; am++)
#pragma unroll
                    for (int an = 0; an < 8; an++)
                        MMA_TF32(acc[am][an], aw[am].x, aw[am].y, aw[am].z, aw[am].w,
                                 bw[an].x, bw[an].y);
            }
        }
        stg = (stg + 1) % 3;
    }
    CP_WAIT0();

    const int bm = blockIdx.y * 128;
    const int bn = blockIdx.x * 256;
#pragma unroll
    for (int am = 0; am < 4; am++) {
        const int row0 = bm + (m16b + am) * 16 + g;
#pragma unroll
        for (int an = 0; an < 8; an++) {
            const int col = bn + (n8b + an) * 8 + t * 2;
            float* c0p = C + (size_t)row0 * Nfull + col;
            c0p[0] = acc[am][an][0];
            c0p[1] = acc[am][an][1];
            float* c2p = c0p + (size_t)8 * Nfull;
            c2p[0] = acc[am][an][2];
            c2p[1] = acc[am][an][3];
        }
    }
#undef G_FILL
}

// ---------------------------------------------------------------------------
// RoPE + tf32 pre-round (heads 0..39 rotate+round, 40..47 round only)
// ---------------------------------------------------------------------------
__global__ void rope_kernel(const int* __restrict__ positions)
{
    const int s = blockIdx.x;
    const int h = blockIdx.y;          // 0..47
    const int d = threadIdx.x;         // 0..63

    float* base = g_qkv + (size_t)s * QKV_N + h * HD;
    const float x1 = base[d];
    const float x2 = base[d + 64];

    if (h < NH + NKV) {
        const float pos = (float)positions[s];
        const float inv_freq = powf(1000000.0f, -(float)d * (1.0f / 64.0f));
        const float ang = pos * inv_freq;
        float sn, cs;
        sincosf(ang, &sn, &cs);
        base[d]      = __uint_as_float(f2tf(x1 * cs - x2 * sn));
        base[d + 64] = __uint_as_float(f2tf(x2 * cs + x1 * sn));
    } else {
        base[d]      = __uint_as_float(f2tf(x1));
        base[d + 64] = __uint_as_float(f2tf(x2));
    }
}

// ---------------------------------------------------------------------------
// Flash attention (unchanged from round 10/11)
// ---------------------------------------------------------------------------
#define FKSTR 132
#define FVSTR 128
#define FPSTR 68
#define KSTG_W (64 * FKSTR)
#define VSTG_W (64 * FVSTR)
#define FLASH_SMEM_WORDS (2 * KSTG_W + 2 * VSTG_W + 128 * FPSTR)
#define FLASH_SMEM_BYTES (FLASH_SMEM_WORDS * 4)   // 167936

__global__ __launch_bounds__(256)
void flash_tc_kernel()
{
    extern __shared__ uint32_t fsm[];
    uint32_t* Ks = fsm;
    uint32_t* Vs = fsm + 2 * KSTG_W;
    uint32_t* Ps = fsm + 2 * KSTG_W + 2 * VSTG_W;
    const uint32_t ks_base = smem_u32(Ks);
    const uint32_t vs_base = smem_u32(Vs);

    const int tid  = threadIdx.x;
    const int warp = tid >> 5;
    const int lane = tid & 31;
    const int g    = lane >> 2;
    const int t    = lane & 3;
    const int qt   = gridDim.x - 1 - blockIdx.x;
    const int h    = blockIdx.y;
    const int kh   = h >> 2;
    const int wr   = warp * 16;

    const float* Qg = g_qkv + (size_t)(qt * 128) * QKV_N + h * HD;
    const float* Kg = g_qkv + NH * HD + kh * HD;
    const float* Vg = g_qkv + (NH + NKV) * HD + kh * HD;

    const int cw  = lane * 4;
    const int vsw = cw ^ ((warp & 3) << 3);

    uint32_t qf[16][4];
    {
        const float* q0 = Qg + (size_t)(wr +     g) * QKV_N;
        const float* q1 = Qg + (size_t)(wr + 8 + g) * QKV_N;
#pragma unroll
        for (int kc = 0; kc < 16; kc++) {
            const int c = kc * 8 + t;
            qf[kc][0] = __float_as_uint(q0[c]);
            qf[kc][1] = __float_as_uint(q1[c]);
            qf[kc][2] = __float_as_uint(q0[c + 4]);
            qf[kc][3] = __float_as_uint(q1[c + 4]);
        }
    }

    float m0 = -INFINITY, m1 = -INFINITY, l0 = 0.0f, l1 = 0.0f;
    float o[16][4];
#pragma unroll
    for (int nf = 0; nf < 16; nf++)
#pragma unroll
        for (int r = 0; r < 4; r++) o[nf][r] = 0.0f;

    const int row0 = qt * 128 + wr + g;
    const int n_ktiles = 2 * qt + 2;

    {
#pragma unroll
        for (int i = 0; i < 8; i++) {
            const int r = warp + 8 * i;
            CP_ASYNC16(ks_base + (uint32_t)(r * FKSTR + cw) * 4,
                       Kg + (size_t)r * QKV_N + cw);
            CP_ASYNC16(vs_base + (uint32_t)(r * FVSTR + vsw) * 4,
                       Vg + (size_t)r * QKV_N + cw);
        }
        CP_COMMIT();
    }

    for (int jt = 0; jt < n_ktiles; jt++) {
        __syncthreads();
        if (jt + 1 < n_ktiles) {
            const int s = (jt + 1) & 1;
            const float* Kt = Kg + (size_t)((jt + 1) * 64) * QKV_N;
            const float* Vt = Vg + (size_t)((jt + 1) * 64) * QKV_N;
            const uint32_t kb = ks_base + s * KSTG_W * 4;
            const uint32_t vb = vs_base + s * VSTG_W * 4;
#pragma unroll
            for (int i = 0; i < 8; i++) {
                const int r = warp + 8 * i;
                CP_ASYNC16(kb + (uint32_t)(r * FKSTR + cw) * 4,
                           Kt + (size_t)r * QKV_N + cw);
                CP_ASYNC16(vb + (uint32_t)(r * FVSTR + vsw) * 4,
                           Vt + (size_t)r * QKV_N + cw);
            }
        }
        CP_COMMIT();
        CP_WAIT1();
        __syncthreads();

        const uint32_t* ks = Ks + (jt & 1) * KSTG_W;
        const uint32_t* vs = Vs + (jt & 1) * VSTG_W;

        float s4[8][4];
#pragma unroll
        for (int nf = 0; nf < 8; nf++)
#pragma unroll
            for (int r = 0; r < 4; r++) s4[nf][r] = 0.0f;

#pragma unroll
        for (int kc = 0; kc < 16; kc++) {
            const int kb = kc * 8;
#pragma unroll
            for (int nf = 0; nf < 8; nf++) {
                uint32_t b0 = ks[(nf * 8 + g) * FKSTR + kb +     t];
                uint32_t b1 = ks[(nf * 8 + g) * FKSTR + kb + 4 + t];
                MMA_TF32(s4[nf], qf[kc][0], qf[kc][1], qf[kc][2], qf[kc][3], b0, b1);
            }
        }

        const int colbase = jt * 64 + 2 * t;
#pragma unroll
        for (int nf = 0; nf < 8; nf++) {
            const int col = colbase + nf * 8;
            float v0 = s4[nf][0] * ATT_SCALE;
            float v1 = s4[nf][1] * ATT_SCALE;
            float v2 = s4[nf][2] * ATT_SCALE;
            float v3 = s4[nf][3] * ATT_SCALE;
            if (col     > row0)     v0 = -1e30f;
            if (col + 1 > row0)     v1 = -1e30f;
            if (col     > row0 + 8) v2 = -1e30f;
            if (col + 1 > row0 + 8) v3 = -1e30f;
            s4[nf][0] = v0; s4[nf][1] = v1; s4[nf][2] = v2; s4[nf][3] = v3;
        }

        float rm0 = -INFINITY, rm1 = -INFINITY;
#pragma unroll
        for (int nf = 0; nf < 8; nf++) {
            rm0 = fmaxf(rm0, fmaxf(s4[nf][0], s4[nf][1]));
            rm1 = fmaxf(rm1, fmaxf(s4[nf][2], s4[nf][3]));
        }
        rm0 = fmaxf(rm0, __shfl_xor_sync(0xffffffffu, rm0, 1));
        rm0 = fmaxf(rm0, __shfl_xor_sync(0xffffffffu, rm0, 2));
        rm1 = fmaxf(rm1, __shfl_xor_sync(0xffffffffu, rm1, 1));
        rm1 = fmaxf(rm1, __shfl_xor_sync(0xffffffffu, rm1, 2));

        const float mn0 = fmaxf(m0, rm0);
        const float mn1 = fmaxf(m1, rm1);
        const float cr_0 = __expf(m0 - mn0);
        const float cr_1 = __expf(m1 - mn1);

        float rs0 = 0.0f, rs1 = 0.0f;
#pragma unroll
        for (int nf = 0; nf < 8; nf++) {
            s4[nf][0] = __expf(s4[nf][0] - mn0);
            s4[nf][1] = __expf(s4[nf][1] - mn0);
            s4[nf][2] = __expf(s4[nf][2] - mn1);
            s4[nf][3] = __expf(s4[nf][3] - mn1);
            rs0 += s4[nf][0] + s4[nf][1];
            rs1 += s4[nf][2] + s4[nf][3];
        }
        rs0 += __shfl_xor_sync(0xffffffffu, rs0, 1);
        rs0 += __shfl_xor_sync(0xffffffffu, rs0, 2);
        rs1 += __shfl_xor_sync(0xffffffffu, rs1, 1);
        rs1 += __shfl_xor_sync(0xffffffffu, rs1, 2);

        l0 = l0 * cr_0 + rs0;  m0 = mn0;
        l1 = l1 * cr_1 + rs1;  m1 = mn1;

#pragma unroll
        for (int nf = 0; nf < 16; nf++) {
            o[nf][0] *= cr_0;  o[nf][1] *= cr_0;
            o[nf][2] *= cr_1;  o[nf][3] *= cr_1;
        }

#pragma unroll
        for (int nf = 0; nf < 8; nf++) {
            const int c = nf * 8 + 2 * t;
            *(uint2*)&Ps[(wr +     g) * FPSTR + c] =
                make_uint2(f2tf(s4[nf][0]), f2tf(s4[nf][1]));
            *(uint2*)&Ps[(wr + 8 + g) * FPSTR + c] =
                make_uint2(f2tf(s4[nf][2]), f2tf(s4[nf][3]));
        }
        __syncwarp();

#pragma unroll
        for (int kc = 0; kc < 8; kc++) {
            const int kb = kc * 8;
            uint32_t a0 = Ps[(wr +     g) * FPSTR + kb +     t];
            uint32_t a1 = Ps[(wr + 8 + g) * FPSTR + kb +     t];
            uint32_t a2 = Ps[(wr +     g) * FPSTR + kb + 4 + t];
            uint32_t a3 = Ps[(wr + 8 + g) * FPSTR + kb + 4 + t];
            const int sw = t << 3;
#pragma unroll
            for (int nf = 0; nf < 16; nf++) {
                uint32_t b0 = vs[(kb +     t) * FVSTR + ((nf * 8 + g) ^ sw)];
                uint32_t b1 = vs[(kb + 4 + t) * FVSTR + ((nf * 8 + g) ^ sw)];
                MMA_TF32(o[nf], a0, a1, a2, a3, b0, b1);
            }
        }
        __syncwarp();
    }

    const float il0 = 1.0f / l0;
    const float il1 = 1.0f / l1;
#pragma unroll
    for (int nf = 0; nf < 16; nf++) {
        const int col = h * HD + nf * 8 + 2 * t;
        float* p0 = g_attn + (size_t)row0 * H_DIM + col;
        p0[0] = __uint_as_float(f2tf(o[nf][0] * il0));
        p0[1] = __uint_as_float(f2tf(o[nf][1] * il0));
        float* p1 = g_attn + (size_t)(row0 + 8) * H_DIM + col;
        p1[0] = __uint_as_float(f2tf(o[nf][2] * il1));
        p1[1] = __uint_as_float(f2tf(o[nf][3] * il1));
    }
}

// ---------------------------------------------------------------------------
// Launch
// ---------------------------------------------------------------------------
extern "C" void kernel_launch(void* const* d_in, const int* in_sizes, int n_in,
                              void* d_out, int out_size)
{
    (void)in_sizes; (void)n_in; (void)out_size;
    const int*   positions = (const int*)d_in[0];
    const float* hidden    = (const float*)d_in[1];
    const float* w_qkv     = (const float*)d_in[2];
    const float* w_o       = (const float*)d_in[3];
    float*       out       = (float*)d_out;

    float *qkv_ptr = nullptr, *attn_ptr = nullptr;
    uint32_t *hidA = nullptr, *wqkvB = nullptr, *woB = nullptr, *attnA = nullptr;
    cudaGetSymbolAddress((void**)&qkv_ptr, g_qkv);
    cudaGetSymbolAddress((void**)&attn_ptr, g_attn);
    cudaGetSymbolAddress((void**)&hidA, g_hidA);
    cudaGetSymbolAddress((void**)&wqkvB, g_wqkvB);
    cudaGetSymbolAddress((void**)&woB, g_woB);
    cudaGetSymbolAddress((void**)&attnA, g_attnA);

    cudaFuncSetAttribute(gemm_tf32_nt,
                         cudaFuncAttributeMaxDynamicSharedMemorySize,
                         G_SMEM_BYTES);
    cudaFuncSetAttribute(flash_tc_kernel,
                         cudaFuncAttributeMaxDynamicSharedMemorySize,
                         FLASH_SMEM_BYTES);

    // 0) convert + pack operands
    pack_a_kernel<<<2048, 256>>>(hidden, (uint4*)hidA, H_DIM,
                                 S_LEN * H_DIM / 4);
    pack_b_kernel<<<2048, 256>>>(w_qkv, (uint2*)wqkvB, H_DIM,
                                 QKV_N * H_DIM / 2);
    pack_b_kernel<<<2048, 256>>>(w_o, (uint2*)woB, H_DIM,
                                 H_DIM * H_DIM / 2);

    // 1) QKV projection
    gemm_tf32_nt<<<dim3(QKV_N / 256, S_LEN / 128), 256, G_SMEM_BYTES>>>(
        H_DIM, QKV_N, hidA, wqkvB, qkv_ptr);

    // 2) RoPE (+ tf32 rounding of Q, K, V)
    rope_kernel<<<dim3(S_LEN, NH + 2 * NKV), 64>>>(positions);

    // 3) Flash attention
    flash_tc_kernel<<<dim3(S_LEN / 128, NH), 256, FLASH_SMEM_BYTES>>>();

    // 3b) pack attention output for O-proj
    pack_a_kernel<<<2048, 256>>>(attn_ptr, (uint4*)attnA, H_DIM,
                                 S_LEN * H_DIM / 4);

    // 4) Output projection
    gemm_tf32_nt<<<dim3(H_DIM / 256, S_LEN / 128), 256, G_SMEM_BYTES>>>(
        H_DIM, H_DIM, attnA, woB, out);
}

// round 13
// speedup vs baseline: 4.6374x; 1.0406x over previous
#include <cuda_runtime.h>
#include <math.h>
#include <stdint.h>

#define S_LEN 2048
#define H_DIM 4096
#define NH 32
#define NKV 8
#define HD 128
#define QKV_N 6144
#define ATT_SCALE 0.08838834764831843f

__device__ float g_qkv[S_LEN * QKV_N];
__device__ float g_attn[S_LEN * H_DIM];
// fragment-packed tf32 operands
__device__ uint32_t g_hidA [S_LEN * H_DIM];
__device__ uint32_t g_wqkvB[QKV_N * H_DIM];
__device__ uint32_t g_woB  [H_DIM * H_DIM];
__device__ uint32_t g_attnA[S_LEN * H_DIM];

__device__ __forceinline__ uint32_t f2tf(float x) {
    uint32_t r;
    asm("cvt.rna.tf32.f32 %0, %1;" : "=r"(r) : "f"(x));
    return r;
}

__device__ __forceinline__ uint32_t smem_u32(const void* p) {
    uint32_t a;
    asm("{ .reg .u64 t; cvta.to.shared.u64 t, %1; cvt.u32.u64 %0, t; }"
        : "=r"(a) : "l"(p));
    return a;
}

#define MMA_TF32(ACC, A0, A1, A2, A3, B0, B1)                                  \
    asm volatile(                                                              \
        "mma.sync.aligned.m16n8k8.row.col.f32.tf32.tf32.f32 "                  \
        "{%0,%1,%2,%3}, {%4,%5,%6,%7}, {%8,%9}, {%0,%1,%2,%3};\n"              \
        : "+f"(ACC[0]), "+f"(ACC[1]), "+f"(ACC[2]), "+f"(ACC[3])               \
        : "r"(A0), "r"(A1), "r"(A2), "r"(A3), "r"(B0), "r"(B1))

#define CP_ASYNC16(dst, src)                                                   \
    asm volatile("cp.async.cg.shared.global [%0], [%1], 16;"                   \
                 :: "r"(dst), "l"(src) : "memory")
#define CP_COMMIT()  asm volatile("cp.async.commit_group;" ::: "memory")
#define CP_WAIT1()   asm volatile("cp.async.wait_group 1;" ::: "memory")
#define CP_WAIT0()   asm volatile("cp.async.wait_group 0;" ::: "memory")

// ---------------------------------------------------------------------------
// A-pack: float [M,K] row-major -> fragment-packed tf32.
// ---------------------------------------------------------------------------
__global__ void pack_a_kernel(const float* __restrict__ in,
                              uint4* __restrict__ out, int K, int n4)
{
    const int k16n = K / 16;
    for (int idx = blockIdx.x * blockDim.x + threadIdx.x; idx < n4;
         idx += gridDim.x * blockDim.x) {
        const int slab = idx >> 9;
        const int rem  = idx & 511;
        const int sub  = rem >> 5;
        const int lane = rem & 31;
        const int mblk = slab / k16n;
        const int k16  = slab - mblk * k16n;
        const int row  = mblk * 128 + (sub >> 1) * 16 + (lane >> 2);
        const int k    = k16 * 16 + (sub & 1) * 8 + (lane & 3);
        const float* p = in + (size_t)row * K + k;
        out[idx] = make_uint4(f2tf(p[0]),
                              f2tf(p[(size_t)8 * K]),
                              f2tf(p[4]),
                              f2tf(p[(size_t)8 * K + 4]));
    }
}

// ---------------------------------------------------------------------------
// B-pack: float [N,K] row-major -> fragment-packed tf32.
// ---------------------------------------------------------------------------
__global__ void pack_b_kernel(const float* __restrict__ in,
                              uint2* __restrict__ out, int K, int n2)
{
    const int k16n = K / 16;
    for (int idx = blockIdx.x * blockDim.x + threadIdx.x; idx < n2;
         idx += gridDim.x * blockDim.x) {
        const int slab = idx >> 10;
        const int rem  = idx & 1023;
        const int sub  = rem >> 5;
        const int lane = rem & 31;
        const int nblk = slab / k16n;
        const int k16  = slab - nblk * k16n;
        const int row  = nblk * 128 + (sub >> 1) * 8 + (lane >> 2);
        const int k    = k16 * 16 + (sub & 1) * 8 + (lane & 3);
        const float* p = in + (size_t)row * K + k;
        out[idx] = make_uint2(f2tf(p[0]), f2tf(p[4]));
    }
}

// ---------------------------------------------------------------------------
// TF32 GEMM, 128x128 CTA tile, 128 THREADS (4 warps, 64x64 warp tiles),
// cp.async 3-stage ring with BK=32 stages. 98 KB smem -> 2 CTAs/SM with
// INDEPENDENT barriers: the two CTAs drift out of phase and fill each
// other's LDS-latency bubbles on the tensor pipe.
// ---------------------------------------------------------------------------
#define A_SLAB_W 2048
#define A_STG_W  4096                       // 2 k16-slabs (BK=32)
#define B_STG_W  4096
#define G_SMEM_BYTES (3 * (A_STG_W + B_STG_W) * 4)   // 98304

__global__ __launch_bounds__(128, 2)
void gemm_tf32_nt(int K, int Nfull,
                  const uint32_t* __restrict__ A,
                  const uint32_t* __restrict__ B,
                  float* __restrict__ C)
{
    extern __shared__ uint32_t gdyn[];
    uint32_t* As = gdyn;                     // [3][A_STG_W]
    uint32_t* Bs = gdyn + 3 * A_STG_W;       // [3][B_STG_W]
    const uint32_t as_base = smem_u32(As);
    const uint32_t bs_base = smem_u32(Bs);

    const int tid  = threadIdx.x;
    const int warp = tid >> 5;
    const int lane = tid & 31;
    const int g    = lane >> 2;
    const int t    = lane & 3;

    const int k16n = K / 16;
    const int nkp  = k16n / 2;               // BK=32 steps
    const uint32_t* Aslab = A + (size_t)blockIdx.y * k16n * A_SLAB_W;
    const uint32_t* Bslab = B + (size_t)blockIdx.x * k16n * A_SLAB_W;

    const int m16b = (warp & 1) * 4;         // 0 or 4
    const int n8b  = (warp >> 1) * 8;        // 0 or 8

    float acc[4][8][4];
#pragma unroll
    for (int i = 0; i < 4; i++)
#pragma unroll
        for (int j = 0; j < 8; j++)
#pragma unroll
            for (int r = 0; r < 4; r++) acc[i][j][r] = 0.0f;

    // stage fill for BK=32 step kp: A+B slabs {2kp, 2kp+1}; 4 chunks each
    // per thread per slab (512 chunks / 128 threads).
#define G_FILL(stage, kp)                                                      \
    do {                                                                       \
        const uint32_t ab = as_base + (stage) * A_STG_W * 4;                   \
        const uint32_t bb = bs_base + (stage) * B_STG_W * 4;                   \
        _Pragma("unroll")                                                      \
        for (int j = 0; j < 2; j++) {                                          \
            const uint32_t* Ap = Aslab + (size_t)(2 * (kp) + j) * A_SLAB_W;    \
            const uint32_t* Bp = Bslab + (size_t)(2 * (kp) + j) * A_SLAB_W;    \
            _Pragma("unroll")                                                  \
            for (int i = 0; i < 4; i++) {                                      \
                const int c = tid + i * 128;                                   \
                CP_ASYNC16(ab + j * 8192 + c * 16, Ap + c * 4);                \
                CP_ASYNC16(bb + j * 8192 + c * 16, Bp + c * 4);                \
            }                                                                  \
        }                                                                      \
    } while (0)

    G_FILL(0, 0);
    CP_COMMIT();
    G_FILL(1, 1);
    CP_COMMIT();

    int stg = 0;
    for (int kp = 0; kp < nkp; kp++) {
        CP_WAIT1();
        __syncthreads();

        if (kp + 2 < nkp) {
            const int s2 = (kp + 2) % 3;
            G_FILL(s2, kp + 2);
        }
        CP_COMMIT();

#pragma unroll
        for (int j = 0; j < 2; j++) {
            const uint32_t* as = As + stg * A_STG_W + j * A_SLAB_W;
            const uint32_t* bs = Bs + stg * B_STG_W + j * A_SLAB_W;
#pragma unroll
            for (int ks = 0; ks < 2; ks++) {
                uint4 aw[4];
                uint2 bw[8];
#pragma unroll
                for (int am = 0; am < 4; am++)
                    aw[am] = *(const uint4*)&as[((m16b + am) * 2 + ks) * 128 + lane * 4];
#pragma unroll
                for (int an = 0; an < 8; an++)
                    bw[an] = *(const uint2*)&bs[((n8b + an) * 2 + ks) * 64 + lane * 2];
#pragma unroll
                for (int am = 0; am < 4; am++)
#pragma unroll
                    for (int an = 0; an < 8; an++)
                        MMA_TF32(acc[am][an], aw[am].x, aw[am].y, aw[am].z, aw[am].w,
                                 bw[an].x, bw[an].y);
            }
        }
        stg = (stg + 1) % 3;
    }
    CP_WAIT0();

    const int bm = blockIdx.y * 128;
    const int bn = blockIdx.x * 128;
#pragma unroll
    for (int am = 0; am < 4; am++) {
        const int row0 = bm + (m16b + am) * 16 + g;
#pragma unroll
        for (int an = 0; an < 8; an++) {
            const int col = bn + (n8b + an) * 8 + t * 2;
            float* c0p = C + (size_t)row0 * Nfull + col;
            c0p[0] = acc[am][an][0];
            c0p[1] = acc[am][an][1];
            float* c2p = c0p + (size_t)8 * Nfull;
            c2p[0] = acc[am][an][2];
            c2p[1] = acc[am][an][3];
        }
    }
#undef G_FILL
}

// ---------------------------------------------------------------------------
// RoPE + tf32 pre-round (heads 0..39 rotate+round, 40..47 round only)
// ---------------------------------------------------------------------------
__global__ void rope_kernel(const int* __restrict__ positions)
{
    const int s = blockIdx.x;
    const int h = blockIdx.y;          // 0..47
    const int d = threadIdx.x;         // 0..63

    float* base = g_qkv + (size_t)s * QKV_N + h * HD;
    const float x1 = base[d];
    const float x2 = base[d + 64];

    if (h < NH + NKV) {
        const float pos = (float)positions[s];
        const float inv_freq = powf(1000000.0f, -(float)d * (1.0f / 64.0f));
        const float ang = pos * inv_freq;
        float sn, cs;
        sincosf(ang, &sn, &cs);
        base[d]      = __uint_as_float(f2tf(x1 * cs - x2 * sn));
        base[d + 64] = __uint_as_float(f2tf(x2 * cs + x1 * sn));
    } else {
        base[d]      = __uint_as_float(f2tf(x1));
        base[d + 64] = __uint_as_float(f2tf(x2));
    }
}

// ---------------------------------------------------------------------------
// Flash attention (unchanged from round 12)
// ---------------------------------------------------------------------------
#define FKSTR 132
#define FVSTR 128
#define FPSTR 68
#define KSTG_W (64 * FKSTR)
#define VSTG_W (64 * FVSTR)
#define FLASH_SMEM_WORDS (2 * KSTG_W + 2 * VSTG_W + 128 * FPSTR)
#define FLASH_SMEM_BYTES (FLASH_SMEM_WORDS * 4)   // 167936

__global__ __launch_bounds__(256)
void flash_tc_kernel()
{
    extern __shared__ uint32_t fsm[];
    uint32_t* Ks = fsm;
    uint32_t* Vs = fsm + 2 * KSTG_W;
    uint32_t* Ps = fsm + 2 * KSTG_W + 2 * VSTG_W;
    const uint32_t ks_base = smem_u32(Ks);
    const uint32_t vs_base = smem_u32(Vs);

    const int tid  = threadIdx.x;
    const int warp = tid >> 5;
    const int lane = tid & 31;
    const int g    = lane >> 2;
    const int t    = lane & 3;
    const int qt   = gridDim.x - 1 - blockIdx.x;
    const int h    = blockIdx.y;
    const int kh   = h >> 2;
    const int wr   = warp * 16;

    const float* Qg = g_qkv + (size_t)(qt * 128) * QKV_N + h * HD;
    const float* Kg = g_qkv + NH * HD + kh * HD;
    const float* Vg = g_qkv + (NH + NKV) * HD + kh * HD;

    const int cw  = lane * 4;
    const int vsw = cw ^ ((warp & 3) << 3);

    uint32_t qf[16][4];
    {
        const float* q0 = Qg + (size_t)(wr +     g) * QKV_N;
        const float* q1 = Qg + (size_t)(wr + 8 + g) * QKV_N;
#pragma unroll
        for (int kc = 0; kc < 16; kc++) {
            const int c = kc * 8 + t;
            qf[kc][0] = __float_as_uint(q0[c]);
            qf[kc][1] = __float_as_uint(q1[c]);
            qf[kc][2] = __float_as_uint(q0[c + 4]);
            qf[kc][3] = __float_as_uint(q1[c + 4]);
        }
    }

    float m0 = -INFINITY, m1 = -INFINITY, l0 = 0.0f, l1 = 0.0f;
    float o[16][4];
#pragma unroll
    for (int nf = 0; nf < 16; nf++)
#pragma unroll
        for (int r = 0; r < 4; r++) o[nf][r] = 0.0f;

    const int row0 = qt * 128 + wr + g;
    const int n_ktiles = 2 * qt + 2;

    {
#pragma unroll
        for (int i = 0; i < 8; i++) {
            const int r = warp + 8 * i;
            CP_ASYNC16(ks_base + (uint32_t)(r * FKSTR + cw) * 4,
                       Kg + (size_t)r * QKV_N + cw);
            CP_ASYNC16(vs_base + (uint32_t)(r * FVSTR + vsw) * 4,
                       Vg + (size_t)r * QKV_N + cw);
        }
        CP_COMMIT();
    }

    for (int jt = 0; jt < n_ktiles; jt++) {
        __syncthreads();
        if (jt + 1 < n_ktiles) {
            const int s = (jt + 1) & 1;
            const float* Kt = Kg + (size_t)((jt + 1) * 64) * QKV_N;
            const float* Vt = Vg + (size_t)((jt + 1) * 64) * QKV_N;
            const uint32_t kb = ks_base + s * KSTG_W * 4;
            const uint32_t vb = vs_base + s * VSTG_W * 4;
#pragma unroll
            for (int i = 0; i < 8; i++) {
                const int r = warp + 8 * i;
                CP_ASYNC16(kb + (uint32_t)(r * FKSTR + cw) * 4,
                           Kt + (size_t)r * QKV_N + cw);
                CP_ASYNC16(vb + (uint32_t)(r * FVSTR + vsw) * 4,
                           Vt + (size_t)r * QKV_N + cw);
            }
        }
        CP_COMMIT();
        CP_WAIT1();
        __syncthreads();

        const uint32_t* ks = Ks + (jt & 1) * KSTG_W;
        const uint32_t* vs = Vs + (jt & 1) * VSTG_W;

        float s4[8][4];
#pragma unroll
        for (int nf = 0; nf < 8; nf++)
#pragma unroll
            for (int r = 0; r < 4; r++) s4[nf][r] = 0.0f;

#pragma unroll
        for (int kc = 0; kc < 16; kc++) {
            const int kb = kc * 8;
#pragma unroll
            for (int nf = 0; nf < 8; nf++) {
                uint32_t b0 = ks[(nf * 8 + g) * FKSTR + kb +     t];
                uint32_t b1 = ks[(nf * 8 + g) * FKSTR + kb + 4 + t];
                MMA_TF32(s4[nf], qf[kc][0], qf[kc][1], qf[kc][2], qf[kc][3], b0, b1);
            }
        }

        const int colbase = jt * 64 + 2 * t;
#pragma unroll
        for (int nf = 0; nf < 8; nf++) {
            const int col = colbase + nf * 8;
            float v0 = s4[nf][0] * ATT_SCALE;
            float v1 = s4[nf][1] * ATT_SCALE;
            float v2 = s4[nf][2] * ATT_SCALE;
            float v3 = s4[nf][3] * ATT_SCALE;
            if (col     > row0)     v0 = -1e30f;
            if (col + 1 > row0)     v1 = -1e30f;
            if (col     > row0 + 8) v2 = -1e30f;
            if (col + 1 > row0 + 8) v3 = -1e30f;
            s4[nf][0] = v0; s4[nf][1] = v1; s4[nf][2] = v2; s4[nf][3] = v3;
        }

        float rm0 = -INFINITY, rm1 = -INFINITY;
#pragma unroll
        for (int nf = 0; nf < 8; nf++) {
            rm0 = fmaxf(rm0, fmaxf(s4[nf][0], s4[nf][1]));
            rm1 = fmaxf(rm1, fmaxf(s4[nf][2], s4[nf][3]));
        }
        rm0 = fmaxf(rm0, __shfl_xor_sync(0xffffffffu, rm0, 1));
        rm0 = fmaxf(rm0, __shfl_xor_sync(0xffffffffu, rm0, 2));
        rm1 = fmaxf(rm1, __shfl_xor_sync(0xffffffffu, rm1, 1));
        rm1 = fmaxf(rm1, __shfl_xor_sync(0xffffffffu, rm1, 2));

        const float mn0 = fmaxf(m0, rm0);
        const float mn1 = fmaxf(m1, rm1);
        const float cr_0 = __expf(m0 - mn0);
        const float cr_1 = __expf(m1 - mn1);

        float rs0 = 0.0f, rs1 = 0.0f;
#pragma unroll
        for (int nf = 0; nf < 8; nf++) {
            s4[nf][0] = __expf(s4[nf][0] - mn0);
            s4[nf][1] = __expf(s4[nf][1] - mn0);
            s4[nf][2] = __expf(s4[nf][2] - mn1);
            s4[nf][3] = __expf(s4[nf][3] - mn1);
            rs0 += s4[nf][0] + s4[nf][1];
            rs1 += s4[nf][2] + s4[nf][3];
        }
        rs0 += __shfl_xor_sync(0xffffffffu, rs0, 1);
        rs0 += __shfl_xor_sync(0xffffffffu, rs0, 2);
        rs1 += __shfl_xor_sync(0xffffffffu, rs1, 1);
        rs1 += __shfl_xor_sync(0xffffffffu, rs1, 2);

        l0 = l0 * cr_0 + rs0;  m0 = mn0;
        l1 = l1 * cr_1 + rs1;  m1 = mn1;

#pragma unroll
        for (int nf = 0; nf < 16; nf++) {
            o[nf][0] *= cr_0;  o[nf][1] *= cr_0;
            o[nf][2] *= cr_1;  o[nf][3] *= cr_1;
        }

#pragma unroll
        for (int nf = 0; nf < 8; nf++) {
            const int c = nf * 8 + 2 * t;
            *(uint2*)&Ps[(wr +     g) * FPSTR + c] =
                make_uint2(f2tf(s4[nf][0]), f2tf(s4[nf][1]));
            *(uint2*)&Ps[(wr + 8 + g) * FPSTR + c] =
                make_uint2(f2tf(s4[nf][2]), f2tf(s4[nf][3]));
        }
        __syncwarp();

#pragma unroll
        for (int kc = 0; kc < 8; kc++) {
            const int kb = kc * 8;
            uint32_t a0 = Ps[(wr +     g) * FPSTR + kb +     t];
            uint32_t a1 = Ps[(wr + 8 + g) * FPSTR + kb +     t];
            uint32_t a2 = Ps[(wr +     g) * FPSTR + kb + 4 + t];
            uint32_t a3 = Ps[(wr + 8 + g) * FPSTR + kb + 4 + t];
            const int sw = t << 3;
#pragma unroll
            for (int nf = 0; nf < 16; nf++) {
                uint32_t b0 = vs[(kb +     t) * FVSTR + ((nf * 8 + g) ^ sw)];
                uint32_t b1 = vs[(kb + 4 + t) * FVSTR + ((nf * 8 + g) ^ sw)];
                MMA_TF32(o[nf], a0, a1, a2, a3, b0, b1);
            }
        }
        __syncwarp();
    }

    const float il0 = 1.0f / l0;
    const float il1 = 1.0f / l1;
#pragma unroll
    for (int nf = 0; nf < 16; nf++) {
        const int col = h * HD + nf * 8 + 2 * t;
        float* p0 = g_attn + (size_t)row0 * H_DIM + col;
        p0[0] = __uint_as_float(f2tf(o[nf][0] * il0));
        p0[1] = __uint_as_float(f2tf(o[nf][1] * il0));
        float* p1 = g_attn + (size_t)(row0 + 8) * H_DIM + col;
        p1[0] = __uint_as_float(f2tf(o[nf][2] * il1));
        p1[1] = __uint_as_float(f2tf(o[nf][3] * il1));
    }
}

// ---------------------------------------------------------------------------
// Launch
// ---------------------------------------------------------------------------
extern "C" void kernel_launch(void* const* d_in, const int* in_sizes, int n_in,
                              void* d_out, int out_size)
{
    (void)in_sizes; (void)n_in; (void)out_size;
    const int*   positions = (const int*)d_in[0];
    const float* hidden    = (const float*)d_in[1];
    const float* w_qkv     = (const float*)d_in[2];
    const float* w_o       = (const float*)d_in[3];
    float*       out       = (float*)d_out;

    float *qkv_ptr = nullptr, *attn_ptr = nullptr;
    uint32_t *hidA = nullptr, *wqkvB = nullptr, *woB = nullptr, *attnA = nullptr;
    cudaGetSymbolAddress((void**)&qkv_ptr, g_qkv);
    cudaGetSymbolAddress((void**)&attn_ptr, g_attn);
    cudaGetSymbolAddress((void**)&hidA, g_hidA);
    cudaGetSymbolAddress((void**)&wqkvB, g_wqkvB);
    cudaGetSymbolAddress((void**)&woB, g_woB);
    cudaGetSymbolAddress((void**)&attnA, g_attnA);

    cudaFuncSetAttribute(gemm_tf32_nt,
                         cudaFuncAttributeMaxDynamicSharedMemorySize,
                         G_SMEM_BYTES);
    cudaFuncSetAttribute(flash_tc_kernel,
                         cudaFuncAttributeMaxDynamicSharedMemorySize,
                         FLASH_SMEM_BYTES);

    // 0) convert + pack operands
    pack_a_kernel<<<2048, 256>>>(hidden, (uint4*)hidA, H_DIM,
                                 S_LEN * H_DIM / 4);
    pack_b_kernel<<<2048, 256>>>(w_qkv, (uint2*)wqkvB, H_DIM,
                                 QKV_N * H_DIM / 2);
    pack_b_kernel<<<2048, 256>>>(w_o, (uint2*)woB, H_DIM,
                                 H_DIM * H_DIM / 2);

    // 1) QKV projection (tiles: 48 x 16, 2 CTAs/SM)
    gemm_tf32_nt<<<dim3(QKV_N / 128, S_LEN / 128), 128, G_SMEM_BYTES>>>(
        H_DIM, QKV_N, hidA, wqkvB, qkv_ptr);

    // 2) RoPE (+ tf32 rounding of Q, K, V)
    rope_kernel<<<dim3(S_LEN, NH + 2 * NKV), 64>>>(positions);

    // 3) Flash attention
    flash_tc_kernel<<<dim3(S_LEN / 128, NH), 256, FLASH_SMEM_BYTES>>>();

    // 3b) pack attention output for O-proj
    pack_a_kernel<<<2048, 256>>>(attn_ptr, (uint4*)attnA, H_DIM,
                                 S_LEN * H_DIM / 4);

    // 4) Output projection (tiles: 32 x 16, 2 CTAs/SM)
    gemm_tf32_nt<<<dim3(H_DIM / 128, S_LEN / 128), 128, G_SMEM_BYTES>>>(
        H_DIM, H_DIM, attnA, woB, out);
}

// round 14
// speedup vs baseline: 4.9822x; 1.0744x over previous
#include <cuda_runtime.h>
#include <math.h>
#include <stdint.h>

#define S_LEN 2048
#define H_DIM 4096
#define NH 32
#define NKV 8
#define HD 128
#define QKV_N 6144
#define ATT_SCALE 0.08838834764831843f

__device__ float g_qkv[S_LEN * QKV_N];
__device__ float g_attn[S_LEN * H_DIM];
// fragment-packed tf32 operands
__device__ uint32_t g_hidA [S_LEN * H_DIM];
__device__ uint32_t g_wqkvB[QKV_N * H_DIM];
__device__ uint32_t g_woB  [H_DIM * H_DIM];
__device__ uint32_t g_attnA[S_LEN * H_DIM];

__device__ __forceinline__ uint32_t f2tf(float x) {
    uint32_t r;
    asm("cvt.rna.tf32.f32 %0, %1;" : "=r"(r) : "f"(x));
    return r;
}

__device__ __forceinline__ uint32_t smem_u32(const void* p) {
    uint32_t a;
    asm("{ .reg .u64 t; cvta.to.shared.u64 t, %1; cvt.u32.u64 %0, t; }"
        : "=r"(a) : "l"(p));
    return a;
}

#define MMA_TF32(ACC, A0, A1, A2, A3, B0, B1)                                  \
    asm volatile(                                                              \
        "mma.sync.aligned.m16n8k8.row.col.f32.tf32.tf32.f32 "                  \
        "{%0,%1,%2,%3}, {%4,%5,%6,%7}, {%8,%9}, {%0,%1,%2,%3};\n"              \
        : "+f"(ACC[0]), "+f"(ACC[1]), "+f"(ACC[2]), "+f"(ACC[3])               \
        : "r"(A0), "r"(A1), "r"(A2), "r"(A3), "r"(B0), "r"(B1))

#define CP_ASYNC16(dst, src)                                                   \
    asm volatile("cp.async.cg.shared.global [%0], [%1], 16;"                   \
                 :: "r"(dst), "l"(src) : "memory")
#define CP_COMMIT()  asm volatile("cp.async.commit_group;" ::: "memory")
#define CP_WAIT1()   asm volatile("cp.async.wait_group 1;" ::: "memory")
#define CP_WAIT0()   asm volatile("cp.async.wait_group 0;" ::: "memory")

// ---------------------------------------------------------------------------
// A-pack: float [M,K] row-major -> fragment-packed tf32.
// ---------------------------------------------------------------------------
__global__ void pack_a_kernel(const float* __restrict__ in,
                              uint4* __restrict__ out, int K, int n4)
{
    const int k16n = K / 16;
    for (int idx = blockIdx.x * blockDim.x + threadIdx.x; idx < n4;
         idx += gridDim.x * blockDim.x) {
        const int slab = idx >> 9;
        const int rem  = idx & 511;
        const int sub  = rem >> 5;
        const int lane = rem & 31;
        const int mblk = slab / k16n;
        const int k16  = slab - mblk * k16n;
        const int row  = mblk * 128 + (sub >> 1) * 16 + (lane >> 2);
        const int k    = k16 * 16 + (sub & 1) * 8 + (lane & 3);
        const float* p = in + (size_t)row * K + k;
        out[idx] = make_uint4(f2tf(p[0]),
                              f2tf(p[(size_t)8 * K]),
                              f2tf(p[4]),
                              f2tf(p[(size_t)8 * K + 4]));
    }
}

// ---------------------------------------------------------------------------
// B-pack: float [N,K] row-major -> fragment-packed tf32.
// ---------------------------------------------------------------------------
__global__ void pack_b_kernel(const float* __restrict__ in,
                              uint2* __restrict__ out, int K, int n2)
{
    const int k16n = K / 16;
    for (int idx = blockIdx.x * blockDim.x + threadIdx.x; idx < n2;
         idx += gridDim.x * blockDim.x) {
        const int slab = idx >> 10;
        const int rem  = idx & 1023;
        const int sub  = rem >> 5;
        const int lane = rem & 31;
        const int nblk = slab / k16n;
        const int k16  = slab - nblk * k16n;
        const int row  = nblk * 128 + (sub >> 1) * 8 + (lane >> 2);
        const int k    = k16 * 16 + (sub & 1) * 8 + (lane & 3);
        const float* p = in + (size_t)row * K + k;
        out[idx] = make_uint2(f2tf(p[0]), f2tf(p[4]));
    }
}

// ---------------------------------------------------------------------------
// TF32 GEMM, 128x128 CTA tile, 128 threads (4 warps, 64x64 warp tiles),
// cp.async 3-stage ring, BK=32 stages, 2 CTAs/SM.
// NEW: software-pipelined fragment loads — register double buffers aw/bw;
// phase p+1's LDS issue precedes phase p's MMA burst.
// ---------------------------------------------------------------------------
#define A_SLAB_W 2048
#define A_STG_W  4096                       // 2 k16-slabs (BK=32)
#define B_STG_W  4096
#define G_SMEM_BYTES (3 * (A_STG_W + B_STG_W) * 4)   // 98304

__global__ __launch_bounds__(128, 2)
void gemm_tf32_nt(int K, int Nfull,
                  const uint32_t* __restrict__ A,
                  const uint32_t* __restrict__ B,
                  float* __restrict__ C)
{
    extern __shared__ uint32_t gdyn[];
    uint32_t* As = gdyn;                     // [3][A_STG_W]
    uint32_t* Bs = gdyn + 3 * A_STG_W;       // [3][B_STG_W]
    const uint32_t as_base = smem_u32(As);
    const uint32_t bs_base = smem_u32(Bs);

    const int tid  = threadIdx.x;
    const int warp = tid >> 5;
    const int lane = tid & 31;
    const int g    = lane >> 2;
    const int t    = lane & 3;

    const int k16n = K / 16;
    const int nkp  = k16n / 2;               // BK=32 steps
    const uint32_t* Aslab = A + (size_t)blockIdx.y * k16n * A_SLAB_W;
    const uint32_t* Bslab = B + (size_t)blockIdx.x * k16n * A_SLAB_W;

    const int m16b = (warp & 1) * 4;         // 0 or 4
    const int n8b  = (warp >> 1) * 8;        // 0 or 8

    float acc[4][8][4];
#pragma unroll
    for (int i = 0; i < 4; i++)
#pragma unroll
        for (int j = 0; j < 8; j++)
#pragma unroll
            for (int r = 0; r < 4; r++) acc[i][j][r] = 0.0f;

#define G_FILL(stage, kp)                                                      \
    do {                                                                       \
        const uint32_t ab = as_base + (stage) * A_STG_W * 4;                   \
        const uint32_t bb = bs_base + (stage) * B_STG_W * 4;                   \
        _Pragma("unroll")                                                      \
        for (int j = 0; j < 2; j++) {                                          \
            const uint32_t* Ap = Aslab + (size_t)(2 * (kp) + j) * A_SLAB_W;    \
            const uint32_t* Bp = Bslab + (size_t)(2 * (kp) + j) * A_SLAB_W;    \
            _Pragma("unroll")                                                  \
            for (int i = 0; i < 4; i++) {                                      \
                const int c = tid + i * 128;                                   \
                CP_ASYNC16(ab + j * 8192 + c * 16, Ap + c * 4);                \
                CP_ASYNC16(bb + j * 8192 + c * 16, Bp + c * 4);                \
            }                                                                  \
        }                                                                      \
    } while (0)

// fragment load: phase ph = j*2 + ks into register buffer buf
#define LOADF(buf, ph)                                                         \
    do {                                                                       \
        const int j_  = (ph) >> 1;                                             \
        const int ks_ = (ph) & 1;                                              \
        const uint32_t* as_ = as_s + j_ * A_SLAB_W;                            \
        const uint32_t* bs_ = bs_s + j_ * A_SLAB_W;                            \
        _Pragma("unroll")                                                      \
        for (int am = 0; am < 4; am++)                                         \
            aw[buf][am] = *(const uint4*)&as_[((m16b + am) * 2 + ks_) * 128 +  \
                                              lane * 4];                       \
        _Pragma("unroll")                                                      \
        for (int an = 0; an < 8; an++)                                         \
            bw[buf][an] = *(const uint2*)&bs_[((n8b + an) * 2 + ks_) * 64 +    \
                                              lane * 2];                       \
    } while (0)

    G_FILL(0, 0);
    CP_COMMIT();
    G_FILL(1, 1);
    CP_COMMIT();

    int stg = 0;
    for (int kp = 0; kp < nkp; kp++) {
        CP_WAIT1();
        __syncthreads();

        if (kp + 2 < nkp) {
            const int s2 = (kp + 2) % 3;
            G_FILL(s2, kp + 2);
        }
        CP_COMMIT();

        const uint32_t* as_s = As + stg * A_STG_W;
        const uint32_t* bs_s = Bs + stg * B_STG_W;

        uint4 aw[2][4];
        uint2 bw[2][8];
        LOADF(0, 0);
#pragma unroll
        for (int ph = 0; ph < 4; ph++) {
            const int cur = ph & 1;
            if (ph < 3) LOADF(cur ^ 1, ph + 1);
#pragma unroll
            for (int am = 0; am < 4; am++)
#pragma unroll
                for (int an = 0; an < 8; an++)
                    MMA_TF32(acc[am][an],
                             aw[cur][am].x, aw[cur][am].y,
                             aw[cur][am].z, aw[cur][am].w,
                             bw[cur][an].x, bw[cur][an].y);
        }
        stg = (stg + 1) % 3;
    }
    CP_WAIT0();

    const int bm = blockIdx.y * 128;
    const int bn = blockIdx.x * 128;
#pragma unroll
    for (int am = 0; am < 4; am++) {
        const int row0 = bm + (m16b + am) * 16 + g;
#pragma unroll
        for (int an = 0; an < 8; an++) {
            const int col = bn + (n8b + an) * 8 + t * 2;
            float* c0p = C + (size_t)row0 * Nfull + col;
            c0p[0] = acc[am][an][0];
            c0p[1] = acc[am][an][1];
            float* c2p = c0p + (size_t)8 * Nfull;
            c2p[0] = acc[am][an][2];
            c2p[1] = acc[am][an][3];
        }
    }
#undef LOADF
#undef G_FILL
}

// ---------------------------------------------------------------------------
// RoPE + tf32 pre-round (heads 0..39 rotate+round, 40..47 round only)
// ---------------------------------------------------------------------------
__global__ void rope_kernel(const int* __restrict__ positions)
{
    const int s = blockIdx.x;
    const int h = blockIdx.y;          // 0..47
    const int d = threadIdx.x;         // 0..63

    float* base = g_qkv + (size_t)s * QKV_N + h * HD;
    const float x1 = base[d];
    const float x2 = base[d + 64];

    if (h < NH + NKV) {
        const float pos = (float)positions[s];
        const float inv_freq = powf(1000000.0f, -(float)d * (1.0f / 64.0f));
        const float ang = pos * inv_freq;
        float sn, cs;
        sincosf(ang, &sn, &cs);
        base[d]      = __uint_as_float(f2tf(x1 * cs - x2 * sn));
        base[d + 64] = __uint_as_float(f2tf(x2 * cs + x1 * sn));
    } else {
        base[d]      = __uint_as_float(f2tf(x1));
        base[d + 64] = __uint_as_float(f2tf(x2));
    }
}

// ---------------------------------------------------------------------------
// Flash attention (unchanged from round 13)
// ---------------------------------------------------------------------------
#define FKSTR 132
#define FVSTR 128
#define FPSTR 68
#define KSTG_W (64 * FKSTR)
#define VSTG_W (64 * FVSTR)
#define FLASH_SMEM_WORDS (2 * KSTG_W + 2 * VSTG_W + 128 * FPSTR)
#define FLASH_SMEM_BYTES (FLASH_SMEM_WORDS * 4)   // 167936

__global__ __launch_bounds__(256)
void flash_tc_kernel()
{
    extern __shared__ uint32_t fsm[];
    uint32_t* Ks = fsm;
    uint32_t* Vs = fsm + 2 * KSTG_W;
    uint32_t* Ps = fsm + 2 * KSTG_W + 2 * VSTG_W;
    const uint32_t ks_base = smem_u32(Ks);
    const uint32_t vs_base = smem_u32(Vs);

    const int tid  = threadIdx.x;
    const int warp = tid >> 5;
    const int lane = tid & 31;
    const int g    = lane >> 2;
    const int t    = lane & 3;
    const int qt   = gridDim.x - 1 - blockIdx.x;
    const int h    = blockIdx.y;
    const int kh   = h >> 2;
    const int wr   = warp * 16;

    const float* Qg = g_qkv + (size_t)(qt * 128) * QKV_N + h * HD;
    const float* Kg = g_qkv + NH * HD + kh * HD;
    const float* Vg = g_qkv + (NH + NKV) * HD + kh * HD;

    const int cw  = lane * 4;
    const int vsw = cw ^ ((warp & 3) << 3);

    uint32_t qf[16][4];
    {
        const float* q0 = Qg + (size_t)(wr +     g) * QKV_N;
        const float* q1 = Qg + (size_t)(wr + 8 + g) * QKV_N;
#pragma unroll
        for (int kc = 0; kc < 16; kc++) {
            const int c = kc * 8 + t;
            qf[kc][0] = __float_as_uint(q0[c]);
            qf[kc][1] = __float_as_uint(q1[c]);
            qf[kc][2] = __float_as_uint(q0[c + 4]);
            qf[kc][3] = __float_as_uint(q1[c + 4]);
        }
    }

    float m0 = -INFINITY, m1 = -INFINITY, l0 = 0.0f, l1 = 0.0f;
    float o[16][4];
#pragma unroll
    for (int nf = 0; nf < 16; nf++)
#pragma unroll
        for (int r = 0; r < 4; r++) o[nf][r] = 0.0f;

    const int row0 = qt * 128 + wr + g;
    const int n_ktiles = 2 * qt + 2;

    {
#pragma unroll
        for (int i = 0; i < 8; i++) {
            const int r = warp + 8 * i;
            CP_ASYNC16(ks_base + (uint32_t)(r * FKSTR + cw) * 4,
                       Kg + (size_t)r * QKV_N + cw);
            CP_ASYNC16(vs_base + (uint32_t)(r * FVSTR + vsw) * 4,
                       Vg + (size_t)r * QKV_N + cw);
        }
        CP_COMMIT();
    }

    for (int jt = 0; jt < n_ktiles; jt++) {
        __syncthreads();
        if (jt + 1 < n_ktiles) {
            const int s = (jt + 1) & 1;
            const float* Kt = Kg + (size_t)((jt + 1) * 64) * QKV_N;
            const float* Vt = Vg + (size_t)((jt + 1) * 64) * QKV_N;
            const uint32_t kb = ks_base + s * KSTG_W * 4;
            const uint32_t vb = vs_base + s * VSTG_W * 4;
#pragma unroll
            for (int i = 0; i < 8; i++) {
                const int r = warp + 8 * i;
                CP_ASYNC16(kb + (uint32_t)(r * FKSTR + cw) * 4,
                           Kt + (size_t)r * QKV_N + cw);
                CP_ASYNC16(vb + (uint32_t)(r * FVSTR + vsw) * 4,
                           Vt + (size_t)r * QKV_N + cw);
            }
        }
        CP_COMMIT();
        CP_WAIT1();
        __syncthreads();

        const uint32_t* ks = Ks + (jt & 1) * KSTG_W;
        const uint32_t* vs = Vs + (jt & 1) * VSTG_W;

        float s4[8][4];
#pragma unroll
        for (int nf = 0; nf < 8; nf++)
#pragma unroll
            for (int r = 0; r < 4; r++) s4[nf][r] = 0.0f;

#pragma unroll
        for (int kc = 0; kc < 16; kc++) {
            const int kb = kc * 8;
#pragma unroll
            for (int nf = 0; nf < 8; nf++) {
                uint32_t b0 = ks[(nf * 8 + g) * FKSTR + kb +     t];
                uint32_t b1 = ks[(nf * 8 + g) * FKSTR + kb + 4 + t];
                MMA_TF32(s4[nf], qf[kc][0], qf[kc][1], qf[kc][2], qf[kc][3], b0, b1);
            }
        }

        const int colbase = jt * 64 + 2 * t;
#pragma unroll
        for (int nf = 0; nf < 8; nf++) {
            const int col = colbase + nf * 8;
            float v0 = s4[nf][0] * ATT_SCALE;
            float v1 = s4[nf][1] * ATT_SCALE;
            float v2 = s4[nf][2] * ATT_SCALE;
            float v3 = s4[nf][3] * ATT_SCALE;
            if (col     > row0)     v0 = -1e30f;
            if (col + 1 > row0)     v1 = -1e30f;
            if (col     > row0 + 8) v2 = -1e30f;
            if (col + 1 > row0 + 8) v3 = -1e30f;
            s4[nf][0] = v0; s4[nf][1] = v1; s4[nf][2] = v2; s4[nf][3] = v3;
        }

        float rm0 = -INFINITY, rm1 = -INFINITY;
#pragma unroll
        for (int nf = 0; nf < 8; nf++) {
            rm0 = fmaxf(rm0, fmaxf(s4[nf][0], s4[nf][1]));
            rm1 = fmaxf(rm1, fmaxf(s4[nf][2], s4[nf][3]));
        }
        rm0 = fmaxf(rm0, __shfl_xor_sync(0xffffffffu, rm0, 1));
        rm0 = fmaxf(rm0, __shfl_xor_sync(0xffffffffu, rm0, 2));
        rm1 = fmaxf(rm1, __shfl_xor_sync(0xffffffffu, rm1, 1));
        rm1 = fmaxf(rm1, __shfl_xor_sync(0xffffffffu, rm1, 2));

        const float mn0 = fmaxf(m0, rm0);
        const float mn1 = fmaxf(m1, rm1);
        const float cr_0 = __expf(m0 - mn0);
        const float cr_1 = __expf(m1 - mn1);

        float rs0 = 0.0f, rs1 = 0.0f;
#pragma unroll
        for (int nf = 0; nf < 8; nf++) {
            s4[nf][0] = __expf(s4[nf][0] - mn0);
            s4[nf][1] = __expf(s4[nf][1] - mn0);
            s4[nf][2] = __expf(s4[nf][2] - mn1);
            s4[nf][3] = __expf(s4[nf][3] - mn1);
            rs0 += s4[nf][0] + s4[nf][1];
            rs1 += s4[nf][2] + s4[nf][3];
        }
        rs0 += __shfl_xor_sync(0xffffffffu, rs0, 1);
        rs0 += __shfl_xor_sync(0xffffffffu, rs0, 2);
        rs1 += __shfl_xor_sync(0xffffffffu, rs1, 1);
        rs1 += __shfl_xor_sync(0xffffffffu, rs1, 2);

        l0 = l0 * cr_0 + rs0;  m0 = mn0;
        l1 = l1 * cr_1 + rs1;  m1 = mn1;

#pragma unroll
        for (int nf = 0; nf < 16; nf++) {
            o[nf][0] *= cr_0;  o[nf][1] *= cr_0;
            o[nf][2] *= cr_1;  o[nf][3] *= cr_1;
        }

#pragma unroll
        for (int nf = 0; nf < 8; nf++) {
            const int c = nf * 8 + 2 * t;
            *(uint2*)&Ps[(wr +     g) * FPSTR + c] =
                make_uint2(f2tf(s4[nf][0]), f2tf(s4[nf][1]));
            *(uint2*)&Ps[(wr + 8 + g) * FPSTR + c] =
                make_uint2(f2tf(s4[nf][2]), f2tf(s4[nf][3]));
        }
        __syncwarp();

#pragma unroll
        for (int kc = 0; kc < 8; kc++) {
            const int kb = kc * 8;
            uint32_t a0 = Ps[(wr +     g) * FPSTR + kb +     t];
            uint32_t a1 = Ps[(wr + 8 + g) * FPSTR + kb +     t];
            uint32_t a2 = Ps[(wr +     g) * FPSTR + kb + 4 + t];
            uint32_t a3 = Ps[(wr + 8 + g) * FPSTR + kb + 4 + t];
            const int sw = t << 3;
#pragma unroll
            for (int nf = 0; nf < 16; nf++) {
                uint32_t b0 = vs[(kb +     t) * FVSTR + ((nf * 8 + g) ^ sw)];
                uint32_t b1 = vs[(kb + 4 + t) * FVSTR + ((nf * 8 + g) ^ sw)];
                MMA_TF32(o[nf], a0, a1, a2, a3, b0, b1);
            }
        }
        __syncwarp();
    }

    const float il0 = 1.0f / l0;
    const float il1 = 1.0f / l1;
#pragma unroll
    for (int nf = 0; nf < 16; nf++) {
        const int col = h * HD + nf * 8 + 2 * t;
        float* p0 = g_attn + (size_t)row0 * H_DIM + col;
        p0[0] = __uint_as_float(f2tf(o[nf][0] * il0));
        p0[1] = __uint_as_float(f2tf(o[nf][1] * il0));
        float* p1 = g_attn + (size_t)(row0 + 8) * H_DIM + col;
        p1[0] = __uint_as_float(f2tf(o[nf][2] * il1));
        p1[1] = __uint_as_float(f2tf(o[nf][3] * il1));
    }
}

// ---------------------------------------------------------------------------
// Launch
// ---------------------------------------------------------------------------
extern "C" void kernel_launch(void* const* d_in, const int* in_sizes, int n_in,
                              void* d_out, int out_size)
{
    (void)in_sizes; (void)n_in; (void)out_size;
    const int*   positions = (const int*)d_in[0];
    const float* hidden    = (const float*)d_in[1];
    const float* w_qkv     = (const float*)d_in[2];
    const float* w_o       = (const float*)d_in[3];
    float*       out       = (float*)d_out;

    float *qkv_ptr = nullptr, *attn_ptr = nullptr;
    uint32_t *hidA = nullptr, *wqkvB = nullptr, *woB = nullptr, *attnA = nullptr;
    cudaGetSymbolAddress((void**)&qkv_ptr, g_qkv);
    cudaGetSymbolAddress((void**)&attn_ptr, g_attn);
    cudaGetSymbolAddress((void**)&hidA, g_hidA);
    cudaGetSymbolAddress((void**)&wqkvB, g_wqkvB);
    cudaGetSymbolAddress((void**)&woB, g_woB);
    cudaGetSymbolAddress((void**)&attnA, g_attnA);

    cudaFuncSetAttribute(gemm_tf32_nt,
                         cudaFuncAttributeMaxDynamicSharedMemorySize,
                         G_SMEM_BYTES);
    cudaFuncSetAttribute(flash_tc_kernel,
                         cudaFuncAttributeMaxDynamicSharedMemorySize,
                         FLASH_SMEM_BYTES);

    // 0) convert + pack operands
    pack_a_kernel<<<2048, 256>>>(hidden, (uint4*)hidA, H_DIM,
                                 S_LEN * H_DIM / 4);
    pack_b_kernel<<<2048, 256>>>(w_qkv, (uint2*)wqkvB, H_DIM,
                                 QKV_N * H_DIM / 2);
    pack_b_kernel<<<2048, 256>>>(w_o, (uint2*)woB, H_DIM,
                                 H_DIM * H_DIM / 2);

    // 1) QKV projection (48 x 16 tiles, 2 CTAs/SM)
    gemm_tf32_nt<<<dim3(QKV_N / 128, S_LEN / 128), 128, G_SMEM_BYTES>>>(
        H_DIM, QKV_N, hidA, wqkvB, qkv_ptr);

    // 2) RoPE (+ tf32 rounding of Q, K, V)
    rope_kernel<<<dim3(S_LEN, NH + 2 * NKV), 64>>>(positions);

    // 3) Flash attention
    flash_tc_kernel<<<dim3(S_LEN / 128, NH), 256, FLASH_SMEM_BYTES>>>();

    // 3b) pack attention output for O-proj
    pack_a_kernel<<<2048, 256>>>(attn_ptr, (uint4*)attnA, H_DIM,
                                 S_LEN * H_DIM / 4);

    // 4) Output projection (32 x 16 tiles, 2 CTAs/SM)
    gemm_tf32_nt<<<dim3(H_DIM / 128, S_LEN / 128), 128, G_SMEM_BYTES>>>(
        H_DIM, H_DIM, attnA, woB, out);
}

// round 15
// speedup vs baseline: 4.9905x; 1.0017x over previous
#include <cuda_runtime.h>
#include <math.h>
#include <stdint.h>

#define S_LEN 2048
#define H_DIM 4096
#define NH 32
#define NKV 8
#define HD 128
#define QKV_N 6144
#define ATT_SCALE 0.08838834764831843f

__device__ float g_qkv[S_LEN * QKV_N];
__device__ float g_attn[S_LEN * H_DIM];
// fragment-packed tf32 operands
__device__ uint32_t g_hidA [S_LEN * H_DIM];
__device__ uint32_t g_wqkvB[QKV_N * H_DIM];
__device__ uint32_t g_woB  [H_DIM * H_DIM];
__device__ uint32_t g_attnA[S_LEN * H_DIM];

__device__ __forceinline__ uint32_t f2tf(float x) {
    uint32_t r;
    asm("cvt.rna.tf32.f32 %0, %1;" : "=r"(r) : "f"(x));
    return r;
}

__device__ __forceinline__ uint32_t smem_u32(const void* p) {
    uint32_t a;
    asm("{ .reg .u64 t; cvta.to.shared.u64 t, %1; cvt.u32.u64 %0, t; }"
        : "=r"(a) : "l"(p));
    return a;
}

#define MMA_TF32(ACC, A0, A1, A2, A3, B0, B1)                                  \
    asm volatile(                                                              \
        "mma.sync.aligned.m16n8k8.row.col.f32.tf32.tf32.f32 "                  \
        "{%0,%1,%2,%3}, {%4,%5,%6,%7}, {%8,%9}, {%0,%1,%2,%3};\n"              \
        : "+f"(ACC[0]), "+f"(ACC[1]), "+f"(ACC[2]), "+f"(ACC[3])               \
        : "r"(A0), "r"(A1), "r"(A2), "r"(A3), "r"(B0), "r"(B1))

#define CP_ASYNC16(dst, src)                                                   \
    asm volatile("cp.async.cg.shared.global [%0], [%1], 16;"                   \
                 :: "r"(dst), "l"(src) : "memory")
#define CP_COMMIT()  asm volatile("cp.async.commit_group;" ::: "memory")
#define CP_WAIT1()   asm volatile("cp.async.wait_group 1;" ::: "memory")
#define CP_WAIT0()   asm volatile("cp.async.wait_group 0;" ::: "memory")

// ---------------------------------------------------------------------------
// A-pack: float [M,K] row-major -> fragment-packed tf32.
// ---------------------------------------------------------------------------
__global__ void pack_a_kernel(const float* __restrict__ in,
                              uint4* __restrict__ out, int K, int n4)
{
    const int k16n = K / 16;
    for (int idx = blockIdx.x * blockDim.x + threadIdx.x; idx < n4;
         idx += gridDim.x * blockDim.x) {
        const int slab = idx >> 9;
        const int rem  = idx & 511;
        const int sub  = rem >> 5;
        const int lane = rem & 31;
        const int mblk = slab / k16n;
        const int k16  = slab - mblk * k16n;
        const int row  = mblk * 128 + (sub >> 1) * 16 + (lane >> 2);
        const int k    = k16 * 16 + (sub & 1) * 8 + (lane & 3);
        const float* p = in + (size_t)row * K + k;
        out[idx] = make_uint4(f2tf(p[0]),
                              f2tf(p[(size_t)8 * K]),
                              f2tf(p[4]),
                              f2tf(p[(size_t)8 * K + 4]));
    }
}

// ---------------------------------------------------------------------------
// B-pack: float [N,K] row-major -> fragment-packed tf32.
// ---------------------------------------------------------------------------
__global__ void pack_b_kernel(const float* __restrict__ in,
                              uint2* __restrict__ out, int K, int n2)
{
    const int k16n = K / 16;
    for (int idx = blockIdx.x * blockDim.x + threadIdx.x; idx < n2;
         idx += gridDim.x * blockDim.x) {
        const int slab = idx >> 10;
        const int rem  = idx & 1023;
        const int sub  = rem >> 5;
        const int lane = rem & 31;
        const int nblk = slab / k16n;
        const int k16  = slab - nblk * k16n;
        const int row  = nblk * 128 + (sub >> 1) * 8 + (lane >> 2);
        const int k    = k16 * 16 + (sub & 1) * 8 + (lane & 3);
        const float* p = in + (size_t)row * K + k;
        out[idx] = make_uint2(f2tf(p[0]), f2tf(p[4]));
    }
}

// ---------------------------------------------------------------------------
// TF32 GEMM (unchanged from round 14 — pipelined fragments, 2 CTAs/SM)
// ---------------------------------------------------------------------------
#define A_SLAB_W 2048
#define A_STG_W  4096
#define B_STG_W  4096
#define G_SMEM_BYTES (3 * (A_STG_W + B_STG_W) * 4)   // 98304

__global__ __launch_bounds__(128, 2)
void gemm_tf32_nt(int K, int Nfull,
                  const uint32_t* __restrict__ A,
                  const uint32_t* __restrict__ B,
                  float* __restrict__ C)
{
    extern __shared__ uint32_t gdyn[];
    uint32_t* As = gdyn;
    uint32_t* Bs = gdyn + 3 * A_STG_W;
    const uint32_t as_base = smem_u32(As);
    const uint32_t bs_base = smem_u32(Bs);

    const int tid  = threadIdx.x;
    const int warp = tid >> 5;
    const int lane = tid & 31;
    const int g    = lane >> 2;
    const int t    = lane & 3;

    const int k16n = K / 16;
    const int nkp  = k16n / 2;
    const uint32_t* Aslab = A + (size_t)blockIdx.y * k16n * A_SLAB_W;
    const uint32_t* Bslab = B + (size_t)blockIdx.x * k16n * A_SLAB_W;

    const int m16b = (warp & 1) * 4;
    const int n8b  = (warp >> 1) * 8;

    float acc[4][8][4];
#pragma unroll
    for (int i = 0; i < 4; i++)
#pragma unroll
        for (int j = 0; j < 8; j++)
#pragma unroll
            for (int r = 0; r < 4; r++) acc[i][j][r] = 0.0f;

#define G_FILL(stage, kp)                                                      \
    do {                                                                       \
        const uint32_t ab = as_base + (stage) * A_STG_W * 4;                   \
        const uint32_t bb = bs_base + (stage) * B_STG_W * 4;                   \
        _Pragma("unroll")                                                      \
        for (int j = 0; j < 2; j++) {                                          \
            const uint32_t* Ap = Aslab + (size_t)(2 * (kp) + j) * A_SLAB_W;    \
            const uint32_t* Bp = Bslab + (size_t)(2 * (kp) + j) * A_SLAB_W;    \
            _Pragma("unroll")                                                  \
            for (int i = 0; i < 4; i++) {                                      \
                const int c = tid + i * 128;                                   \
                CP_ASYNC16(ab + j * 8192 + c * 16, Ap + c * 4);                \
                CP_ASYNC16(bb + j * 8192 + c * 16, Bp + c * 4);                \
            }                                                                  \
        }                                                                      \
    } while (0)

#define LOADF(buf, ph)                                                         \
    do {                                                                       \
        const int j_  = (ph) >> 1;                                             \
        const int ks_ = (ph) & 1;                                              \
        const uint32_t* as_ = as_s + j_ * A_SLAB_W;                            \
        const uint32_t* bs_ = bs_s + j_ * A_SLAB_W;                            \
        _Pragma("unroll")                                                      \
        for (int am = 0; am < 4; am++)                                         \
            aw[buf][am] = *(const uint4*)&as_[((m16b + am) * 2 + ks_) * 128 +  \
                                              lane * 4];                       \
        _Pragma("unroll")                                                      \
        for (int an = 0; an < 8; an++)                                         \
            bw[buf][an] = *(const uint2*)&bs_[((n8b + an) * 2 + ks_) * 64 +    \
                                              lane * 2];                       \
    } while (0)

    G_FILL(0, 0);
    CP_COMMIT();
    G_FILL(1, 1);
    CP_COMMIT();

    int stg = 0;
    for (int kp = 0; kp < nkp; kp++) {
        CP_WAIT1();
        __syncthreads();

        if (kp + 2 < nkp) {
            const int s2 = (kp + 2) % 3;
            G_FILL(s2, kp + 2);
        }
        CP_COMMIT();

        const uint32_t* as_s = As + stg * A_STG_W;
        const uint32_t* bs_s = Bs + stg * B_STG_W;

        uint4 aw[2][4];
        uint2 bw[2][8];
        LOADF(0, 0);
#pragma unroll
        for (int ph = 0; ph < 4; ph++) {
            const int cur = ph & 1;
            if (ph < 3) LOADF(cur ^ 1, ph + 1);
#pragma unroll
            for (int am = 0; am < 4; am++)
#pragma unroll
                for (int an = 0; an < 8; an++)
                    MMA_TF32(acc[am][an],
                             aw[cur][am].x, aw[cur][am].y,
                             aw[cur][am].z, aw[cur][am].w,
                             bw[cur][an].x, bw[cur][an].y);
        }
        stg = (stg + 1) % 3;
    }
    CP_WAIT0();

    const int bm = blockIdx.y * 128;
    const int bn = blockIdx.x * 128;
#pragma unroll
    for (int am = 0; am < 4; am++) {
        const int row0 = bm + (m16b + am) * 16 + g;
#pragma unroll
        for (int an = 0; an < 8; an++) {
            const int col = bn + (n8b + an) * 8 + t * 2;
            float* c0p = C + (size_t)row0 * Nfull + col;
            c0p[0] = acc[am][an][0];
            c0p[1] = acc[am][an][1];
            float* c2p = c0p + (size_t)8 * Nfull;
            c2p[0] = acc[am][an][2];
            c2p[1] = acc[am][an][3];
        }
    }
#undef LOADF
#undef G_FILL
}

// ---------------------------------------------------------------------------
// RoPE + tf32 pre-round (heads 0..39 rotate+round, 40..47 round only)
// ---------------------------------------------------------------------------
__global__ void rope_kernel(const int* __restrict__ positions)
{
    const int s = blockIdx.x;
    const int h = blockIdx.y;          // 0..47
    const int d = threadIdx.x;         // 0..63

    float* base = g_qkv + (size_t)s * QKV_N + h * HD;
    const float x1 = base[d];
    const float x2 = base[d + 64];

    if (h < NH + NKV) {
        const float pos = (float)positions[s];
        const float inv_freq = powf(1000000.0f, -(float)d * (1.0f / 64.0f));
        const float ang = pos * inv_freq;
        float sn, cs;
        sincosf(ang, &sn, &cs);
        base[d]      = __uint_as_float(f2tf(x1 * cs - x2 * sn));
        base[d + 64] = __uint_as_float(f2tf(x2 * cs + x1 * sn));
    } else {
        base[d]      = __uint_as_float(f2tf(x1));
        base[d + 64] = __uint_as_float(f2tf(x2));
    }
}

// ---------------------------------------------------------------------------
// Flash attention — NEW: register-double-buffered fragment loads in both
// the QK loop (kb[2][16]) and the PV loop (vb[2][16] half-phases + av[2][4]).
// ---------------------------------------------------------------------------
#define FKSTR 132
#define FVSTR 128
#define FPSTR 68
#define KSTG_W (64 * FKSTR)
#define VSTG_W (64 * FVSTR)
#define FLASH_SMEM_WORDS (2 * KSTG_W + 2 * VSTG_W + 128 * FPSTR)
#define FLASH_SMEM_BYTES (FLASH_SMEM_WORDS * 4)   // 167936

__global__ __launch_bounds__(256)
void flash_tc_kernel()
{
    extern __shared__ uint32_t fsm[];
    uint32_t* Ks = fsm;
    uint32_t* Vs = fsm + 2 * KSTG_W;
    uint32_t* Ps = fsm + 2 * KSTG_W + 2 * VSTG_W;
    const uint32_t ks_base = smem_u32(Ks);
    const uint32_t vs_base = smem_u32(Vs);

    const int tid  = threadIdx.x;
    const int warp = tid >> 5;
    const int lane = tid & 31;
    const int g    = lane >> 2;
    const int t    = lane & 3;
    const int qt   = gridDim.x - 1 - blockIdx.x;
    const int h    = blockIdx.y;
    const int kh   = h >> 2;
    const int wr   = warp * 16;

    const float* Qg = g_qkv + (size_t)(qt * 128) * QKV_N + h * HD;
    const float* Kg = g_qkv + NH * HD + kh * HD;
    const float* Vg = g_qkv + (NH + NKV) * HD + kh * HD;

    const int cw  = lane * 4;
    const int vsw = cw ^ ((warp & 3) << 3);

    uint32_t qf[16][4];
    {
        const float* q0 = Qg + (size_t)(wr +     g) * QKV_N;
        const float* q1 = Qg + (size_t)(wr + 8 + g) * QKV_N;
#pragma unroll
        for (int kc = 0; kc < 16; kc++) {
            const int c = kc * 8 + t;
            qf[kc][0] = __float_as_uint(q0[c]);
            qf[kc][1] = __float_as_uint(q1[c]);
            qf[kc][2] = __float_as_uint(q0[c + 4]);
            qf[kc][3] = __float_as_uint(q1[c + 4]);
        }
    }

    float m0 = -INFINITY, m1 = -INFINITY, l0 = 0.0f, l1 = 0.0f;
    float o[16][4];
#pragma unroll
    for (int nf = 0; nf < 16; nf++)
#pragma unroll
        for (int r = 0; r < 4; r++) o[nf][r] = 0.0f;

    const int row0 = qt * 128 + wr + g;
    const int n_ktiles = 2 * qt + 2;

    {
#pragma unroll
        for (int i = 0; i < 8; i++) {
            const int r = warp + 8 * i;
            CP_ASYNC16(ks_base + (uint32_t)(r * FKSTR + cw) * 4,
                       Kg + (size_t)r * QKV_N + cw);
            CP_ASYNC16(vs_base + (uint32_t)(r * FVSTR + vsw) * 4,
                       Vg + (size_t)r * QKV_N + cw);
        }
        CP_COMMIT();
    }

    for (int jt = 0; jt < n_ktiles; jt++) {
        __syncthreads();
        if (jt + 1 < n_ktiles) {
            const int s = (jt + 1) & 1;
            const float* Kt = Kg + (size_t)((jt + 1) * 64) * QKV_N;
            const float* Vt = Vg + (size_t)((jt + 1) * 64) * QKV_N;
            const uint32_t kb = ks_base + s * KSTG_W * 4;
            const uint32_t vb = vs_base + s * VSTG_W * 4;
#pragma unroll
            for (int i = 0; i < 8; i++) {
                const int r = warp + 8 * i;
                CP_ASYNC16(kb + (uint32_t)(r * FKSTR + cw) * 4,
                           Kt + (size_t)r * QKV_N + cw);
                CP_ASYNC16(vb + (uint32_t)(r * FVSTR + vsw) * 4,
                           Vt + (size_t)r * QKV_N + cw);
            }
        }
        CP_COMMIT();
        CP_WAIT1();
        __syncthreads();

        const uint32_t* ks = Ks + (jt & 1) * KSTG_W;
        const uint32_t* vs = Vs + (jt & 1) * VSTG_W;

        // ---- S = Q K^T (pipelined b-frags) ----
        float s4[8][4];
#pragma unroll
        for (int nf = 0; nf < 8; nf++)
#pragma unroll
            for (int r = 0; r < 4; r++) s4[nf][r] = 0.0f;

        uint32_t kbf[2][16];
#pragma unroll
        for (int nf = 0; nf < 8; nf++) {
            kbf[0][nf * 2]     = ks[(nf * 8 + g) * FKSTR +     t];
            kbf[0][nf * 2 + 1] = ks[(nf * 8 + g) * FKSTR + 4 + t];
        }
#pragma unroll
        for (int kc = 0; kc < 16; kc++) {
            const int cur = kc & 1;
            if (kc < 15) {
                const int kb2 = (kc + 1) * 8;
#pragma unroll
                for (int nf = 0; nf < 8; nf++) {
                    kbf[cur ^ 1][nf * 2]     = ks[(nf * 8 + g) * FKSTR + kb2 +     t];
                    kbf[cur ^ 1][nf * 2 + 1] = ks[(nf * 8 + g) * FKSTR + kb2 + 4 + t];
                }
            }
#pragma unroll
            for (int nf = 0; nf < 8; nf++)
                MMA_TF32(s4[nf], qf[kc][0], qf[kc][1], qf[kc][2], qf[kc][3],
                         kbf[cur][nf * 2], kbf[cur][nf * 2 + 1]);
        }

        // ---- scale + causal mask ----
        const int colbase = jt * 64 + 2 * t;
#pragma unroll
        for (int nf = 0; nf < 8; nf++) {
            const int col = colbase + nf * 8;
            float v0 = s4[nf][0] * ATT_SCALE;
            float v1 = s4[nf][1] * ATT_SCALE;
            float v2 = s4[nf][2] * ATT_SCALE;
            float v3 = s4[nf][3] * ATT_SCALE;
            if (col     > row0)     v0 = -1e30f;
            if (col + 1 > row0)     v1 = -1e30f;
            if (col     > row0 + 8) v2 = -1e30f;
            if (col + 1 > row0 + 8) v3 = -1e30f;
            s4[nf][0] = v0; s4[nf][1] = v1; s4[nf][2] = v2; s4[nf][3] = v3;
        }

        // ---- online softmax ----
        float rm0 = -INFINITY, rm1 = -INFINITY;
#pragma unroll
        for (int nf = 0; nf < 8; nf++) {
            rm0 = fmaxf(rm0, fmaxf(s4[nf][0], s4[nf][1]));
            rm1 = fmaxf(rm1, fmaxf(s4[nf][2], s4[nf][3]));
        }
        rm0 = fmaxf(rm0, __shfl_xor_sync(0xffffffffu, rm0, 1));
        rm0 = fmaxf(rm0, __shfl_xor_sync(0xffffffffu, rm0, 2));
        rm1 = fmaxf(rm1, __shfl_xor_sync(0xffffffffu, rm1, 1));
        rm1 = fmaxf(rm1, __shfl_xor_sync(0xffffffffu, rm1, 2));

        const float mn0 = fmaxf(m0, rm0);
        const float mn1 = fmaxf(m1, rm1);
        const float cr_0 = __expf(m0 - mn0);
        const float cr_1 = __expf(m1 - mn1);

        float rs0 = 0.0f, rs1 = 0.0f;
#pragma unroll
        for (int nf = 0; nf < 8; nf++) {
            s4[nf][0] = __expf(s4[nf][0] - mn0);
            s4[nf][1] = __expf(s4[nf][1] - mn0);
            s4[nf][2] = __expf(s4[nf][2] - mn1);
            s4[nf][3] = __expf(s4[nf][3] - mn1);
            rs0 += s4[nf][0] + s4[nf][1];
            rs1 += s4[nf][2] + s4[nf][3];
        }
        rs0 += __shfl_xor_sync(0xffffffffu, rs0, 1);
        rs0 += __shfl_xor_sync(0xffffffffu, rs0, 2);
        rs1 += __shfl_xor_sync(0xffffffffu, rs1, 1);
        rs1 += __shfl_xor_sync(0xffffffffu, rs1, 2);

        l0 = l0 * cr_0 + rs0;  m0 = mn0;
        l1 = l1 * cr_1 + rs1;  m1 = mn1;

#pragma unroll
        for (int nf = 0; nf < 16; nf++) {
            o[nf][0] *= cr_0;  o[nf][1] *= cr_0;
            o[nf][2] *= cr_1;  o[nf][3] *= cr_1;
        }

        // ---- stage P ----
#pragma unroll
        for (int nf = 0; nf < 8; nf++) {
            const int c = nf * 8 + 2 * t;
            *(uint2*)&Ps[(wr +     g) * FPSTR + c] =
                make_uint2(f2tf(s4[nf][0]), f2tf(s4[nf][1]));
            *(uint2*)&Ps[(wr + 8 + g) * FPSTR + c] =
                make_uint2(f2tf(s4[nf][2]), f2tf(s4[nf][3]));
        }
        __syncwarp();

        // ---- O += P V (pipelined: half-phases of 8 nf, vb double-buffer) ----
        {
            const int sw = t << 3;
            uint32_t vbf[2][16];
            uint32_t av[2][4];
            // preload phase 0 (kc=0, half=0) b-frags and kc=0 a-frags
#pragma unroll
            for (int nf = 0; nf < 8; nf++) {
                const int colv = ((nf * 8) + g) ^ sw;
                vbf[0][nf * 2]     = vs[(    t) * FVSTR + colv];
                vbf[0][nf * 2 + 1] = vs[(4 + t) * FVSTR + colv];
            }
            av[0][0] = Ps[(wr +     g) * FPSTR +     t];
            av[0][1] = Ps[(wr + 8 + g) * FPSTR +     t];
            av[0][2] = Ps[(wr +     g) * FPSTR + 4 + t];
            av[0][3] = Ps[(wr + 8 + g) * FPSTR + 4 + t];

#pragma unroll
            for (int p = 0; p < 16; p++) {
                const int cur  = p & 1;
                const int kc   = p >> 1;
                const int half = p & 1;
                const int ac   = kc & 1;
                // prefetch next phase's b-frags
                if (p < 15) {
                    const int pn    = p + 1;
                    const int kcn   = pn >> 1;
                    const int halfn = pn & 1;
                    const int kbn   = kcn * 8;
#pragma unroll
                    for (int nf = 0; nf < 8; nf++) {
                        const int colv = ((halfn * 8 + nf) * 8 + g) ^ sw;
                        vbf[cur ^ 1][nf * 2]     = vs[(kbn +     t) * FVSTR + colv];
                        vbf[cur ^ 1][nf * 2 + 1] = vs[(kbn + 4 + t) * FVSTR + colv];
                    }
                }
                // prefetch next kc's a-frags during half 0
                if (half == 0 && kc < 7) {
                    const int kbn = (kc + 1) * 8;
                    av[ac ^ 1][0] = Ps[(wr +     g) * FPSTR + kbn +     t];
                    av[ac ^ 1][1] = Ps[(wr + 8 + g) * FPSTR + kbn +     t];
                    av[ac ^ 1][2] = Ps[(wr +     g) * FPSTR + kbn + 4 + t];
                    av[ac ^ 1][3] = Ps[(wr + 8 + g) * FPSTR + kbn + 4 + t];
                }
#pragma unroll
                for (int nf = 0; nf < 8; nf++)
                    MMA_TF32(o[half * 8 + nf],
                             av[ac][0], av[ac][1], av[ac][2], av[ac][3],
                             vbf[cur][nf * 2], vbf[cur][nf * 2 + 1]);
            }
        }
        __syncwarp();
    }

    const float il0 = 1.0f / l0;
    const float il1 = 1.0f / l1;
#pragma unroll
    for (int nf = 0; nf < 16; nf++) {
        const int col = h * HD + nf * 8 + 2 * t;
        float* p0 = g_attn + (size_t)row0 * H_DIM + col;
        p0[0] = __uint_as_float(f2tf(o[nf][0] * il0));
        p0[1] = __uint_as_float(f2tf(o[nf][1] * il0));
        float* p1 = g_attn + (size_t)(row0 + 8) * H_DIM + col;
        p1[0] = __uint_as_float(f2tf(o[nf][2] * il1));
        p1[1] = __uint_as_float(f2tf(o[nf][3] * il1));
    }
}

// ---------------------------------------------------------------------------
// Launch
// ---------------------------------------------------------------------------
extern "C" void kernel_launch(void* const* d_in, const int* in_sizes, int n_in,
                              void* d_out, int out_size)
{
    (void)in_sizes; (void)n_in; (void)out_size;
    const int*   positions = (const int*)d_in[0];
    const float* hidden    = (const float*)d_in[1];
    const float* w_qkv     = (const float*)d_in[2];
    const float* w_o       = (const float*)d_in[3];
    float*       out       = (float*)d_out;

    float *qkv_ptr = nullptr, *attn_ptr = nullptr;
    uint32_t *hidA = nullptr, *wqkvB = nullptr, *woB = nullptr, *attnA = nullptr;
    cudaGetSymbolAddress((void**)&qkv_ptr, g_qkv);
    cudaGetSymbolAddress((void**)&attn_ptr, g_attn);
    cudaGetSymbolAddress((void**)&hidA, g_hidA);
    cudaGetSymbolAddress((void**)&wqkvB, g_wqkvB);
    cudaGetSymbolAddress((void**)&woB, g_woB);
    cudaGetSymbolAddress((void**)&attnA, g_attnA);

    cudaFuncSetAttribute(gemm_tf32_nt,
                         cudaFuncAttributeMaxDynamicSharedMemorySize,
                         G_SMEM_BYTES);
    cudaFuncSetAttribute(flash_tc_kernel,
                         cudaFuncAttributeMaxDynamicSharedMemorySize,
                         FLASH_SMEM_BYTES);

    // 0) convert + pack operands
    pack_a_kernel<<<2048, 256>>>(hidden, (uint4*)hidA, H_DIM,
                                 S_LEN * H_DIM / 4);
    pack_b_kernel<<<2048, 256>>>(w_qkv, (uint2*)wqkvB, H_DIM,
                                 QKV_N * H_DIM / 2);
    pack_b_kernel<<<2048, 256>>>(w_o, (uint2*)woB, H_DIM,
                                 H_DIM * H_DIM / 2);

    // 1) QKV projection (48 x 16 tiles, 2 CTAs/SM)
    gemm_tf32_nt<<<dim3(QKV_N / 128, S_LEN / 128), 128, G_SMEM_BYTES>>>(
        H_DIM, QKV_N, hidA, wqkvB, qkv_ptr);

    // 2) RoPE (+ tf32 rounding of Q, K, V)
    rope_kernel<<<dim3(S_LEN, NH + 2 * NKV), 64>>>(positions);

    // 3) Flash attention
    flash_tc_kernel<<<dim3(S_LEN / 128, NH), 256, FLASH_SMEM_BYTES>>>();

    // 3b) pack attention output for O-proj
    pack_a_kernel<<<2048, 256>>>(attn_ptr, (uint4*)attnA, H_DIM,
                                 S_LEN * H_DIM / 4);

    // 4) Output projection (32 x 16 tiles, 2 CTAs/SM)
    gemm_tf32_nt<<<dim3(H_DIM / 128, S_LEN / 128), 128, G_SMEM_BYTES>>>(
        H_DIM, H_DIM, attnA, woB, out);
}

// round 17
// speedup vs baseline: 5.1242x; 1.0268x over previous
#include <cuda_runtime.h>
#include <math.h>
#include <stdint.h>

#define S_LEN 2048
#define H_DIM 4096
#define NH 32
#define NKV 8
#define HD 128
#define QKV_N 6144
#define ATT_SCALE 0.08838834764831843f

__device__ float g_qkv[S_LEN * QKV_N];
// fragment-packed tf32 operands
__device__ uint32_t g_hidA [S_LEN * H_DIM];
__device__ uint32_t g_wqkvB[QKV_N * H_DIM];
__device__ uint32_t g_woB  [H_DIM * H_DIM];
__device__ uint32_t g_attnA[S_LEN * H_DIM];

__device__ __forceinline__ uint32_t f2tf(float x) {
    uint32_t r;
    asm("cvt.rna.tf32.f32 %0, %1;" : "=r"(r) : "f"(x));
    return r;
}

__device__ __forceinline__ uint32_t smem_u32(const void* p) {
    uint32_t a;
    asm("{ .reg .u64 t; cvta.to.shared.u64 t, %1; cvt.u32.u64 %0, t; }"
        : "=r"(a) : "l"(p));
    return a;
}

#define MMA_TF32(ACC, A0, A1, A2, A3, B0, B1)                                  \
    asm volatile(                                                              \
        "mma.sync.aligned.m16n8k8.row.col.f32.tf32.tf32.f32 "                  \
        "{%0,%1,%2,%3}, {%4,%5,%6,%7}, {%8,%9}, {%0,%1,%2,%3};\n"              \
        : "+f"(ACC[0]), "+f"(ACC[1]), "+f"(ACC[2]), "+f"(ACC[3])               \
        : "r"(A0), "r"(A1), "r"(A2), "r"(A3), "r"(B0), "r"(B1))

#define CP_ASYNC16(dst, src)                                                   \
    asm volatile("cp.async.cg.shared.global [%0], [%1], 16;"                   \
                 :: "r"(dst), "l"(src) : "memory")
#define CP_COMMIT()  asm volatile("cp.async.commit_group;" ::: "memory")
#define CP_WAIT2()   asm volatile("cp.async.wait_group 2;" ::: "memory")
#define CP_WAIT1()   asm volatile("cp.async.wait_group 1;" ::: "memory")
#define CP_WAIT0()   asm volatile("cp.async.wait_group 0;" ::: "memory")

// ---------------------------------------------------------------------------
// A-pack: float [M,K] row-major -> fragment-packed tf32.
// ---------------------------------------------------------------------------
__global__ void pack_a_kernel(const float* __restrict__ in,
                              uint4* __restrict__ out, int K, int n4)
{
    const int k16n = K / 16;
    for (int idx = blockIdx.x * blockDim.x + threadIdx.x; idx < n4;
         idx += gridDim.x * blockDim.x) {
        const int slab = idx >> 9;
        const int rem  = idx & 511;
        const int sub  = rem >> 5;
        const int lane = rem & 31;
        const int mblk = slab / k16n;
        const int k16  = slab - mblk * k16n;
        const int row  = mblk * 128 + (sub >> 1) * 16 + (lane >> 2);
        const int k    = k16 * 16 + (sub & 1) * 8 + (lane & 3);
        const float* p = in + (size_t)row * K + k;
        out[idx] = make_uint4(f2tf(p[0]),
                              f2tf(p[(size_t)8 * K]),
                              f2tf(p[4]),
                              f2tf(p[(size_t)8 * K + 4]));
    }
}

// ---------------------------------------------------------------------------
// B-pack: float [N,K] row-major -> fragment-packed tf32.
// ---------------------------------------------------------------------------
__global__ void pack_b_kernel(const float* __restrict__ in,
                              uint2* __restrict__ out, int K, int n2)
{
    const int k16n = K / 16;
    for (int idx = blockIdx.x * blockDim.x + threadIdx.x; idx < n2;
         idx += gridDim.x * blockDim.x) {
        const int slab = idx >> 10;
        const int rem  = idx & 1023;
        const int sub  = rem >> 5;
        const int lane = rem & 31;
        const int nblk = slab / k16n;
        const int k16  = slab - nblk * k16n;
        const int row  = nblk * 128 + (sub >> 1) * 8 + (lane >> 2);
        const int k    = k16 * 16 + (sub & 1) * 8 + (lane & 3);
        const float* p = in + (size_t)row * K + k;
        out[idx] = make_uint2(f2tf(p[0]), f2tf(p[4]));
    }
}

// ---------------------------------------------------------------------------
// TF32 GEMM (unchanged from round 14 — pipelined fragments, 2 CTAs/SM)
// ---------------------------------------------------------------------------
#define A_SLAB_W 2048
#define A_STG_W  4096
#define B_STG_W  4096
#define G_SMEM_BYTES (3 * (A_STG_W + B_STG_W) * 4)   // 98304

__global__ __launch_bounds__(128, 2)
void gemm_tf32_nt(int K, int Nfull,
                  const uint32_t* __restrict__ A,
                  const uint32_t* __restrict__ B,
                  float* __restrict__ C)
{
    extern __shared__ uint32_t gdyn[];
    uint32_t* As = gdyn;
    uint32_t* Bs = gdyn + 3 * A_STG_W;
    const uint32_t as_base = smem_u32(As);
    const uint32_t bs_base = smem_u32(Bs);

    const int tid  = threadIdx.x;
    const int warp = tid >> 5;
    const int lane = tid & 31;
    const int g    = lane >> 2;
    const int t    = lane & 3;

    const int k16n = K / 16;
    const int nkp  = k16n / 2;
    const uint32_t* Aslab = A + (size_t)blockIdx.y * k16n * A_SLAB_W;
    const uint32_t* Bslab = B + (size_t)blockIdx.x * k16n * A_SLAB_W;

    const int m16b = (warp & 1) * 4;
    const int n8b  = (warp >> 1) * 8;

    float acc[4][8][4];
#pragma unroll
    for (int i = 0; i < 4; i++)
#pragma unroll
        for (int j = 0; j < 8; j++)
#pragma unroll
            for (int r = 0; r < 4; r++) acc[i][j][r] = 0.0f;

#define G_FILL(stage, kp)                                                      \
    do {                                                                       \
        const uint32_t ab = as_base + (stage) * A_STG_W * 4;                   \
        const uint32_t bb = bs_base + (stage) * B_STG_W * 4;                   \
        _Pragma("unroll")                                                      \
        for (int j = 0; j < 2; j++) {                                          \
            const uint32_t* Ap = Aslab + (size_t)(2 * (kp) + j) * A_SLAB_W;    \
            const uint32_t* Bp = Bslab + (size_t)(2 * (kp) + j) * A_SLAB_W;    \
            _Pragma("unroll")                                                  \
            for (int i = 0; i < 4; i++) {                                      \
                const int c = tid + i * 128;                                   \
                CP_ASYNC16(ab + j * 8192 + c * 16, Ap + c * 4);                \
                CP_ASYNC16(bb + j * 8192 + c * 16, Bp + c * 4);                \
            }                                                                  \
        }                                                                      \
    } while (0)

#define LOADF(buf, ph)                                                         \
    do {                                                                       \
        const int j_  = (ph) >> 1;                                             \
        const int ks_ = (ph) & 1;                                              \
        const uint32_t* as_ = as_s + j_ * A_SLAB_W;                            \
        const uint32_t* bs_ = bs_s + j_ * A_SLAB_W;                            \
        _Pragma("unroll")                                                      \
        for (int am = 0; am < 4; am++)                                         \
            aw[buf][am] = *(const uint4*)&as_[((m16b + am) * 2 + ks_) * 128 +  \
                                              lane * 4];                       \
        _Pragma("unroll")                                                      \
        for (int an = 0; an < 8; an++)                                         \
            bw[buf][an] = *(const uint2*)&bs_[((n8b + an) * 2 + ks_) * 64 +    \
                                              lane * 2];                       \
    } while (0)

    G_FILL(0, 0);
    CP_COMMIT();
    G_FILL(1, 1);
    CP_COMMIT();

    int stg = 0;
    for (int kp = 0; kp < nkp; kp++) {
        CP_WAIT1();
        __syncthreads();

        if (kp + 2 < nkp) {
            const int s2 = (kp + 2) % 3;
            G_FILL(s2, kp + 2);
        }
        CP_COMMIT();

        const uint32_t* as_s = As + stg * A_STG_W;
        const uint32_t* bs_s = Bs + stg * B_STG_W;

        uint4 aw[2][4];
        uint2 bw[2][8];
        LOADF(0, 0);
#pragma unroll
        for (int ph = 0; ph < 4; ph++) {
            const int cur = ph & 1;
            if (ph < 3) LOADF(cur ^ 1, ph + 1);
#pragma unroll
            for (int am = 0; am < 4; am++)
#pragma unroll
                for (int an = 0; an < 8; an++)
                    MMA_TF32(acc[am][an],
                             aw[cur][am].x, aw[cur][am].y,
                             aw[cur][am].z, aw[cur][am].w,
                             bw[cur][an].x, bw[cur][an].y);
        }
        stg = (stg + 1) % 3;
    }
    CP_WAIT0();

    const int bm = blockIdx.y * 128;
    const int bn = blockIdx.x * 128;
#pragma unroll
    for (int am = 0; am < 4; am++) {
        const int row0 = bm + (m16b + am) * 16 + g;
#pragma unroll
        for (int an = 0; an < 8; an++) {
            const int col = bn + (n8b + an) * 8 + t * 2;
            float* c0p = C + (size_t)row0 * Nfull + col;
            c0p[0] = acc[am][an][0];
            c0p[1] = acc[am][an][1];
            float* c2p = c0p + (size_t)8 * Nfull;
            c2p[0] = acc[am][an][2];
            c2p[1] = acc[am][an][3];
        }
    }
#undef LOADF
#undef G_FILL
}

// ---------------------------------------------------------------------------
// RoPE + tf32 pre-round (heads 0..39 rotate+round, 40..47 round only)
// ---------------------------------------------------------------------------
__global__ void rope_kernel(const int* __restrict__ positions)
{
    const int s = blockIdx.x;
    const int h = blockIdx.y;          // 0..47
    const int d = threadIdx.x;         // 0..63

    float* base = g_qkv + (size_t)s * QKV_N + h * HD;
    const float x1 = base[d];
    const float x2 = base[d + 64];

    if (h < NH + NKV) {
        const float pos = (float)positions[s];
        const float inv_freq = powf(1000000.0f, -(float)d * (1.0f / 64.0f));
        const float ang = pos * inv_freq;
        float sn, cs;
        sincosf(ang, &sn, &cs);
        base[d]      = __uint_as_float(f2tf(x1 * cs - x2 * sn));
        base[d + 64] = __uint_as_float(f2tf(x2 * cs + x1 * sn));
    } else {
        base[d]      = __uint_as_float(f2tf(x1));
        base[d + 64] = __uint_as_float(f2tf(x2));
    }
}

// ---------------------------------------------------------------------------
// Flash attention v3 (fixed loader): 128 threads (4 warps), 64-row q-tiles,
// 2 CTAs/SM. K double-buffered, V single-buffered. FULL tile coverage:
// 16 chunks/thread/tile (row = warp + 4*i, colw = lane*4). P relayout via
// warp shuffles (no Ps smem). Epilogue writes g_attnA in packed-A layout.
// ---------------------------------------------------------------------------
#define FKSTR 132
#define FVSTR 128
#define KSTG_W (64 * FKSTR)     // 8448 words
#define VBUF_W (64 * FVSTR)     // 8192 words
#define FLASH_SMEM_BYTES ((2 * KSTG_W + VBUF_W) * 4)   // 100352

// shuffle repack: consumer (g,t) gets rows (g,g+8) x cols (t,t+4) of an
// 8-col block from c-frag regs V0..V3 (rows g,g+8 x cols 2t',2t'+1).
#define P_REPACK(A0, A1, A2, A3, V0, V1, V2, V3)                               \
    do {                                                                       \
        uint32_t x0 = __shfl_sync(0xffffffffu, V0, srcA);                      \
        uint32_t x1 = __shfl_sync(0xffffffffu, V1, srcA);                      \
        uint32_t x2 = __shfl_sync(0xffffffffu, V2, srcA);                      \
        uint32_t x3 = __shfl_sync(0xffffffffu, V3, srcA);                      \
        uint32_t y0 = __shfl_sync(0xffffffffu, V0, srcB);                      \
        uint32_t y1 = __shfl_sync(0xffffffffu, V1, srcB);                      \
        uint32_t y2 = __shfl_sync(0xffffffffu, V2, srcB);                      \
        uint32_t y3 = __shfl_sync(0xffffffffu, V3, srcB);                      \
        A0 = odd ? x1 : x0;                                                    \
        A1 = odd ? x3 : x2;                                                    \
        A2 = odd ? y1 : y0;                                                    \
        A3 = odd ? y3 : y2;                                                    \
    } while (0)

__global__ __launch_bounds__(128, 2)
void flash_tc_kernel()
{
    extern __shared__ uint32_t fsm[];
    uint32_t* Ks = fsm;                    // [2][KSTG_W]
    uint32_t* Vs = fsm + 2 * KSTG_W;       // [VBUF_W]
    const uint32_t ks_base = smem_u32(Ks);
    const uint32_t vs_base = smem_u32(Vs);

    const int tid  = threadIdx.x;
    const int warp = tid >> 5;             // 0..3
    const int lane = tid & 31;
    const int g    = lane >> 2;
    const int t    = lane & 3;
    const int qt   = gridDim.x - 1 - blockIdx.x;   // 31..0, heavy first
    const int h    = blockIdx.y;
    const int kh   = h >> 2;
    const int wr   = warp * 16;

    const int  srcA = (lane & 28) | (t >> 1);
    const int  srcB = srcA + 2;
    const bool odd  = (t & 1) != 0;

    const float* Qg = g_qkv + (size_t)(qt * 64) * QKV_N + h * HD;
    const float* Kg = g_qkv + NH * HD + kh * HD;
    const float* Vg = g_qkv + (NH + NKV) * HD + kh * HD;

    // cp.async mapping: 16 chunks per tile per thread.
    // chunk i: row = warp + 4*i (covers 64 rows), colw = lane*4.
    const int cw  = lane * 4;
    const int vsw = cw ^ ((warp & 3) << 3);   // (row&3)==(warp&3) for all i

    // Q a-fragments -> registers (one-time; g_qkv already tf32-rounded)
    uint32_t qf[16][4];
    {
        const float* q0 = Qg + (size_t)(wr +     g) * QKV_N;
        const float* q1 = Qg + (size_t)(wr + 8 + g) * QKV_N;
#pragma unroll
        for (int kc = 0; kc < 16; kc++) {
            const int c = kc * 8 + t;
            qf[kc][0] = __float_as_uint(q0[c]);
            qf[kc][1] = __float_as_uint(q1[c]);
            qf[kc][2] = __float_as_uint(q0[c + 4]);
            qf[kc][3] = __float_as_uint(q1[c + 4]);
        }
    }

    float m0 = -INFINITY, m1 = -INFINITY, l0 = 0.0f, l1 = 0.0f;
    float o[16][4];
#pragma unroll
    for (int nf = 0; nf < 16; nf++)
#pragma unroll
        for (int r = 0; r < 4; r++) o[nf][r] = 0.0f;

    const int row0 = qt * 64 + wr + g;
    const int n_ktiles = qt + 1;

    // prologue: GK(0) -> K stage 0
    {
#pragma unroll
        for (int i = 0; i < 16; i++) {
            const int r = warp + 4 * i;
            CP_ASYNC16(ks_base + (uint32_t)(r * FKSTR + cw) * 4,
                       Kg + (size_t)r * QKV_N + cw);
        }
        CP_COMMIT();
    }

    for (int jt = 0; jt < n_ktiles; jt++) {
        __syncthreads();   // prev iter's K/V reads done before overwriting

        // GV(jt) -> V buffer
        {
            const float* Vt = Vg + (size_t)(jt * 64) * QKV_N;
#pragma unroll
            for (int i = 0; i < 16; i++) {
                const int r = warp + 4 * i;
                CP_ASYNC16(vs_base + (uint32_t)(r * FVSTR + vsw) * 4,
                           Vt + (size_t)r * QKV_N + cw);
            }
            CP_COMMIT();
        }
        // GK(jt+1) -> K stage (jt+1)&1
        {
            if (jt + 1 < n_ktiles) {
                const float* Kt = Kg + (size_t)((jt + 1) * 64) * QKV_N;
                const uint32_t kb = ks_base + ((jt + 1) & 1) * KSTG_W * 4;
#pragma unroll
                for (int i = 0; i < 16; i++) {
                    const int r = warp + 4 * i;
                    CP_ASYNC16(kb + (uint32_t)(r * FKSTR + cw) * 4,
                               Kt + (size_t)r * QKV_N + cw);
                }
            }
            CP_COMMIT();
        }

        CP_WAIT2();        // GK(jt) complete (GV(jt), GK(jt+1) may pend)
        __syncthreads();

        const uint32_t* ks = Ks + (jt & 1) * KSTG_W;

        // ---- S = Q K^T ----
        float s4[8][4];
#pragma unroll
        for (int nf = 0; nf < 8; nf++)
#pragma unroll
            for (int r = 0; r < 4; r++) s4[nf][r] = 0.0f;

#pragma unroll
        for (int kc = 0; kc < 16; kc++) {
            const int kb = kc * 8;
#pragma unroll
            for (int nf = 0; nf < 8; nf++) {
                uint32_t b0 = ks[(nf * 8 + g) * FKSTR + kb +     t];
                uint32_t b1 = ks[(nf * 8 + g) * FKSTR + kb + 4 + t];
                MMA_TF32(s4[nf], qf[kc][0], qf[kc][1], qf[kc][2], qf[kc][3], b0, b1);
            }
        }

        // ---- scale + causal mask ----
        const int colbase = jt * 64 + 2 * t;
#pragma unroll
        for (int nf = 0; nf < 8; nf++) {
            const int col = colbase + nf * 8;
            float v0 = s4[nf][0] * ATT_SCALE;
            float v1 = s4[nf][1] * ATT_SCALE;
            float v2 = s4[nf][2] * ATT_SCALE;
            float v3 = s4[nf][3] * ATT_SCALE;
            if (col     > row0)     v0 = -1e30f;
            if (col + 1 > row0)     v1 = -1e30f;
            if (col     > row0 + 8) v2 = -1e30f;
            if (col + 1 > row0 + 8) v3 = -1e30f;
            s4[nf][0] = v0; s4[nf][1] = v1; s4[nf][2] = v2; s4[nf][3] = v3;
        }

        // ---- online softmax ----
        float rm0 = -INFINITY, rm1 = -INFINITY;
#pragma unroll
        for (int nf = 0; nf < 8; nf++) {
            rm0 = fmaxf(rm0, fmaxf(s4[nf][0], s4[nf][1]));
            rm1 = fmaxf(rm1, fmaxf(s4[nf][2], s4[nf][3]));
        }
        rm0 = fmaxf(rm0, __shfl_xor_sync(0xffffffffu, rm0, 1));
        rm0 = fmaxf(rm0, __shfl_xor_sync(0xffffffffu, rm0, 2));
        rm1 = fmaxf(rm1, __shfl_xor_sync(0xffffffffu, rm1, 1));
        rm1 = fmaxf(rm1, __shfl_xor_sync(0xffffffffu, rm1, 2));

        const float mn0 = fmaxf(m0, rm0);
        const float mn1 = fmaxf(m1, rm1);
        const float cr_0 = __expf(m0 - mn0);
        const float cr_1 = __expf(m1 - mn1);

        float rs0 = 0.0f, rs1 = 0.0f;
#pragma unroll
        for (int nf = 0; nf < 8; nf++) {
            s4[nf][0] = __expf(s4[nf][0] - mn0);
            s4[nf][1] = __expf(s4[nf][1] - mn0);
            s4[nf][2] = __expf(s4[nf][2] - mn1);
            s4[nf][3] = __expf(s4[nf][3] - mn1);
            rs0 += s4[nf][0] + s4[nf][1];
            rs1 += s4[nf][2] + s4[nf][3];
        }
        rs0 += __shfl_xor_sync(0xffffffffu, rs0, 1);
        rs0 += __shfl_xor_sync(0xffffffffu, rs0, 2);
        rs1 += __shfl_xor_sync(0xffffffffu, rs1, 1);
        rs1 += __shfl_xor_sync(0xffffffffu, rs1, 2);

        l0 = l0 * cr_0 + rs0;  m0 = mn0;
        l1 = l1 * cr_1 + rs1;  m1 = mn1;

#pragma unroll
        for (int nf = 0; nf < 16; nf++) {
            o[nf][0] *= cr_0;  o[nf][1] *= cr_0;
            o[nf][2] *= cr_1;  o[nf][3] *= cr_1;
        }

        // ---- P to tf32 (same rounding point as the old Ps staging) ----
        uint32_t pf[8][4];
#pragma unroll
        for (int nf = 0; nf < 8; nf++) {
            pf[nf][0] = f2tf(s4[nf][0]);
            pf[nf][1] = f2tf(s4[nf][1]);
            pf[nf][2] = f2tf(s4[nf][2]);
            pf[nf][3] = f2tf(s4[nf][3]);
        }

        CP_WAIT1();        // GV(jt) complete (GK(jt+1) may pend)
        __syncthreads();   // V visible to all warps

        // ---- O += P V  (a-frags via shuffle repack) ----
        const int sw = t << 3;
#pragma unroll
        for (int kc = 0; kc < 8; kc++) {
            uint32_t a0, a1, a2, a3;
            P_REPACK(a0, a1, a2, a3, pf[kc][0], pf[kc][1], pf[kc][2], pf[kc][3]);
            const int kb = kc * 8;
#pragma unroll
            for (int nf = 0; nf < 16; nf++) {
                uint32_t b0 = Vs[(kb +     t) * FVSTR + ((nf * 8 + g) ^ sw)];
                uint32_t b1 = Vs[(kb + 4 + t) * FVSTR + ((nf * 8 + g) ^ sw)];
                MMA_TF32(o[nf], a0, a1, a2, a3, b0, b1);
            }
        }
    }

    // ---- epilogue: normalize + write DIRECTLY in packed-A layout ----
    {
        const float il0 = 1.0f / l0;
        const float il1 = 1.0f / l1;
        const int m16g   = qt * 4 + warp;      // global m16 index
        const int mblk   = m16g >> 3;
        const int m16loc = m16g & 7;
        uint4* outp = (uint4*)g_attnA;
#pragma unroll
        for (int nf = 0; nf < 16; nf++) {
            uint32_t p0 = f2tf(o[nf][0] * il0);
            uint32_t p1 = f2tf(o[nf][1] * il0);
            uint32_t p2 = f2tf(o[nf][2] * il1);
            uint32_t p3 = f2tf(o[nf][3] * il1);
            uint32_t a0, a1, a2, a3;
            P_REPACK(a0, a1, a2, a3, p0, p1, p2, p3);
            const int k16 = h * 8 + (nf >> 1);
            const int sub = m16loc * 2 + (nf & 1);
            const size_t idx = ((size_t)mblk * 256 + k16) * 512 + sub * 32 + lane;
            outp[idx] = make_uint4(a0, a1, a2, a3);
        }
    }
}

// ---------------------------------------------------------------------------
// Launch
// ---------------------------------------------------------------------------
extern "C" void kernel_launch(void* const* d_in, const int* in_sizes, int n_in,
                              void* d_out, int out_size)
{
    (void)in_sizes; (void)n_in; (void)out_size;
    const int*   positions = (const int*)d_in[0];
    const float* hidden    = (const float*)d_in[1];
    const float* w_qkv     = (const float*)d_in[2];
    const float* w_o       = (const float*)d_in[3];
    float*       out       = (float*)d_out;

    float *qkv_ptr = nullptr;
    uint32_t *hidA = nullptr, *wqkvB = nullptr, *woB = nullptr, *attnA = nullptr;
    cudaGetSymbolAddress((void**)&qkv_ptr, g_qkv);
    cudaGetSymbolAddress((void**)&hidA, g_hidA);
    cudaGetSymbolAddress((void**)&wqkvB, g_wqkvB);
    cudaGetSymbolAddress((void**)&woB, g_woB);
    cudaGetSymbolAddress((void**)&attnA, g_attnA);

    cudaFuncSetAttribute(gemm_tf32_nt,
                         cudaFuncAttributeMaxDynamicSharedMemorySize,
                         G_SMEM_BYTES);
    cudaFuncSetAttribute(flash_tc_kernel,
                         cudaFuncAttributeMaxDynamicSharedMemorySize,
                         FLASH_SMEM_BYTES);

    // 0) convert + pack operands
    pack_a_kernel<<<2048, 256>>>(hidden, (uint4*)hidA, H_DIM,
                                 S_LEN * H_DIM / 4);
    pack_b_kernel<<<2048, 256>>>(w_qkv, (uint2*)wqkvB, H_DIM,
                                 QKV_N * H_DIM / 2);
    pack_b_kernel<<<2048, 256>>>(w_o, (uint2*)woB, H_DIM,
                                 H_DIM * H_DIM / 2);

    // 1) QKV projection (48 x 16 tiles, 2 CTAs/SM)
    gemm_tf32_nt<<<dim3(QKV_N / 128, S_LEN / 128), 128, G_SMEM_BYTES>>>(
        H_DIM, QKV_N, hidA, wqkvB, qkv_ptr);

    // 2) RoPE (+ tf32 rounding of Q, K, V)
    rope_kernel<<<dim3(S_LEN, NH + 2 * NKV), 64>>>(positions);

    // 3) Flash attention (64-row q-tiles, writes packed attnA directly)
    flash_tc_kernel<<<dim3(S_LEN / 64, NH), 128, FLASH_SMEM_BYTES>>>();

    // 4) Output projection (32 x 16 tiles, 2 CTAs/SM)
    gemm_tf32_nt<<<dim3(H_DIM / 128, S_LEN / 128), 128, G_SMEM_BYTES>>>(
        H_DIM, H_DIM, attnA, woB, out);
}